// round 8
// baseline (speedup 1.0000x reference)
#include <cuda_runtime.h>
#include <cuda_fp16.h>
#include <cstdint>

// B=64, N=1000, D=512, H=8, S=20, DK=64
#define NEG_BIG (-1e9f)
#define INV_SQRT_DK 0.125f
#define INV_SQRT_D 0.04419417382415922f

// ---------------- device scratch ----------------
// g_kvlh padded to 64032 rows so attention V-tile tail reads stay in this array (zero pad).
__device__ __align__(16) __half g_kvlh[64032 * 1536];    // [row][gk(unused)|gv|lk]
__device__ __align__(16) __half g_kT[64 * 8 * 64 * 1024]; // K transposed [b][h][d][n(pad 1024)]
__device__ __align__(16) float g_heads[1280 * 512];
__device__ __align__(16) float g_glimpse[1280 * 512];
__device__ __align__(16) float g_logits[1280 * 1000];
__device__ __align__(16) __half g_Af16[64000 * 512];
__device__ __align__(16) __half g_Wkvl_t[1536 * 512];
__device__ __align__(16) __half g_Wout_t[512 * 512];
__device__ __align__(16) __half g_Hf16[1280 * 512];
__device__ __align__(16) unsigned int g_mbits[1280 * 32]; // packed feasibility bits

// ---------------- helpers ----------------
__device__ __forceinline__ float warp_max(float v) {
#pragma unroll
    for (int o = 16; o; o >>= 1) v = fmaxf(v, __shfl_xor_sync(0xffffffffu, v, o));
    return v;
}
__device__ __forceinline__ float warp_sum(float v) {
#pragma unroll
    for (int o = 16; o; o >>= 1) v += __shfl_xor_sync(0xffffffffu, v, o);
    return v;
}
__device__ __forceinline__ uint32_t smem_u32(const void* p) {
    uint32_t a;
    asm("{ .reg .u64 t; cvta.to.shared.u64 t, %1; cvt.u32.u64 %0, t; }" : "=r"(a) : "l"(p));
    return a;
}
__device__ __forceinline__ void cp_async16(uint32_t saddr, const void* gaddr) {
    asm volatile("cp.async.cg.shared.global [%0], [%1], 16;" :: "r"(saddr), "l"(gaddr));
}
__device__ __forceinline__ void cp_commit() { asm volatile("cp.async.commit_group;" ::: "memory"); }
__device__ __forceinline__ void cp_wait1() { asm volatile("cp.async.wait_group 1;" ::: "memory"); }
__device__ __forceinline__ void cp_wait0() { asm volatile("cp.async.wait_group 0;" ::: "memory"); }

__device__ __forceinline__ void ldsm_x4(uint32_t& r0, uint32_t& r1, uint32_t& r2, uint32_t& r3,
                                        uint32_t addr) {
    asm volatile("ldmatrix.sync.aligned.m8n8.x4.shared.b16 {%0,%1,%2,%3}, [%4];"
                 : "=r"(r0), "=r"(r1), "=r"(r2), "=r"(r3) : "r"(addr));
}
__device__ __forceinline__ void mma16816(float& c0, float& c1, float& c2, float& c3,
                                         uint32_t a0, uint32_t a1, uint32_t a2, uint32_t a3,
                                         uint32_t b0, uint32_t b1) {
    asm volatile(
        "mma.sync.aligned.m16n8k16.row.col.f32.f16.f16.f32 "
        "{%0,%1,%2,%3}, {%4,%5,%6,%7}, {%8,%9}, {%0,%1,%2,%3};"
        : "+f"(c0), "+f"(c1), "+f"(c2), "+f"(c3)
        : "r"(a0), "r"(a1), "r"(a2), "r"(a3), "r"(b0), "r"(b1));
}

// ---------------- mask -> packed bits (self-detecting dtype) ----------------
__global__ __launch_bounds__(256)
void mask_bits_kernel(const unsigned int* __restrict__ mw)
{
    __shared__ int flags;
    if (threadIdx.x == 0) flags = 0;
    __syncthreads();
    int f = 0;
    for (int i = threadIdx.x; i < 1024; i += 256) {
        unsigned int v = mw[i];
        if (v != 0u && v != 1u) f |= 1;
        if (v != 0u && v != 0x3F800000u) f |= 2;
    }
    if (f) atomicOr(&flags, f);
    __syncthreads();
    const int mode = ((flags & 1) && (flags & 2)) ? 0 : 1;  // 0=bytes, 1=words

    const int lane = threadIdx.x & 31, wid = threadIdx.x >> 5;
    const int row = blockIdx.x;
#pragma unroll
    for (int j = 0; j < 4; j++) {
        int widx = wid * 4 + j;
        int n = widx * 32 + lane;
        bool feas = false;
        if (n < 1000) {
            int idx = row * 1000 + n;
            feas = mode ? (mw[idx] != 0u)
                        : (((const unsigned char*)mw)[idx] != 0);
        }
        unsigned int word = __ballot_sync(0xffffffffu, feas);
        if (lane == 0) g_mbits[row * 32 + widx] = word;
    }
}

// ---------------- fused prep ----------------
__global__ __launch_bounds__(256)
void prep_kernel(const float* __restrict__ emb, const float* __restrict__ Wkvl,
                 const float* __restrict__ Wout)
{
    int bid = blockIdx.x;
    int tid = threadIdx.x;
    if (bid < 32000) {
        int i = bid * 256 + tid;
        float4 v = ((const float4*)emb)[i];
        ((__half2*)g_Af16)[i * 2] = __floats2half2_rn(v.x, v.y);
        ((__half2*)g_Af16)[i * 2 + 1] = __floats2half2_rn(v.z, v.w);
    } else if (bid < 35072) {
        int idx = (bid - 32000) * 256 + tid;
        int n = idx >> 9, k = idx & 511;
        g_Wkvl_t[idx] = __float2half_rn(Wkvl[(size_t)k * 1536 + n]);
    } else {
        int idx = (bid - 35072) * 256 + tid;
        int n = idx >> 9, k = idx & 511;
        g_Wout_t[idx] = __float2half_rn(Wout[(size_t)k * 512 + n]);
    }
}

// ---------------- fp32 -> fp16 (heads) ----------------
__global__ __launch_bounds__(256)
void conv_f16_kernel(const float* __restrict__ x, __half* __restrict__ y, int n4)
{
    int i = blockIdx.x * 256 + threadIdx.x;
    if (i >= n4) return;
    float4 v = ((const float4*)x)[i];
    ((__half2*)y)[i * 2] = __floats2half2_rn(v.x, v.y);
    ((__half2*)y)[i * 2 + 1] = __floats2half2_rn(v.z, v.w);
}

// ---------------- BIG fp16 HMMA GEMM: 128x256 tile, K section written transposed ----------------
__global__ __launch_bounds__(256)
void hmma_gemm_big(const __half* __restrict__ A, const __half* __restrict__ Bt,
                   __half* __restrict__ C, int Nn)
{
    extern __shared__ char dsm[];
    const uint32_t sb = smem_u32(dsm);
    const int tid = threadIdx.x;
    const int bm = blockIdx.y * 128;
    const int bn = blockIdx.x * 256;
    const int lane = tid & 31, w = tid >> 5;
    const int wr = w >> 2;
    const int wc = w & 3;

    const char* Ag = (const char*)A + (size_t)bm * 1024;
    const char* Bg = (const char*)Bt + (size_t)bn * 1024;

#define LOAD_CHUNK(kc)                                                      \
    do {                                                                    \
        uint32_t st_ = sb + ((kc) % 3) * 49152;                             \
        size_t gk_ = (size_t)(kc) * 128;                                    \
        _Pragma("unroll")                                                   \
        for (int i_ = 0; i_ < 4; i_++) {                                    \
            int g_ = tid + i_ * 256;                                        \
            int row_ = g_ >> 3, ch_ = g_ & 7;                               \
            uint32_t off_ = row_ * 128 + ch_ * 16;                          \
            uint32_t sw_ = off_ ^ ((off_ >> 3) & 0x70);                     \
            cp_async16(st_ + sw_, Ag + (size_t)row_ * 1024 + gk_ + ch_ * 16); \
        }                                                                   \
        _Pragma("unroll")                                                   \
        for (int i_ = 0; i_ < 8; i_++) {                                    \
            int g_ = tid + i_ * 256;                                        \
            int row_ = g_ >> 3, ch_ = g_ & 7;                               \
            uint32_t off_ = row_ * 128 + ch_ * 16;                          \
            uint32_t sw_ = off_ ^ ((off_ >> 3) & 0x70);                     \
            cp_async16(st_ + 16384 + sw_, Bg + (size_t)row_ * 1024 + gk_ + ch_ * 16); \
        }                                                                   \
        cp_commit();                                                        \
    } while (0)

    float acc[4][8][4];
#pragma unroll
    for (int i = 0; i < 4; i++)
#pragma unroll
        for (int j = 0; j < 8; j++)
#pragma unroll
            for (int r = 0; r < 4; r++) acc[i][j][r] = 0.f;

    LOAD_CHUNK(0);
    LOAD_CHUNK(1);

    const int a_row = (lane & 15);
    const int a_c16 = (lane >> 4);
    const int b_nrow = (lane & 7) + ((lane >> 4) & 1) * 8;
    const int b_c16 = (lane >> 3) & 1;

    for (int kc = 0; kc < 8; ++kc) {
        if (kc == 7) cp_wait0(); else cp_wait1();
        __syncthreads();
        if (kc + 2 < 8) LOAD_CHUNK(kc + 2);

        uint32_t st = sb + (kc % 3) * 49152;
#pragma unroll
        for (int ks = 0; ks < 4; ++ks) {
            uint32_t af[4][4];
#pragma unroll
            for (int mi = 0; mi < 4; ++mi) {
                uint32_t off = (uint32_t)(wr * 64 + mi * 16 + a_row) * 128 + ks * 32 + a_c16 * 16;
                uint32_t sw = off ^ ((off >> 3) & 0x70);
                ldsm_x4(af[mi][0], af[mi][1], af[mi][2], af[mi][3], st + sw);
            }
            uint32_t bf[4][4];
#pragma unroll
            for (int pr = 0; pr < 4; ++pr) {
                uint32_t off = (uint32_t)(wc * 64 + pr * 16 + b_nrow) * 128 + ks * 32 + b_c16 * 16;
                uint32_t sw = off ^ ((off >> 3) & 0x70);
                ldsm_x4(bf[pr][0], bf[pr][1], bf[pr][2], bf[pr][3], st + 16384 + sw);
            }
#pragma unroll
            for (int mi = 0; mi < 4; ++mi) {
#pragma unroll
                for (int pr = 0; pr < 4; ++pr) {
                    mma16816(acc[mi][pr * 2][0], acc[mi][pr * 2][1],
                             acc[mi][pr * 2][2], acc[mi][pr * 2][3],
                             af[mi][0], af[mi][1], af[mi][2], af[mi][3],
                             bf[pr][0], bf[pr][1]);
                    mma16816(acc[mi][pr * 2 + 1][0], acc[mi][pr * 2 + 1][1],
                             acc[mi][pr * 2 + 1][2], acc[mi][pr * 2 + 1][3],
                             af[mi][0], af[mi][1], af[mi][2], af[mi][3],
                             bf[pr][2], bf[pr][3]);
                }
            }
        }
    }
    __syncthreads();

    if (bn < 512) {
        // glimpse-K section: write transposed into g_kT[b][h][d][n(1024)]
#pragma unroll
        for (int mi = 0; mi < 4; ++mi) {
            int row0 = bm + wr * 64 + mi * 16 + (lane >> 2);
            int row1 = row0 + 8;
            int b0 = row0 / 1000, n0r = row0 - b0 * 1000;
            int b1 = row1 / 1000, n1r = row1 - b1 * 1000;
#pragma unroll
            for (int ni = 0; ni < 8; ++ni) {
                int col = bn + wc * 64 + ni * 8 + (lane & 3) * 2;
                int hh = col >> 6, dd = col & 63;
                size_t base = (((size_t)hh) * 64 + dd) * 1024;
                size_t o0 = ((size_t)b0 * 512) * 1024 + base + n0r;
                size_t o1 = ((size_t)b1 * 512) * 1024 + base + n1r;
                g_kT[o0]        = __float2half_rn(acc[mi][ni][0]);
                g_kT[o0 + 1024] = __float2half_rn(acc[mi][ni][1]);
                g_kT[o1]        = __float2half_rn(acc[mi][ni][2]);
                g_kT[o1 + 1024] = __float2half_rn(acc[mi][ni][3]);
            }
        }
    } else {
#pragma unroll
        for (int mi = 0; mi < 4; ++mi) {
            int row0 = bm + wr * 64 + mi * 16 + (lane >> 2);
#pragma unroll
            for (int ni = 0; ni < 8; ++ni) {
                int col = bn + wc * 64 + ni * 8 + (lane & 3) * 2;
                *(__half2*)(C + (size_t)row0 * Nn + col) =
                    __floats2half2_rn(acc[mi][ni][0], acc[mi][ni][1]);
                *(__half2*)(C + (size_t)(row0 + 8) * Nn + col) =
                    __floats2half2_rn(acc[mi][ni][2], acc[mi][ni][3]);
            }
        }
    }
#undef LOAD_CHUNK
}

// ---------------- small fp16 HMMA GEMM (glimpse): 128x128, fp32 out ----------------
__global__ __launch_bounds__(256, 2)
void hmma_gemm(const __half* __restrict__ A, const __half* __restrict__ Bt,
               float* __restrict__ C, int Nn)
{
    extern __shared__ char dsm[];
    const uint32_t sb = smem_u32(dsm);
    const int tid = threadIdx.x;
    const int bm = blockIdx.y * 128;
    const int bn = blockIdx.x * 128;
    const int lane = tid & 31, w = tid >> 5;
    const int wr = w >> 2;
    const int wc = w & 3;

    const char* Ag = (const char*)A + (size_t)bm * 1024;
    const char* Bg = (const char*)Bt + (size_t)bn * 1024;

#define LOAD_CHUNK(kc)                                                      \
    do {                                                                    \
        uint32_t st_ = sb + ((kc) & 1) * 32768;                             \
        size_t gk_ = (size_t)(kc) * 128;                                    \
        _Pragma("unroll")                                                   \
        for (int i_ = 0; i_ < 4; i_++) {                                    \
            int g_ = tid + i_ * 256;                                        \
            int row_ = g_ >> 3, ch_ = g_ & 7;                               \
            uint32_t off_ = row_ * 128 + ch_ * 16;                          \
            uint32_t sw_ = off_ ^ ((off_ >> 3) & 0x70);                     \
            size_t go_ = (size_t)row_ * 1024 + gk_ + ch_ * 16;              \
            cp_async16(st_ + sw_, Ag + go_);                                \
            cp_async16(st_ + 16384 + sw_, Bg + go_);                        \
        }                                                                   \
        cp_commit();                                                        \
    } while (0)

    float acc[4][4][4];
#pragma unroll
    for (int i = 0; i < 4; i++)
#pragma unroll
        for (int j = 0; j < 4; j++)
#pragma unroll
            for (int r = 0; r < 4; r++) acc[i][j][r] = 0.f;

    LOAD_CHUNK(0);

    const int a_row = (lane & 15);
    const int a_c16 = (lane >> 4);
    const int b_nrow = (lane & 7) + ((lane >> 4) & 1) * 8;
    const int b_c16 = (lane >> 3) & 1;

    for (int kc = 0; kc < 8; ++kc) {
        if (kc + 1 < 8) { LOAD_CHUNK(kc + 1); cp_wait1(); } else { cp_wait0(); }
        __syncthreads();

        uint32_t st = sb + (kc & 1) * 32768;
#pragma unroll
        for (int ks = 0; ks < 4; ++ks) {
            uint32_t af[4][4];
#pragma unroll
            for (int mi = 0; mi < 4; ++mi) {
                uint32_t off = (uint32_t)(wr * 64 + mi * 16 + a_row) * 128 + ks * 32 + a_c16 * 16;
                uint32_t sw = off ^ ((off >> 3) & 0x70);
                ldsm_x4(af[mi][0], af[mi][1], af[mi][2], af[mi][3], st + sw);
            }
            uint32_t bf[2][4];
#pragma unroll
            for (int pr = 0; pr < 2; ++pr) {
                uint32_t off = (uint32_t)(wc * 32 + pr * 16 + b_nrow) * 128 + ks * 32 + b_c16 * 16;
                uint32_t sw = off ^ ((off >> 3) & 0x70);
                ldsm_x4(bf[pr][0], bf[pr][1], bf[pr][2], bf[pr][3], st + 16384 + sw);
            }
#pragma unroll
            for (int mi = 0; mi < 4; ++mi) {
#pragma unroll
                for (int pr = 0; pr < 2; ++pr) {
                    mma16816(acc[mi][pr * 2][0], acc[mi][pr * 2][1],
                             acc[mi][pr * 2][2], acc[mi][pr * 2][3],
                             af[mi][0], af[mi][1], af[mi][2], af[mi][3],
                             bf[pr][0], bf[pr][1]);
                    mma16816(acc[mi][pr * 2 + 1][0], acc[mi][pr * 2 + 1][1],
                             acc[mi][pr * 2 + 1][2], acc[mi][pr * 2 + 1][3],
                             af[mi][0], af[mi][1], af[mi][2], af[mi][3],
                             bf[pr][2], bf[pr][3]);
                }
            }
        }
        __syncthreads();
    }

#pragma unroll
    for (int mi = 0; mi < 4; ++mi) {
        int row0 = bm + wr * 64 + mi * 16 + (lane >> 2);
#pragma unroll
        for (int ni = 0; ni < 4; ++ni) {
            int col = bn + wc * 32 + ni * 8 + (lane & 3) * 2;
            *(float2*)(C + (size_t)row0 * Nn + col) = make_float2(acc[mi][ni][0], acc[mi][ni][1]);
            *(float2*)(C + (size_t)(row0 + 8) * Nn + col) = make_float2(acc[mi][ni][2], acc[mi][ni][3]);
        }
    }
#undef LOAD_CHUNK
}

// ---------------- attention: lane=node-pair, no per-score reductions ----------------
// grid (8, 64), block 640 = 20 warps (warp = query s). 16 tiles of 64 nodes.
__global__ __launch_bounds__(640, 1)
void attn_kernel(const float* __restrict__ qin)
{
    __shared__ __align__(16) char stg[2][16384];      // per stage: kT 8KB | v 8KB
    __shared__ __align__(8) __half2 sp[20][64];       // duplicated softmax weights
    const int h = blockIdx.x, b = blockIdx.y;
    const int tid = threadIdx.x;
    const int lane = tid & 31, w = tid >> 5;

    // q duplicated into half2 registers
    __half2 qh[64];
    {
        const float4* qrow = (const float4*)(qin + ((size_t)(b * 20 + w)) * 512 + h * 64);
#pragma unroll
        for (int i = 0; i < 16; i++) {
            float4 v = qrow[i];
            qh[4 * i + 0] = __floats2half2_rn(v.x, v.x);
            qh[4 * i + 1] = __floats2half2_rn(v.y, v.y);
            qh[4 * i + 2] = __floats2half2_rn(v.z, v.z);
            qh[4 * i + 3] = __floats2half2_rn(v.w, v.w);
        }
    }
    unsigned int mword = g_mbits[(b * 20 + w) * 32 + lane];   // lane l holds word l

    float m = -1e30f, l = 0.f;
    float2 accf = make_float2(0.f, 0.f);

#define ATTN_LOAD(t)                                                          \
    do {                                                                      \
        char* dst0 = stg[(t) & 1];                                            \
        int n0_ = (t) * 64;                                                   \
        for (int c = tid; c < 1024; c += 640) {                               \
            if (c < 512) {                                                    \
                int d_ = c >> 3, j_ = c & 7;                                  \
                const __half* src = g_kT + (((size_t)b * 8 + h) * 64 + d_) * 1024 + n0_ + j_ * 8; \
                cp_async16(smem_u32(dst0 + d_ * 128 + j_ * 16), src);         \
            } else {                                                          \
                int cv = c - 512; int n_ = cv >> 3, j_ = cv & 7;              \
                const __half* src = g_kvlh + ((size_t)b * 1000 + n0_ + n_) * 1536 + 512 + j_ * 8; \
                cp_async16(smem_u32(dst0 + 8192 + n_ * 128 + j_ * 16), src);  \
            }                                                                 \
        }                                                                     \
        cp_commit();                                                          \
    } while (0)

    ATTN_LOAD(0);

    for (int t = 0; t < 16; ++t) {
        if (t + 1 < 16) { ATTN_LOAD(t + 1); cp_wait1(); } else { cp_wait0(); }
        __syncthreads();
        const char* st = stg[t & 1];
        const __half2* kp = (const __half2*)st;
        const __half2* vp = (const __half2*)(st + 8192);

        // phase A: two scores per lane (n = n0+2l, n0+2l+1)
        __half2 a0 = __float2half2_rn(0.f), a1 = a0;
#pragma unroll
        for (int d = 0; d < 64; d += 2) {
            a0 = __hfma2(qh[d], kp[d * 32 + lane], a0);
            a1 = __hfma2(qh[d + 1], kp[(d + 1) * 32 + lane], a1);
        }
        float2 xf = __half22float2(__hadd2(a0, a1));
        float xa = xf.x * INV_SQRT_DK, xb = xf.y * INV_SQRT_DK;

        unsigned int wd = __shfl_sync(0xffffffffu, mword, t * 2 + (lane >> 4));
        int bi = (2 * lane) & 31;
        xa = ((wd >> bi) & 1u) ? xa : -1e30f;
        xb = ((wd >> (bi + 1)) & 1u) ? xb : -1e30f;

        // online softmax (one reduction per 64 scores)
        float tm = warp_max(fmaxf(xa, xb));
        float mn = fmaxf(m, tm);
        float corr = __expf(m - mn);
        float pa = __expf(xa - mn), pb = __expf(xb - mn);
        float ts = warp_sum(pa + pb);
        l = l * corr + ts;
        m = mn;

        sp[w][2 * lane] = __float2half2_rn(pa);
        sp[w][2 * lane + 1] = __float2half2_rn(pb);
        __syncwarp();

        // phase B: lane owns d-pair (2l, 2l+1), fp16 tile accumulator
        __half2 va = __float2half2_rn(0.f), vb = va;
#pragma unroll 16
        for (int nn = 0; nn < 64; nn += 2) {
            va = __hfma2(sp[w][nn], vp[nn * 32 + lane], va);
            vb = __hfma2(sp[w][nn + 1], vp[(nn + 1) * 32 + lane], vb);
        }
        float2 vf = __half22float2(__hadd2(va, vb));
        accf.x = accf.x * corr + vf.x;
        accf.y = accf.y * corr + vf.y;
        __syncthreads();   // all warps done with this buffer before its reload
    }
#undef ATTN_LOAD

    float inv = 1.f / l;
    *(float2*)(g_heads + ((size_t)(b * 20 + w)) * 512 + h * 64 + 2 * lane) =
        make_float2(accf.x * inv, accf.y * inv);
}

// ---------------- pointer logits (bitmask, hoisted load) ----------------
__global__ __launch_bounds__(256)
void pointer_kernel()
{
    __shared__ __align__(16) float sg[10 * 512];
    __shared__ __align__(16) float slk[8 * 512];
    const int b = blockIdx.x;
    const int sbase = blockIdx.y * 10;
    const int nsl = blockIdx.z;
    const int tid = threadIdx.x;

    for (int i = tid; i < 10 * 512 / 4; i += 256) {
        int off = i << 2;
        int s = off >> 9, d = off & 511;
        *(float4*)&sg[off] = *(const float4*)(g_glimpse + (size_t)(b * 20 + sbase + s) * 512 + d);
    }

    const int lane = tid & 31, w = tid >> 5;
    for (int t = 0; t < 25; ++t) {
        const int n0 = nsl * 200 + t * 8;
        __syncthreads();
        for (int i = tid; i < 8 * 512 / 8; i += 256) {
            int off = i << 3;
            int nn = off >> 9, d = off & 511;
            const __half* src = g_kvlh + ((size_t)b * 1000 + n0 + nn) * 1536 + 1024 + d;
            uint4 raw = *(const uint4*)src;
            const __half2* hp = (const __half2*)&raw;
            float2 f0 = __half22float2(hp[0]);
            float2 f1 = __half22float2(hp[1]);
            float2 f2 = __half22float2(hp[2]);
            float2 f3 = __half22float2(hp[3]);
            *(float4*)&slk[off] = make_float4(f0.x, f0.y, f1.x, f1.y);
            *(float4*)&slk[off + 4] = make_float4(f2.x, f2.y, f3.x, f3.y);
        }
        __syncthreads();
#pragma unroll
        for (int pp = 0; pp < 10; ++pp) {
            const int p = w * 10 + pp;
            const int sl = p >> 3, n = p & 7;
            const int gn = n0 + n;
            unsigned int wd = 0;
            if (lane == 0)
                wd = g_mbits[(b * 20 + sbase + sl) * 32 + (gn >> 5)];
            const float* gr = &sg[sl * 512];
            const float* kr = &slk[n * 512];
            float sum = 0.f;
#pragma unroll
            for (int i = 0; i < 16; ++i)
                sum += gr[lane + i * 32] * kr[lane + i * 32];
            sum = warp_sum(sum);
            if (lane == 0) {
                float lg = ((wd >> (gn & 31)) & 1u)
                         ? 10.f * tanhf(sum * INV_SQRT_D) : NEG_BIG;
                g_logits[(b * 20 + sbase + sl) * 1000 + gn] = lg;
            }
        }
    }
}

// ---------------- log-softmax + transposed writeout ----------------
__global__ __launch_bounds__(256)
void lsm_kernel(float* __restrict__ out)
{
    const int s = blockIdx.x, b = blockIdx.y;
    const float* row = g_logits + (size_t)(b * 20 + s) * 1000;
    float* orow = out + (size_t)(s * 64 + b) * 1000;
    __shared__ float red[8];
    const int tid = threadIdx.x;
    const int lane = tid & 31, w = tid >> 5;

    float mx = -1e30f;
    for (int i = tid; i < 1000; i += 256) mx = fmaxf(mx, row[i]);
    mx = warp_max(mx);
    if (lane == 0) red[w] = mx;
    __syncthreads();
    if (w == 0) {
        float v = (lane < 8) ? red[lane] : -1e30f;
        v = warp_max(v);
        if (lane == 0) red[0] = v;
    }
    __syncthreads();
    mx = red[0];
    __syncthreads();

    float se = 0.f;
    for (int i = tid; i < 1000; i += 256) se += __expf(row[i] - mx);
    se = warp_sum(se);
    if (lane == 0) red[w] = se;
    __syncthreads();
    if (w == 0) {
        float v = (lane < 8) ? red[lane] : 0.f;
        v = warp_sum(v);
        if (lane == 0) red[0] = v;
    }
    __syncthreads();
    const float lse = mx + logf(red[0]);

    for (int i = tid; i < 1000; i += 256) orow[i] = row[i] - lse;
}

// ---------------- launch ----------------
extern "C" void kernel_launch(void* const* d_in, const int* in_sizes, int n_in,
                              void* d_out, int out_size)
{
    (void)out_size;
    const float* emb = nullptr;
    const float* q = nullptr;
    const void* mask = nullptr;
    const float* Wkvl = nullptr;
    const float* Wout = nullptr;
    for (int i = 0; i < n_in; ++i) {
        switch (in_sizes[i]) {
            case 32768000: emb = (const float*)d_in[i]; break;
            case 655360:   q = (const float*)d_in[i]; break;
            case 1280000:  mask = d_in[i]; break;
            case 786432:   Wkvl = (const float*)d_in[i]; break;
            case 262144:   Wout = (const float*)d_in[i]; break;
            default: break;
        }
    }
    float* out = (float*)d_out;

    float *headsp, *glimpsep;
    __half *kvlhp, *af16, *wkt, *wot, *hf16;
    cudaGetSymbolAddress((void**)&kvlhp, g_kvlh);
    cudaGetSymbolAddress((void**)&headsp, g_heads);
    cudaGetSymbolAddress((void**)&glimpsep, g_glimpse);
    cudaGetSymbolAddress((void**)&af16, g_Af16);
    cudaGetSymbolAddress((void**)&wkt, g_Wkvl_t);
    cudaGetSymbolAddress((void**)&wot, g_Wout_t);
    cudaGetSymbolAddress((void**)&hf16, g_Hf16);

    cudaFuncSetAttribute(hmma_gemm_big, cudaFuncAttributeMaxDynamicSharedMemorySize, 147456);
    cudaFuncSetAttribute(hmma_gemm, cudaFuncAttributeMaxDynamicSharedMemorySize, 65536);

    mask_bits_kernel<<<1280, 256>>>((const unsigned int*)mask);         // 1
    prep_kernel<<<36096, 256>>>(emb, Wkvl, Wout);                       // 2

    // kvl GEMM (K section -> g_kT transposed, V/L -> g_kvlh)           // 3
    {
        dim3 grid(6, 500);
        hmma_gemm_big<<<grid, 256, 147456>>>(af16, wkt, kvlhp, 1536);
    }

    // attention                                                        // 4 (profiled)
    {
        dim3 grid(8, 64);
        attn_kernel<<<grid, 640>>>(q);
    }

    // glimpse = heads @ W_out
    conv_f16_kernel<<<640, 256>>>(headsp, hf16, 163840);                // 5
    {
        dim3 grid(4, 10);
        hmma_gemm<<<grid, 256, 65536>>>(hf16, wot, glimpsep, 512);      // 6
    }

    // pointer logits
    {
        dim3 grid(64, 2, 5);
        pointer_kernel<<<grid, 256>>>();                                // 7
    }

    // log-softmax
    {
        dim3 grid(20, 64);
        lsm_kernel<<<grid, 256>>>(out);                                 // 8
    }
}

// round 9
// speedup vs baseline: 1.5193x; 1.5193x over previous
#include <cuda_runtime.h>
#include <cuda_fp16.h>
#include <cstdint>

// B=64, N=1000, D=512, H=8, S=20, DK=64
#define NEG_BIG (-1e9f)
#define INV_SQRT_DK 0.125f
#define INV_SQRT_D 0.04419417382415922f

// ---------------- device scratch ----------------
__device__ __align__(16) __half g_kvlh[64032 * 1536];    // [row][gk|gv|lk], rows>=64000 zero
__device__ __align__(16) __half g_kT[64 * 8 * 64 * 1024]; // K transposed [b][h][d][n(pad 1024)]
__device__ __align__(16) float g_heads[1280 * 512];
__device__ __align__(16) float g_glimpse[1280 * 512];
__device__ __align__(16) float g_logits[1280 * 1000];
__device__ __align__(16) __half g_Af16[64000 * 512];
__device__ __align__(16) __half g_Wkvl_t[1536 * 512];
__device__ __align__(16) __half g_Wout_t[512 * 512];
__device__ __align__(16) __half g_Hf16[1280 * 512];
__device__ __align__(16) unsigned int g_mbits[1280 * 32]; // packed feasibility bits

// ---------------- helpers ----------------
__device__ __forceinline__ float warp_max(float v) {
#pragma unroll
    for (int o = 16; o; o >>= 1) v = fmaxf(v, __shfl_xor_sync(0xffffffffu, v, o));
    return v;
}
__device__ __forceinline__ float warp_sum(float v) {
#pragma unroll
    for (int o = 16; o; o >>= 1) v += __shfl_xor_sync(0xffffffffu, v, o);
    return v;
}
__device__ __forceinline__ uint32_t smem_u32(const void* p) {
    uint32_t a;
    asm("{ .reg .u64 t; cvta.to.shared.u64 t, %1; cvt.u32.u64 %0, t; }" : "=r"(a) : "l"(p));
    return a;
}
__device__ __forceinline__ void cp_async16(uint32_t saddr, const void* gaddr) {
    asm volatile("cp.async.cg.shared.global [%0], [%1], 16;" :: "r"(saddr), "l"(gaddr));
}
__device__ __forceinline__ void cp_commit() { asm volatile("cp.async.commit_group;" ::: "memory"); }
__device__ __forceinline__ void cp_wait1() { asm volatile("cp.async.wait_group 1;" ::: "memory"); }
__device__ __forceinline__ void cp_wait0() { asm volatile("cp.async.wait_group 0;" ::: "memory"); }

__device__ __forceinline__ void ldsm_x4(uint32_t& r0, uint32_t& r1, uint32_t& r2, uint32_t& r3,
                                        uint32_t addr) {
    asm volatile("ldmatrix.sync.aligned.m8n8.x4.shared.b16 {%0,%1,%2,%3}, [%4];"
                 : "=r"(r0), "=r"(r1), "=r"(r2), "=r"(r3) : "r"(addr));
}
__device__ __forceinline__ void mma16816(float& c0, float& c1, float& c2, float& c3,
                                         uint32_t a0, uint32_t a1, uint32_t a2, uint32_t a3,
                                         uint32_t b0, uint32_t b1) {
    asm volatile(
        "mma.sync.aligned.m16n8k16.row.col.f32.f16.f16.f32 "
        "{%0,%1,%2,%3}, {%4,%5,%6,%7}, {%8,%9}, {%0,%1,%2,%3};"
        : "+f"(c0), "+f"(c1), "+f"(c2), "+f"(c3)
        : "r"(a0), "r"(a1), "r"(a2), "r"(a3), "r"(b0), "r"(b1));
}

// ---------------- mask -> packed bits (self-detecting dtype) ----------------
__global__ __launch_bounds__(256)
void mask_bits_kernel(const unsigned int* __restrict__ mw)
{
    __shared__ int flags;
    if (threadIdx.x == 0) flags = 0;
    __syncthreads();
    int f = 0;
    for (int i = threadIdx.x; i < 1024; i += 256) {
        unsigned int v = mw[i];
        if (v != 0u && v != 1u) f |= 1;
        if (v != 0u && v != 0x3F800000u) f |= 2;
    }
    if (f) atomicOr(&flags, f);
    __syncthreads();
    const int mode = ((flags & 1) && (flags & 2)) ? 0 : 1;  // 0=bytes, 1=words

    const int lane = threadIdx.x & 31, wid = threadIdx.x >> 5;
    const int row = blockIdx.x;
#pragma unroll
    for (int j = 0; j < 4; j++) {
        int widx = wid * 4 + j;
        int n = widx * 32 + lane;
        bool feas = false;
        if (n < 1000) {
            int idx = row * 1000 + n;
            feas = mode ? (mw[idx] != 0u)
                        : (((const unsigned char*)mw)[idx] != 0);
        }
        unsigned int word = __ballot_sync(0xffffffffu, feas);
        if (lane == 0) g_mbits[row * 32 + widx] = word;
    }
}

// ---------------- fused prep ----------------
__global__ __launch_bounds__(256)
void prep_kernel(const float* __restrict__ emb, const float* __restrict__ Wkvl,
                 const float* __restrict__ Wout)
{
    int bid = blockIdx.x;
    int tid = threadIdx.x;
    if (bid < 32000) {
        int i = bid * 256 + tid;
        float4 v = ((const float4*)emb)[i];
        ((__half2*)g_Af16)[i * 2] = __floats2half2_rn(v.x, v.y);
        ((__half2*)g_Af16)[i * 2 + 1] = __floats2half2_rn(v.z, v.w);
    } else if (bid < 35072) {
        int idx = (bid - 32000) * 256 + tid;
        int n = idx >> 9, k = idx & 511;
        g_Wkvl_t[idx] = __float2half_rn(Wkvl[(size_t)k * 1536 + n]);
    } else {
        int idx = (bid - 35072) * 256 + tid;
        int n = idx >> 9, k = idx & 511;
        g_Wout_t[idx] = __float2half_rn(Wout[(size_t)k * 512 + n]);
    }
}

// ---------------- fp32 -> fp16 (heads) ----------------
__global__ __launch_bounds__(256)
void conv_f16_kernel(const float* __restrict__ x, __half* __restrict__ y, int n4)
{
    int i = blockIdx.x * 256 + threadIdx.x;
    if (i >= n4) return;
    float4 v = ((const float4*)x)[i];
    ((__half2*)y)[i * 2] = __floats2half2_rn(v.x, v.y);
    ((__half2*)y)[i * 2 + 1] = __floats2half2_rn(v.z, v.w);
}

// ---------------- K transpose: g_kvlh K-section -> g_kT[b][h][d][n] ----------------
// grid (32 n-tiles, 8 h, 64 b), block 256 = 8 warps; warp w owns d-chunk w*8..w*8+7,
// lane owns n = n0+lane. Writes coalesce across lanes (64 B per warp-step).
__global__ __launch_bounds__(256)
void ktrans_kernel()
{
    const int nt = blockIdx.x, h = blockIdx.y, b = blockIdx.z;
    const int lane = threadIdx.x & 31, w = threadIdx.x >> 5;
    const int n = nt * 32 + lane;

    uint4 v = make_uint4(0u, 0u, 0u, 0u);
    if (n < 1000)
        v = *(const uint4*)(g_kvlh + ((size_t)b * 1000 + n) * 1536 + h * 64 + w * 8);
    const __half* hv = (const __half*)&v;

    __half* outb = g_kT + (((size_t)b * 8 + h) * 64 + w * 8) * 1024 + nt * 32 + lane;
#pragma unroll
    for (int k = 0; k < 8; ++k)
        outb[(size_t)k * 1024] = hv[k];
}

// ---------------- BIG fp16 HMMA GEMM: 128x256 tile, coalesced epilogue ----------------
__global__ __launch_bounds__(256)
void hmma_gemm_big(const __half* __restrict__ A, const __half* __restrict__ Bt,
                   __half* __restrict__ C, int Nn)
{
    extern __shared__ char dsm[];
    const uint32_t sb = smem_u32(dsm);
    const int tid = threadIdx.x;
    const int bm = blockIdx.y * 128;
    const int bn = blockIdx.x * 256;
    const int lane = tid & 31, w = tid >> 5;
    const int wr = w >> 2;
    const int wc = w & 3;

    const char* Ag = (const char*)A + (size_t)bm * 1024;
    const char* Bg = (const char*)Bt + (size_t)bn * 1024;

#define LOAD_CHUNK(kc)                                                      \
    do {                                                                    \
        uint32_t st_ = sb + ((kc) % 3) * 49152;                             \
        size_t gk_ = (size_t)(kc) * 128;                                    \
        _Pragma("unroll")                                                   \
        for (int i_ = 0; i_ < 4; i_++) {                                    \
            int g_ = tid + i_ * 256;                                        \
            int row_ = g_ >> 3, ch_ = g_ & 7;                               \
            uint32_t off_ = row_ * 128 + ch_ * 16;                          \
            uint32_t sw_ = off_ ^ ((off_ >> 3) & 0x70);                     \
            cp_async16(st_ + sw_, Ag + (size_t)row_ * 1024 + gk_ + ch_ * 16); \
        }                                                                   \
        _Pragma("unroll")                                                   \
        for (int i_ = 0; i_ < 8; i_++) {                                    \
            int g_ = tid + i_ * 256;                                        \
            int row_ = g_ >> 3, ch_ = g_ & 7;                               \
            uint32_t off_ = row_ * 128 + ch_ * 16;                          \
            uint32_t sw_ = off_ ^ ((off_ >> 3) & 0x70);                     \
            cp_async16(st_ + 16384 + sw_, Bg + (size_t)row_ * 1024 + gk_ + ch_ * 16); \
        }                                                                   \
        cp_commit();                                                        \
    } while (0)

    float acc[4][8][4];
#pragma unroll
    for (int i = 0; i < 4; i++)
#pragma unroll
        for (int j = 0; j < 8; j++)
#pragma unroll
            for (int r = 0; r < 4; r++) acc[i][j][r] = 0.f;

    LOAD_CHUNK(0);
    LOAD_CHUNK(1);

    const int a_row = (lane & 15);
    const int a_c16 = (lane >> 4);
    const int b_nrow = (lane & 7) + ((lane >> 4) & 1) * 8;
    const int b_c16 = (lane >> 3) & 1;

    for (int kc = 0; kc < 8; ++kc) {
        if (kc == 7) cp_wait0(); else cp_wait1();
        __syncthreads();
        if (kc + 2 < 8) LOAD_CHUNK(kc + 2);

        uint32_t st = sb + (kc % 3) * 49152;
#pragma unroll
        for (int ks = 0; ks < 4; ++ks) {
            uint32_t af[4][4];
#pragma unroll
            for (int mi = 0; mi < 4; ++mi) {
                uint32_t off = (uint32_t)(wr * 64 + mi * 16 + a_row) * 128 + ks * 32 + a_c16 * 16;
                uint32_t sw = off ^ ((off >> 3) & 0x70);
                ldsm_x4(af[mi][0], af[mi][1], af[mi][2], af[mi][3], st + sw);
            }
            uint32_t bf[4][4];
#pragma unroll
            for (int pr = 0; pr < 4; ++pr) {
                uint32_t off = (uint32_t)(wc * 64 + pr * 16 + b_nrow) * 128 + ks * 32 + b_c16 * 16;
                uint32_t sw = off ^ ((off >> 3) & 0x70);
                ldsm_x4(bf[pr][0], bf[pr][1], bf[pr][2], bf[pr][3], st + 16384 + sw);
            }
#pragma unroll
            for (int mi = 0; mi < 4; ++mi) {
#pragma unroll
                for (int pr = 0; pr < 4; ++pr) {
                    mma16816(acc[mi][pr * 2][0], acc[mi][pr * 2][1],
                             acc[mi][pr * 2][2], acc[mi][pr * 2][3],
                             af[mi][0], af[mi][1], af[mi][2], af[mi][3],
                             bf[pr][0], bf[pr][1]);
                    mma16816(acc[mi][pr * 2 + 1][0], acc[mi][pr * 2 + 1][1],
                             acc[mi][pr * 2 + 1][2], acc[mi][pr * 2 + 1][3],
                             af[mi][0], af[mi][1], af[mi][2], af[mi][3],
                             bf[pr][2], bf[pr][3]);
                }
            }
        }
    }
    __syncthreads();

#pragma unroll
    for (int mi = 0; mi < 4; ++mi) {
        int row0 = bm + wr * 64 + mi * 16 + (lane >> 2);
#pragma unroll
        for (int ni = 0; ni < 8; ++ni) {
            int col = bn + wc * 64 + ni * 8 + (lane & 3) * 2;
            *(__half2*)(C + (size_t)row0 * Nn + col) =
                __floats2half2_rn(acc[mi][ni][0], acc[mi][ni][1]);
            *(__half2*)(C + (size_t)(row0 + 8) * Nn + col) =
                __floats2half2_rn(acc[mi][ni][2], acc[mi][ni][3]);
        }
    }
#undef LOAD_CHUNK
}

// ---------------- small fp16 HMMA GEMM (glimpse): 128x128, fp32 out ----------------
__global__ __launch_bounds__(256, 2)
void hmma_gemm(const __half* __restrict__ A, const __half* __restrict__ Bt,
               float* __restrict__ C, int Nn)
{
    extern __shared__ char dsm[];
    const uint32_t sb = smem_u32(dsm);
    const int tid = threadIdx.x;
    const int bm = blockIdx.y * 128;
    const int bn = blockIdx.x * 128;
    const int lane = tid & 31, w = tid >> 5;
    const int wr = w >> 2;
    const int wc = w & 3;

    const char* Ag = (const char*)A + (size_t)bm * 1024;
    const char* Bg = (const char*)Bt + (size_t)bn * 1024;

#define LOAD_CHUNK(kc)                                                      \
    do {                                                                    \
        uint32_t st_ = sb + ((kc) & 1) * 32768;                             \
        size_t gk_ = (size_t)(kc) * 128;                                    \
        _Pragma("unroll")                                                   \
        for (int i_ = 0; i_ < 4; i_++) {                                    \
            int g_ = tid + i_ * 256;                                        \
            int row_ = g_ >> 3, ch_ = g_ & 7;                               \
            uint32_t off_ = row_ * 128 + ch_ * 16;                          \
            uint32_t sw_ = off_ ^ ((off_ >> 3) & 0x70);                     \
            size_t go_ = (size_t)row_ * 1024 + gk_ + ch_ * 16;              \
            cp_async16(st_ + sw_, Ag + go_);                                \
            cp_async16(st_ + 16384 + sw_, Bg + go_);                        \
        }                                                                   \
        cp_commit();                                                        \
    } while (0)

    float acc[4][4][4];
#pragma unroll
    for (int i = 0; i < 4; i++)
#pragma unroll
        for (int j = 0; j < 4; j++)
#pragma unroll
            for (int r = 0; r < 4; r++) acc[i][j][r] = 0.f;

    LOAD_CHUNK(0);

    const int a_row = (lane & 15);
    const int a_c16 = (lane >> 4);
    const int b_nrow = (lane & 7) + ((lane >> 4) & 1) * 8;
    const int b_c16 = (lane >> 3) & 1;

    for (int kc = 0; kc < 8; ++kc) {
        if (kc + 1 < 8) { LOAD_CHUNK(kc + 1); cp_wait1(); } else { cp_wait0(); }
        __syncthreads();

        uint32_t st = sb + (kc & 1) * 32768;
#pragma unroll
        for (int ks = 0; ks < 4; ++ks) {
            uint32_t af[4][4];
#pragma unroll
            for (int mi = 0; mi < 4; ++mi) {
                uint32_t off = (uint32_t)(wr * 64 + mi * 16 + a_row) * 128 + ks * 32 + a_c16 * 16;
                uint32_t sw = off ^ ((off >> 3) & 0x70);
                ldsm_x4(af[mi][0], af[mi][1], af[mi][2], af[mi][3], st + sw);
            }
            uint32_t bf[2][4];
#pragma unroll
            for (int pr = 0; pr < 2; ++pr) {
                uint32_t off = (uint32_t)(wc * 32 + pr * 16 + b_nrow) * 128 + ks * 32 + b_c16 * 16;
                uint32_t sw = off ^ ((off >> 3) & 0x70);
                ldsm_x4(bf[pr][0], bf[pr][1], bf[pr][2], bf[pr][3], st + 16384 + sw);
            }
#pragma unroll
            for (int mi = 0; mi < 4; ++mi) {
#pragma unroll
                for (int pr = 0; pr < 2; ++pr) {
                    mma16816(acc[mi][pr * 2][0], acc[mi][pr * 2][1],
                             acc[mi][pr * 2][2], acc[mi][pr * 2][3],
                             af[mi][0], af[mi][1], af[mi][2], af[mi][3],
                             bf[pr][0], bf[pr][1]);
                    mma16816(acc[mi][pr * 2 + 1][0], acc[mi][pr * 2 + 1][1],
                             acc[mi][pr * 2 + 1][2], acc[mi][pr * 2 + 1][3],
                             af[mi][0], af[mi][1], af[mi][2], af[mi][3],
                             bf[pr][2], bf[pr][3]);
                }
            }
        }
        __syncthreads();
    }

#pragma unroll
    for (int mi = 0; mi < 4; ++mi) {
        int row0 = bm + wr * 64 + mi * 16 + (lane >> 2);
#pragma unroll
        for (int ni = 0; ni < 4; ++ni) {
            int col = bn + wc * 32 + ni * 8 + (lane & 3) * 2;
            *(float2*)(C + (size_t)row0 * Nn + col) = make_float2(acc[mi][ni][0], acc[mi][ni][1]);
            *(float2*)(C + (size_t)(row0 + 8) * Nn + col) = make_float2(acc[mi][ni][2], acc[mi][ni][3]);
        }
    }
#undef LOAD_CHUNK
}

// ---------------- attention: lane=node-pair, no per-score reductions ----------------
__global__ __launch_bounds__(640, 1)
void attn_kernel(const float* __restrict__ qin)
{
    __shared__ __align__(16) char stg[2][16384];      // per stage: kT 8KB | v 8KB
    __shared__ __align__(8) __half2 sp[20][64];       // duplicated softmax weights
    const int h = blockIdx.x, b = blockIdx.y;
    const int tid = threadIdx.x;
    const int lane = tid & 31, w = tid >> 5;

    __half2 qh[64];
    {
        const float4* qrow = (const float4*)(qin + ((size_t)(b * 20 + w)) * 512 + h * 64);
#pragma unroll
        for (int i = 0; i < 16; i++) {
            float4 v = qrow[i];
            qh[4 * i + 0] = __floats2half2_rn(v.x, v.x);
            qh[4 * i + 1] = __floats2half2_rn(v.y, v.y);
            qh[4 * i + 2] = __floats2half2_rn(v.z, v.z);
            qh[4 * i + 3] = __floats2half2_rn(v.w, v.w);
        }
    }
    unsigned int mword = g_mbits[(b * 20 + w) * 32 + lane];

    float m = -1e30f, l = 0.f;
    float2 accf = make_float2(0.f, 0.f);

#define ATTN_LOAD(t)                                                          \
    do {                                                                      \
        char* dst0 = stg[(t) & 1];                                            \
        int n0_ = (t) * 64;                                                   \
        for (int c = tid; c < 1024; c += 640) {                               \
            if (c < 512) {                                                    \
                int d_ = c >> 3, j_ = c & 7;                                  \
                const __half* src = g_kT + (((size_t)b * 8 + h) * 64 + d_) * 1024 + n0_ + j_ * 8; \
                cp_async16(smem_u32(dst0 + d_ * 128 + j_ * 16), src);         \
            } else {                                                          \
                int cv = c - 512; int n_ = cv >> 3, j_ = cv & 7;              \
                const __half* src = g_kvlh + ((size_t)b * 1000 + n0_ + n_) * 1536 + 512 + j_ * 8; \
                cp_async16(smem_u32(dst0 + 8192 + n_ * 128 + j_ * 16), src);  \
            }                                                                 \
        }                                                                     \
        cp_commit();                                                          \
    } while (0)

    ATTN_LOAD(0);

    for (int t = 0; t < 16; ++t) {
        if (t + 1 < 16) { ATTN_LOAD(t + 1); cp_wait1(); } else { cp_wait0(); }
        __syncthreads();
        const char* st = stg[t & 1];
        const __half2* kp = (const __half2*)st;
        const __half2* vp = (const __half2*)(st + 8192);

        __half2 a0 = __float2half2_rn(0.f), a1 = a0;
#pragma unroll
        for (int d = 0; d < 64; d += 2) {
            a0 = __hfma2(qh[d], kp[d * 32 + lane], a0);
            a1 = __hfma2(qh[d + 1], kp[(d + 1) * 32 + lane], a1);
        }
        float2 xf = __half22float2(__hadd2(a0, a1));
        float xa = xf.x * INV_SQRT_DK, xb = xf.y * INV_SQRT_DK;

        unsigned int wd = __shfl_sync(0xffffffffu, mword, t * 2 + (lane >> 4));
        int bi = (2 * lane) & 31;
        xa = ((wd >> bi) & 1u) ? xa : -1e30f;
        xb = ((wd >> (bi + 1)) & 1u) ? xb : -1e30f;

        float tm = warp_max(fmaxf(xa, xb));
        float mn = fmaxf(m, tm);
        float corr = __expf(m - mn);
        float pa = __expf(xa - mn), pb = __expf(xb - mn);
        float ts = warp_sum(pa + pb);
        l = l * corr + ts;
        m = mn;

        sp[w][2 * lane] = __float2half2_rn(pa);
        sp[w][2 * lane + 1] = __float2half2_rn(pb);
        __syncwarp();

        __half2 va = __float2half2_rn(0.f), vb = va;
#pragma unroll 16
        for (int nn = 0; nn < 64; nn += 2) {
            va = __hfma2(sp[w][nn], vp[nn * 32 + lane], va);
            vb = __hfma2(sp[w][nn + 1], vp[(nn + 1) * 32 + lane], vb);
        }
        float2 vf = __half22float2(__hadd2(va, vb));
        accf.x = accf.x * corr + vf.x;
        accf.y = accf.y * corr + vf.y;
        __syncthreads();
    }
#undef ATTN_LOAD

    float inv = 1.f / l;
    *(float2*)(g_heads + ((size_t)(b * 20 + w)) * 512 + h * 64 + 2 * lane) =
        make_float2(accf.x * inv, accf.y * inv);
}

// ---------------- pointer logits (bitmask, hoisted load) ----------------
__global__ __launch_bounds__(256)
void pointer_kernel()
{
    __shared__ __align__(16) float sg[10 * 512];
    __shared__ __align__(16) float slk[8 * 512];
    const int b = blockIdx.x;
    const int sbase = blockIdx.y * 10;
    const int nsl = blockIdx.z;
    const int tid = threadIdx.x;

    for (int i = tid; i < 10 * 512 / 4; i += 256) {
        int off = i << 2;
        int s = off >> 9, d = off & 511;
        *(float4*)&sg[off] = *(const float4*)(g_glimpse + (size_t)(b * 20 + sbase + s) * 512 + d);
    }

    const int lane = tid & 31, w = tid >> 5;
    for (int t = 0; t < 25; ++t) {
        const int n0 = nsl * 200 + t * 8;
        __syncthreads();
        for (int i = tid; i < 8 * 512 / 8; i += 256) {
            int off = i << 3;
            int nn = off >> 9, d = off & 511;
            const __half* src = g_kvlh + ((size_t)b * 1000 + n0 + nn) * 1536 + 1024 + d;
            uint4 raw = *(const uint4*)src;
            const __half2* hp = (const __half2*)&raw;
            float2 f0 = __half22float2(hp[0]);
            float2 f1 = __half22float2(hp[1]);
            float2 f2 = __half22float2(hp[2]);
            float2 f3 = __half22float2(hp[3]);
            *(float4*)&slk[off] = make_float4(f0.x, f0.y, f1.x, f1.y);
            *(float4*)&slk[off + 4] = make_float4(f2.x, f2.y, f3.x, f3.y);
        }
        __syncthreads();
#pragma unroll
        for (int pp = 0; pp < 10; ++pp) {
            const int p = w * 10 + pp;
            const int sl = p >> 3, n = p & 7;
            const int gn = n0 + n;
            unsigned int wd = 0;
            if (lane == 0)
                wd = g_mbits[(b * 20 + sbase + sl) * 32 + (gn >> 5)];
            const float* gr = &sg[sl * 512];
            const float* kr = &slk[n * 512];
            float sum = 0.f;
#pragma unroll
            for (int i = 0; i < 16; ++i)
                sum += gr[lane + i * 32] * kr[lane + i * 32];
            sum = warp_sum(sum);
            if (lane == 0) {
                float lg = ((wd >> (gn & 31)) & 1u)
                         ? 10.f * tanhf(sum * INV_SQRT_D) : NEG_BIG;
                g_logits[(b * 20 + sbase + sl) * 1000 + gn] = lg;
            }
        }
    }
}

// ---------------- log-softmax + transposed writeout ----------------
__global__ __launch_bounds__(256)
void lsm_kernel(float* __restrict__ out)
{
    const int s = blockIdx.x, b = blockIdx.y;
    const float* row = g_logits + (size_t)(b * 20 + s) * 1000;
    float* orow = out + (size_t)(s * 64 + b) * 1000;
    __shared__ float red[8];
    const int tid = threadIdx.x;
    const int lane = tid & 31, w = tid >> 5;

    float mx = -1e30f;
    for (int i = tid; i < 1000; i += 256) mx = fmaxf(mx, row[i]);
    mx = warp_max(mx);
    if (lane == 0) red[w] = mx;
    __syncthreads();
    if (w == 0) {
        float v = (lane < 8) ? red[lane] : -1e30f;
        v = warp_max(v);
        if (lane == 0) red[0] = v;
    }
    __syncthreads();
    mx = red[0];
    __syncthreads();

    float se = 0.f;
    for (int i = tid; i < 1000; i += 256) se += __expf(row[i] - mx);
    se = warp_sum(se);
    if (lane == 0) red[w] = se;
    __syncthreads();
    if (w == 0) {
        float v = (lane < 8) ? red[lane] : 0.f;
        v = warp_sum(v);
        if (lane == 0) red[0] = v;
    }
    __syncthreads();
    const float lse = mx + logf(red[0]);

    for (int i = tid; i < 1000; i += 256) orow[i] = row[i] - lse;
}

// ---------------- launch ----------------
extern "C" void kernel_launch(void* const* d_in, const int* in_sizes, int n_in,
                              void* d_out, int out_size)
{
    (void)out_size;
    const float* emb = nullptr;
    const float* q = nullptr;
    const void* mask = nullptr;
    const float* Wkvl = nullptr;
    const float* Wout = nullptr;
    for (int i = 0; i < n_in; ++i) {
        switch (in_sizes[i]) {
            case 32768000: emb = (const float*)d_in[i]; break;
            case 655360:   q = (const float*)d_in[i]; break;
            case 1280000:  mask = d_in[i]; break;
            case 786432:   Wkvl = (const float*)d_in[i]; break;
            case 262144:   Wout = (const float*)d_in[i]; break;
            default: break;
        }
    }
    float* out = (float*)d_out;

    float *headsp, *glimpsep;
    __half *kvlhp, *af16, *wkt, *wot, *hf16;
    cudaGetSymbolAddress((void**)&kvlhp, g_kvlh);
    cudaGetSymbolAddress((void**)&headsp, g_heads);
    cudaGetSymbolAddress((void**)&glimpsep, g_glimpse);
    cudaGetSymbolAddress((void**)&af16, g_Af16);
    cudaGetSymbolAddress((void**)&wkt, g_Wkvl_t);
    cudaGetSymbolAddress((void**)&wot, g_Wout_t);
    cudaGetSymbolAddress((void**)&hf16, g_Hf16);

    cudaFuncSetAttribute(hmma_gemm_big, cudaFuncAttributeMaxDynamicSharedMemorySize, 147456);
    cudaFuncSetAttribute(hmma_gemm, cudaFuncAttributeMaxDynamicSharedMemorySize, 65536);

    mask_bits_kernel<<<1280, 256>>>((const unsigned int*)mask);         // 1
    prep_kernel<<<36096, 256>>>(emb, Wkvl, Wout);                       // 2

    // kvl GEMM (fully coalesced epilogue)                              // 3
    {
        dim3 grid(6, 500);
        hmma_gemm_big<<<grid, 256, 147456>>>(af16, wkt, kvlhp, 1536);
    }

    // K transpose                                                      // 4 (profiled)
    {
        dim3 grid(32, 8, 64);
        ktrans_kernel<<<grid, 256>>>();
    }

    // attention                                                        // 5
    {
        dim3 grid(8, 64);
        attn_kernel<<<grid, 640>>>(q);
    }

    // glimpse = heads @ W_out
    conv_f16_kernel<<<640, 256>>>(headsp, hf16, 163840);                // 6
    {
        dim3 grid(4, 10);
        hmma_gemm<<<grid, 256, 65536>>>(hf16, wot, glimpsep, 512);      // 7
    }

    // pointer logits
    {
        dim3 grid(64, 2, 5);
        pointer_kernel<<<grid, 256>>>();                                // 8
    }

    // log-softmax
    {
        dim3 grid(20, 64);
        lsm_kernel<<<grid, 256>>>(out);                                 // 9
    }
}

// round 11
// speedup vs baseline: 1.6764x; 1.1034x over previous
#include <cuda_runtime.h>
#include <cuda_fp16.h>
#include <cstdint>

// B=64, N=1000, D=512, H=8, S=20, DK=64
#define NEG_BIG (-1e9f)
#define INV_SQRT_DK 0.125f
#define INV_SQRT_D 0.04419417382415922f

// ---------------- device scratch ----------------
__device__ __align__(16) __half g_kvlh[64032 * 1536];     // [row][gk|gv|lk], rows>=64000 pad
__device__ __align__(16) __half g_vT[64 * 8 * 64 * 1024]; // V transposed [b][h][d][n(pad 1024)]
__device__ __align__(16) float g_glimpse[1280 * 512];
__device__ __align__(16) float g_logits[1280 * 1000];
__device__ __align__(16) __half g_Af16[64000 * 512];
__device__ __align__(16) __half g_Wkvl_t[1536 * 512];
__device__ __align__(16) __half g_Wout_t[512 * 512];
__device__ __align__(16) __half g_Hf16[1280 * 512];       // heads fp16 (written by attn)
__device__ __align__(16) unsigned int g_mbits[1280 * 32]; // packed feasibility bits

// ---------------- helpers ----------------
__device__ __forceinline__ float warp_max(float v) {
#pragma unroll
    for (int o = 16; o; o >>= 1) v = fmaxf(v, __shfl_xor_sync(0xffffffffu, v, o));
    return v;
}
__device__ __forceinline__ float warp_sum(float v) {
#pragma unroll
    for (int o = 16; o; o >>= 1) v += __shfl_xor_sync(0xffffffffu, v, o);
    return v;
}
__device__ __forceinline__ uint32_t smem_u32(const void* p) {
    uint32_t a;
    asm("{ .reg .u64 t; cvta.to.shared.u64 t, %1; cvt.u32.u64 %0, t; }" : "=r"(a) : "l"(p));
    return a;
}
__device__ __forceinline__ void cp_async16(uint32_t saddr, const void* gaddr) {
    asm volatile("cp.async.cg.shared.global [%0], [%1], 16;" :: "r"(saddr), "l"(gaddr));
}
__device__ __forceinline__ void cp_commit() { asm volatile("cp.async.commit_group;" ::: "memory"); }
__device__ __forceinline__ void cp_wait1() { asm volatile("cp.async.wait_group 1;" ::: "memory"); }
__device__ __forceinline__ void cp_wait0() { asm volatile("cp.async.wait_group 0;" ::: "memory"); }

__device__ __forceinline__ void ldsm_x4(uint32_t& r0, uint32_t& r1, uint32_t& r2, uint32_t& r3,
                                        uint32_t addr) {
    asm volatile("ldmatrix.sync.aligned.m8n8.x4.shared.b16 {%0,%1,%2,%3}, [%4];"
                 : "=r"(r0), "=r"(r1), "=r"(r2), "=r"(r3) : "r"(addr));
}
__device__ __forceinline__ void mma16816(float& c0, float& c1, float& c2, float& c3,
                                         uint32_t a0, uint32_t a1, uint32_t a2, uint32_t a3,
                                         uint32_t b0, uint32_t b1) {
    asm volatile(
        "mma.sync.aligned.m16n8k16.row.col.f32.f16.f16.f32 "
        "{%0,%1,%2,%3}, {%4,%5,%6,%7}, {%8,%9}, {%0,%1,%2,%3};"
        : "+f"(c0), "+f"(c1), "+f"(c2), "+f"(c3)
        : "r"(a0), "r"(a1), "r"(a2), "r"(a3), "r"(b0), "r"(b1));
}

// ---------------- mask -> packed bits ----------------
__global__ __launch_bounds__(256)
void mask_bits_kernel(const unsigned int* __restrict__ mw)
{
    __shared__ int flags;
    if (threadIdx.x == 0) flags = 0;
    __syncthreads();
    int f = 0;
    for (int i = threadIdx.x; i < 1024; i += 256) {
        unsigned int v = mw[i];
        if (v != 0u && v != 1u) f |= 1;
        if (v != 0u && v != 0x3F800000u) f |= 2;
    }
    if (f) atomicOr(&flags, f);
    __syncthreads();
    const int mode = ((flags & 1) && (flags & 2)) ? 0 : 1;

    const int lane = threadIdx.x & 31, wid = threadIdx.x >> 5;
    const int row = blockIdx.x;
#pragma unroll
    for (int j = 0; j < 4; j++) {
        int widx = wid * 4 + j;
        int n = widx * 32 + lane;
        bool feas = false;
        if (n < 1000) {
            int idx = row * 1000 + n;
            feas = mode ? (mw[idx] != 0u)
                        : (((const unsigned char*)mw)[idx] != 0);
        }
        unsigned int word = __ballot_sync(0xffffffffu, feas);
        if (lane == 0) g_mbits[row * 32 + widx] = word;
    }
}

// ---------------- fused prep ----------------
__global__ __launch_bounds__(256)
void prep_kernel(const float* __restrict__ emb, const float* __restrict__ Wkvl,
                 const float* __restrict__ Wout)
{
    int bid = blockIdx.x;
    int tid = threadIdx.x;
    if (bid < 32000) {
        int i = bid * 256 + tid;
        float4 v = ((const float4*)emb)[i];
        ((__half2*)g_Af16)[i * 2] = __floats2half2_rn(v.x, v.y);
        ((__half2*)g_Af16)[i * 2 + 1] = __floats2half2_rn(v.z, v.w);
    } else if (bid < 35072) {
        int idx = (bid - 32000) * 256 + tid;
        int n = idx >> 9, k = idx & 511;
        g_Wkvl_t[idx] = __float2half_rn(Wkvl[(size_t)k * 1536 + n]);
    } else {
        int idx = (bid - 35072) * 256 + tid;
        int n = idx >> 9, k = idx & 511;
        g_Wout_t[idx] = __float2half_rn(Wout[(size_t)k * 512 + n]);
    }
}

// ---------------- V transpose: g_kvlh V-section -> g_vT[b][h][d][n] ----------------
__global__ __launch_bounds__(256)
void vtrans_kernel()
{
    const int nt = blockIdx.x, h = blockIdx.y, b = blockIdx.z;
    const int lane = threadIdx.x & 31, w = threadIdx.x >> 5;
    const int n = nt * 32 + lane;

    uint4 v = make_uint4(0u, 0u, 0u, 0u);
    if (n < 1000)
        v = *(const uint4*)(g_kvlh + ((size_t)b * 1000 + n) * 1536 + 512 + h * 64 + w * 8);
    const __half* hv = (const __half*)&v;

    __half* outb = g_vT + (((size_t)b * 8 + h) * 64 + w * 8) * 1024 + nt * 32 + lane;
#pragma unroll
    for (int k = 0; k < 8; ++k)
        outb[(size_t)k * 1024] = hv[k];
}

// ---------------- BIG fp16 HMMA GEMM: 128x256 tile ----------------
__global__ __launch_bounds__(256)
void hmma_gemm_big(const __half* __restrict__ A, const __half* __restrict__ Bt,
                   __half* __restrict__ C, int Nn)
{
    extern __shared__ char dsm[];
    const uint32_t sb = smem_u32(dsm);
    const int tid = threadIdx.x;
    const int bm = blockIdx.y * 128;
    const int bn = blockIdx.x * 256;
    const int lane = tid & 31, w = tid >> 5;
    const int wr = w >> 2;
    const int wc = w & 3;

    const char* Ag = (const char*)A + (size_t)bm * 1024;
    const char* Bg = (const char*)Bt + (size_t)bn * 1024;

#define LOAD_CHUNK(kc)                                                      \
    do {                                                                    \
        uint32_t st_ = sb + ((kc) % 3) * 49152;                             \
        size_t gk_ = (size_t)(kc) * 128;                                    \
        _Pragma("unroll")                                                   \
        for (int i_ = 0; i_ < 4; i_++) {                                    \
            int g_ = tid + i_ * 256;                                        \
            int row_ = g_ >> 3, ch_ = g_ & 7;                               \
            uint32_t off_ = row_ * 128 + ch_ * 16;                          \
            uint32_t sw_ = off_ ^ ((off_ >> 3) & 0x70);                     \
            cp_async16(st_ + sw_, Ag + (size_t)row_ * 1024 + gk_ + ch_ * 16); \
        }                                                                   \
        _Pragma("unroll")                                                   \
        for (int i_ = 0; i_ < 8; i_++) {                                    \
            int g_ = tid + i_ * 256;                                        \
            int row_ = g_ >> 3, ch_ = g_ & 7;                               \
            uint32_t off_ = row_ * 128 + ch_ * 16;                          \
            uint32_t sw_ = off_ ^ ((off_ >> 3) & 0x70);                     \
            cp_async16(st_ + 16384 + sw_, Bg + (size_t)row_ * 1024 + gk_ + ch_ * 16); \
        }                                                                   \
        cp_commit();                                                        \
    } while (0)

    float acc[4][8][4];
#pragma unroll
    for (int i = 0; i < 4; i++)
#pragma unroll
        for (int j = 0; j < 8; j++)
#pragma unroll
            for (int r = 0; r < 4; r++) acc[i][j][r] = 0.f;

    LOAD_CHUNK(0);
    LOAD_CHUNK(1);

    const int a_row = (lane & 15);
    const int a_c16 = (lane >> 4);
    const int b_nrow = (lane & 7) + ((lane >> 4) & 1) * 8;
    const int b_c16 = (lane >> 3) & 1;

    for (int kc = 0; kc < 8; ++kc) {
        if (kc == 7) cp_wait0(); else cp_wait1();
        __syncthreads();
        if (kc + 2 < 8) LOAD_CHUNK(kc + 2);

        uint32_t st = sb + (kc % 3) * 49152;
#pragma unroll
        for (int ks = 0; ks < 4; ++ks) {
            uint32_t af[4][4];
#pragma unroll
            for (int mi = 0; mi < 4; ++mi) {
                uint32_t off = (uint32_t)(wr * 64 + mi * 16 + a_row) * 128 + ks * 32 + a_c16 * 16;
                uint32_t sw = off ^ ((off >> 3) & 0x70);
                ldsm_x4(af[mi][0], af[mi][1], af[mi][2], af[mi][3], st + sw);
            }
            uint32_t bf[4][4];
#pragma unroll
            for (int pr = 0; pr < 4; ++pr) {
                uint32_t off = (uint32_t)(wc * 64 + pr * 16 + b_nrow) * 128 + ks * 32 + b_c16 * 16;
                uint32_t sw = off ^ ((off >> 3) & 0x70);
                ldsm_x4(bf[pr][0], bf[pr][1], bf[pr][2], bf[pr][3], st + 16384 + sw);
            }
#pragma unroll
            for (int mi = 0; mi < 4; ++mi) {
#pragma unroll
                for (int pr = 0; pr < 4; ++pr) {
                    mma16816(acc[mi][pr * 2][0], acc[mi][pr * 2][1],
                             acc[mi][pr * 2][2], acc[mi][pr * 2][3],
                             af[mi][0], af[mi][1], af[mi][2], af[mi][3],
                             bf[pr][0], bf[pr][1]);
                    mma16816(acc[mi][pr * 2 + 1][0], acc[mi][pr * 2 + 1][1],
                             acc[mi][pr * 2 + 1][2], acc[mi][pr * 2 + 1][3],
                             af[mi][0], af[mi][1], af[mi][2], af[mi][3],
                             bf[pr][2], bf[pr][3]);
                }
            }
        }
    }
    __syncthreads();

#pragma unroll
    for (int mi = 0; mi < 4; ++mi) {
        int row0 = bm + wr * 64 + mi * 16 + (lane >> 2);
#pragma unroll
        for (int ni = 0; ni < 8; ++ni) {
            int col = bn + wc * 64 + ni * 8 + (lane & 3) * 2;
            *(__half2*)(C + (size_t)row0 * Nn + col) =
                __floats2half2_rn(acc[mi][ni][0], acc[mi][ni][1]);
            *(__half2*)(C + (size_t)(row0 + 8) * Nn + col) =
                __floats2half2_rn(acc[mi][ni][2], acc[mi][ni][3]);
        }
    }
#undef LOAD_CHUNK
}

// ---------------- small fp16 HMMA GEMM (glimpse): 128x128, fp32 out ----------------
__global__ __launch_bounds__(256, 2)
void hmma_gemm(const __half* __restrict__ A, const __half* __restrict__ Bt,
               float* __restrict__ C, int Nn)
{
    extern __shared__ char dsm[];
    const uint32_t sb = smem_u32(dsm);
    const int tid = threadIdx.x;
    const int bm = blockIdx.y * 128;
    const int bn = blockIdx.x * 128;
    const int lane = tid & 31, w = tid >> 5;
    const int wr = w >> 2;
    const int wc = w & 3;

    const char* Ag = (const char*)A + (size_t)bm * 1024;
    const char* Bg = (const char*)Bt + (size_t)bn * 1024;

#define LOAD_CHUNK(kc)                                                      \
    do {                                                                    \
        uint32_t st_ = sb + ((kc) & 1) * 32768;                             \
        size_t gk_ = (size_t)(kc) * 128;                                    \
        _Pragma("unroll")                                                   \
        for (int i_ = 0; i_ < 4; i_++) {                                    \
            int g_ = tid + i_ * 256;                                        \
            int row_ = g_ >> 3, ch_ = g_ & 7;                               \
            uint32_t off_ = row_ * 128 + ch_ * 16;                          \
            uint32_t sw_ = off_ ^ ((off_ >> 3) & 0x70);                     \
            size_t go_ = (size_t)row_ * 1024 + gk_ + ch_ * 16;              \
            cp_async16(st_ + sw_, Ag + go_);                                \
            cp_async16(st_ + 16384 + sw_, Bg + go_);                        \
        }                                                                   \
        cp_commit();                                                        \
    } while (0)

    float acc[4][4][4];
#pragma unroll
    for (int i = 0; i < 4; i++)
#pragma unroll
        for (int j = 0; j < 4; j++)
#pragma unroll
            for (int r = 0; r < 4; r++) acc[i][j][r] = 0.f;

    LOAD_CHUNK(0);

    const int a_row = (lane & 15);
    const int a_c16 = (lane >> 4);
    const int b_nrow = (lane & 7) + ((lane >> 4) & 1) * 8;
    const int b_c16 = (lane >> 3) & 1;

    for (int kc = 0; kc < 8; ++kc) {
        if (kc + 1 < 8) { LOAD_CHUNK(kc + 1); cp_wait1(); } else { cp_wait0(); }
        __syncthreads();

        uint32_t st = sb + (kc & 1) * 32768;
#pragma unroll
        for (int ks = 0; ks < 4; ++ks) {
            uint32_t af[4][4];
#pragma unroll
            for (int mi = 0; mi < 4; ++mi) {
                uint32_t off = (uint32_t)(wr * 64 + mi * 16 + a_row) * 128 + ks * 32 + a_c16 * 16;
                uint32_t sw = off ^ ((off >> 3) & 0x70);
                ldsm_x4(af[mi][0], af[mi][1], af[mi][2], af[mi][3], st + sw);
            }
            uint32_t bf[2][4];
#pragma unroll
            for (int pr = 0; pr < 2; ++pr) {
                uint32_t off = (uint32_t)(wc * 32 + pr * 16 + b_nrow) * 128 + ks * 32 + b_c16 * 16;
                uint32_t sw = off ^ ((off >> 3) & 0x70);
                ldsm_x4(bf[pr][0], bf[pr][1], bf[pr][2], bf[pr][3], st + 16384 + sw);
            }
#pragma unroll
            for (int mi = 0; mi < 4; ++mi) {
#pragma unroll
                for (int pr = 0; pr < 2; ++pr) {
                    mma16816(acc[mi][pr * 2][0], acc[mi][pr * 2][1],
                             acc[mi][pr * 2][2], acc[mi][pr * 2][3],
                             af[mi][0], af[mi][1], af[mi][2], af[mi][3],
                             bf[pr][0], bf[pr][1]);
                    mma16816(acc[mi][pr * 2 + 1][0], acc[mi][pr * 2 + 1][1],
                             acc[mi][pr * 2 + 1][2], acc[mi][pr * 2 + 1][3],
                             af[mi][0], af[mi][1], af[mi][2], af[mi][3],
                             bf[pr][2], bf[pr][3]);
                }
            }
        }
        __syncthreads();
    }

#pragma unroll
    for (int mi = 0; mi < 4; ++mi) {
        int row0 = bm + wr * 64 + mi * 16 + (lane >> 2);
#pragma unroll
        for (int ni = 0; ni < 4; ++ni) {
            int col = bn + wc * 32 + ni * 8 + (lane & 3) * 2;
            *(float2*)(C + (size_t)row0 * Nn + col) = make_float2(acc[mi][ni][0], acc[mi][ni][1]);
            *(float2*)(C + (size_t)(row0 + 8) * Nn + col) = make_float2(acc[mi][ni][2], acc[mi][ni][3]);
        }
    }
#undef LOAD_CHUNK
}

// ---------------- tensor-core attention, materialized softmax ----------------
#define ATT_P 0
#define ATT_KV 65536
#define ATT_Q 90112
#define ATT_MASK 94208
#define ATT_STAT 96768
#define ATT_SMEM 97024

__device__ __forceinline__ uint32_t psw(int row, int bytecol) {
    return (uint32_t)(row * 2048 + (bytecol ^ ((row & 7) << 4)));
}

__global__ __launch_bounds__(256)
void attn_mma_kernel(const float* __restrict__ qin)
{
    extern __shared__ char dsm[];
    const uint32_t sb = smem_u32(dsm);
    unsigned int* smask = (unsigned int*)(dsm + ATT_MASK);
    float* sm = (float*)(dsm + ATT_STAT);
    float* sl = (float*)(dsm + ATT_STAT + 80);

    const int h = blockIdx.x, b = blockIdx.y;
    const int tid = threadIdx.x;
    const int lane = tid & 31, w = tid >> 5;
    const int wm = w >> 2, wn = w & 3;

    const int a_row = (lane & 15);
    const int a_c16 = (lane >> 4);
    const int b_nrow = (lane & 7) + ((lane >> 4) & 1) * 8;
    const int b_c16 = (lane >> 3) & 1;

    // ---- setup: mask + Q tile ----
    if (tid < 160) {
#pragma unroll
        for (int j = 0; j < 4; j++) {
            int idx = tid * 4 + j;
            smask[idx] = g_mbits[(b * 20 + (idx >> 5)) * 32 + (idx & 31)];
        }
    }
    for (int e = tid; e < 2048; e += 256) {
        int row = e >> 6, d = e & 63;
        __half v = __float2half_rn(0.f);
        if (row < 20) v = __float2half_rn(qin[((size_t)(b * 20 + row)) * 512 + h * 64 + d]);
        uint32_t off = (uint32_t)(row * 128 + d * 2);
        *(__half*)(dsm + ATT_Q + (off ^ ((off >> 3) & 0x70))) = v;
    }

#define LOADK(t)                                                              \
    do {                                                                      \
        uint32_t st_ = sb + ATT_KV + ((t) % 3) * 8192;                        \
        int n0_ = (t) * 64;                                                   \
        _Pragma("unroll")                                                     \
        for (int i_ = 0; i_ < 2; i_++) {                                      \
            int c_ = tid + i_ * 256;                                          \
            int row_ = c_ >> 3, j_ = c_ & 7;                                  \
            uint32_t off_ = row_ * 128 + j_ * 16;                             \
            uint32_t sw_ = off_ ^ ((off_ >> 3) & 0x70);                       \
            cp_async16(st_ + sw_, g_kvlh + ((size_t)b * 1000 + n0_ + row_) * 1536 + h * 64 + j_ * 8); \
        }                                                                     \
        cp_commit();                                                          \
    } while (0)

#define LOADV(t)                                                              \
    do {                                                                      \
        uint32_t st_ = sb + ATT_KV + ((t) % 3) * 8192;                        \
        int n0_ = (t) * 64;                                                   \
        _Pragma("unroll")                                                     \
        for (int i_ = 0; i_ < 2; i_++) {                                      \
            int c_ = tid + i_ * 256;                                          \
            int row_ = c_ >> 3, j_ = c_ & 7;                                  \
            uint32_t off_ = row_ * 128 + j_ * 16;                             \
            uint32_t sw_ = off_ ^ ((off_ >> 3) & 0x70);                       \
            cp_async16(st_ + sw_, g_vT + (((size_t)b * 8 + h) * 64 + row_) * 1024 + n0_ + j_ * 8); \
        }                                                                     \
        cp_commit();                                                          \
    } while (0)

    LOADK(0);
    LOADK(1);
    __syncthreads();

    // Q a-frags (persistent)
    uint32_t af[4][4];
#pragma unroll
    for (int ks = 0; ks < 4; ++ks) {
        uint32_t off = (uint32_t)((wm * 16 + a_row) * 128 + ks * 32 + a_c16 * 16);
        ldsm_x4(af[ks][0], af[ks][1], af[ks][2], af[ks][3],
                sb + ATT_Q + (off ^ ((off >> 3) & 0x70)));
    }

    const int r0 = wm * 16 + (lane >> 2);
    const int r1 = r0 + 8;

    // ---- phase 1: S tiles -> P smem ----
    for (int t = 0; t < 16; ++t) {
        if (t >= 14) cp_wait0(); else cp_wait1();
        __syncthreads();
        if (t + 2 < 16) LOADK(t + 2);

        uint32_t st = sb + ATT_KV + (t % 3) * 8192;
        float acc[2][4] = {{0.f, 0.f, 0.f, 0.f}, {0.f, 0.f, 0.f, 0.f}};
#pragma unroll
        for (int ks = 0; ks < 4; ++ks) {
            uint32_t off = (uint32_t)((wn * 16 + b_nrow) * 128 + ks * 32 + b_c16 * 16);
            uint32_t bf0, bf1, bf2, bf3;
            ldsm_x4(bf0, bf1, bf2, bf3, st + (off ^ ((off >> 3) & 0x70)));
            mma16816(acc[0][0], acc[0][1], acc[0][2], acc[0][3],
                     af[ks][0], af[ks][1], af[ks][2], af[ks][3], bf0, bf1);
            mma16816(acc[1][0], acc[1][1], acc[1][2], acc[1][3],
                     af[ks][0], af[ks][1], af[ks][2], af[ks][3], bf2, bf3);
        }

        const int nb = t * 64 + wn * 16;
        const int widx = nb >> 5;
        unsigned int w0 = (r0 < 20) ? smask[r0 * 32 + widx] : 0u;
        unsigned int w1 = (r1 < 20) ? smask[r1 * 32 + widx] : 0u;
#pragma unroll
        for (int f = 0; f < 2; ++f) {
            int c = (lane & 3) * 2 + f * 8;
            int bit = (nb + c) & 31;
            float v00 = ((w0 >> bit) & 1u) ? acc[f][0] * INV_SQRT_DK : -65504.f;
            float v01 = ((w0 >> (bit + 1)) & 1u) ? acc[f][1] * INV_SQRT_DK : -65504.f;
            float v10 = ((w1 >> bit) & 1u) ? acc[f][2] * INV_SQRT_DK : -65504.f;
            float v11 = ((w1 >> (bit + 1)) & 1u) ? acc[f][3] * INV_SQRT_DK : -65504.f;
            if (r0 >= 20) { v00 = 0.f; v01 = 0.f; }
            if (r1 >= 20) { v10 = 0.f; v11 = 0.f; }
            int bytec = t * 128 + (wn * 16 + c) * 2;
            *(__half2*)(dsm + ATT_P + psw(r0, bytec)) = __floats2half2_rn(v00, v01);
            *(__half2*)(dsm + ATT_P + psw(r1, bytec)) = __floats2half2_rn(v10, v11);
        }
    }
    __syncthreads();

    // prefetch V tiles 0,1 (hidden under phases 2-3)
    LOADV(0);
    LOADV(1);

    // ---- phase 2: per-row max & sum ----
    for (int row = w; row < 20; row += 8) {
        float mi = -1e30f, li = 0.f;
        for (int c = lane; c < 1024; c += 32) {
            float x = __half2float(*(const __half*)(dsm + ATT_P + psw(row, c * 2)));
            if (x > mi) { li = li * __expf(mi - x) + 1.f; mi = x; }
            else li += __expf(x - mi);
        }
        float mg = warp_max(mi);
        float lg = warp_sum(li * __expf(mi - mg));
        if (lane == 0) { sm[row] = mg; sl[row] = lg; }
    }
    __syncthreads();

    // ---- phase 3: P = exp(s - m)  (proper 64-bit generic pointer) ----
    for (int i = tid; i < 20 * 1024; i += 256) {
        int row = i >> 10, c = i & 1023;
        __half* p = (__half*)(dsm + ATT_P + psw(row, c * 2));
        float x = __half2float(*p);
        *p = __float2half_rn(__expf(x - sm[row]));
    }
    __syncthreads();

    // ---- phase 4: O = P @ V ----
    float oacc[2][4] = {{0.f, 0.f, 0.f, 0.f}, {0.f, 0.f, 0.f, 0.f}};
    for (int t = 0; t < 16; ++t) {
        if (t >= 14) cp_wait0(); else cp_wait1();
        __syncthreads();
        if (t + 2 < 16) LOADV(t + 2);

        uint32_t st = sb + ATT_KV + (t % 3) * 8192;
#pragma unroll
        for (int ks = 0; ks < 4; ++ks) {
            uint32_t pa0, pa1, pa2, pa3;
            ldsm_x4(pa0, pa1, pa2, pa3,
                    sb + ATT_P + psw(wm * 16 + a_row, t * 128 + ks * 32 + a_c16 * 16));
            uint32_t off = (uint32_t)((wn * 16 + b_nrow) * 128 + ks * 32 + b_c16 * 16);
            uint32_t bf0, bf1, bf2, bf3;
            ldsm_x4(bf0, bf1, bf2, bf3, st + (off ^ ((off >> 3) & 0x70)));
            mma16816(oacc[0][0], oacc[0][1], oacc[0][2], oacc[0][3],
                     pa0, pa1, pa2, pa3, bf0, bf1);
            mma16816(oacc[1][0], oacc[1][1], oacc[1][2], oacc[1][3],
                     pa0, pa1, pa2, pa3, bf2, bf3);
        }
    }

    // ---- phase 5: writeout heads fp16 ----
#pragma unroll
    for (int f = 0; f < 2; ++f) {
        int col = h * 64 + wn * 16 + f * 8 + (lane & 3) * 2;
        if (r0 < 20) {
            float inv = 1.f / sl[r0];
            *(__half2*)(g_Hf16 + ((size_t)(b * 20 + r0)) * 512 + col) =
                __floats2half2_rn(oacc[f][0] * inv, oacc[f][1] * inv);
        }
        if (r1 < 20) {
            float inv = 1.f / sl[r1];
            *(__half2*)(g_Hf16 + ((size_t)(b * 20 + r1)) * 512 + col) =
                __floats2half2_rn(oacc[f][2] * inv, oacc[f][3] * inv);
        }
    }
#undef LOADK
#undef LOADV
}

// ---------------- pointer logits ----------------
__global__ __launch_bounds__(256)
void pointer_kernel()
{
    __shared__ __align__(16) float sg[10 * 512];
    __shared__ __align__(16) float slk[8 * 512];
    const int b = blockIdx.x;
    const int sbase = blockIdx.y * 10;
    const int nsl = blockIdx.z;
    const int tid = threadIdx.x;

    for (int i = tid; i < 10 * 512 / 4; i += 256) {
        int off = i << 2;
        int s = off >> 9, d = off & 511;
        *(float4*)&sg[off] = *(const float4*)(g_glimpse + (size_t)(b * 20 + sbase + s) * 512 + d);
    }

    const int lane = tid & 31, w = tid >> 5;
    for (int t = 0; t < 25; ++t) {
        const int n0 = nsl * 200 + t * 8;
        __syncthreads();
        for (int i = tid; i < 8 * 512 / 8; i += 256) {
            int off = i << 3;
            int nn = off >> 9, d = off & 511;
            const __half* src = g_kvlh + ((size_t)b * 1000 + n0 + nn) * 1536 + 1024 + d;
            uint4 raw = *(const uint4*)src;
            const __half2* hp = (const __half2*)&raw;
            float2 f0 = __half22float2(hp[0]);
            float2 f1 = __half22float2(hp[1]);
            float2 f2 = __half22float2(hp[2]);
            float2 f3 = __half22float2(hp[3]);
            *(float4*)&slk[off] = make_float4(f0.x, f0.y, f1.x, f1.y);
            *(float4*)&slk[off + 4] = make_float4(f2.x, f2.y, f3.x, f3.y);
        }
        __syncthreads();
#pragma unroll
        for (int pp = 0; pp < 10; ++pp) {
            const int p = w * 10 + pp;
            const int sl_ = p >> 3, n = p & 7;
            const int gn = n0 + n;
            unsigned int wd = 0;
            if (lane == 0)
                wd = g_mbits[(b * 20 + sbase + sl_) * 32 + (gn >> 5)];
            const float* gr = &sg[sl_ * 512];
            const float* kr = &slk[n * 512];
            float sum = 0.f;
#pragma unroll
            for (int i = 0; i < 16; ++i)
                sum += gr[lane + i * 32] * kr[lane + i * 32];
            sum = warp_sum(sum);
            if (lane == 0) {
                float lg = ((wd >> (gn & 31)) & 1u)
                         ? 10.f * tanhf(sum * INV_SQRT_D) : NEG_BIG;
                g_logits[(b * 20 + sbase + sl_) * 1000 + gn] = lg;
            }
        }
    }
}

// ---------------- log-softmax + transposed writeout ----------------
__global__ __launch_bounds__(256)
void lsm_kernel(float* __restrict__ out)
{
    const int s = blockIdx.x, b = blockIdx.y;
    const float* row = g_logits + (size_t)(b * 20 + s) * 1000;
    float* orow = out + (size_t)(s * 64 + b) * 1000;
    __shared__ float red[8];
    const int tid = threadIdx.x;
    const int lane = tid & 31, w = tid >> 5;

    float mx = -1e30f;
    for (int i = tid; i < 1000; i += 256) mx = fmaxf(mx, row[i]);
    mx = warp_max(mx);
    if (lane == 0) red[w] = mx;
    __syncthreads();
    if (w == 0) {
        float v = (lane < 8) ? red[lane] : -1e30f;
        v = warp_max(v);
        if (lane == 0) red[0] = v;
    }
    __syncthreads();
    mx = red[0];
    __syncthreads();

    float se = 0.f;
    for (int i = tid; i < 1000; i += 256) se += __expf(row[i] - mx);
    se = warp_sum(se);
    if (lane == 0) red[w] = se;
    __syncthreads();
    if (w == 0) {
        float v = (lane < 8) ? red[lane] : 0.f;
        v = warp_sum(v);
        if (lane == 0) red[0] = v;
    }
    __syncthreads();
    const float lse = mx + logf(red[0]);

    for (int i = tid; i < 1000; i += 256) orow[i] = row[i] - lse;
}

// ---------------- launch ----------------
extern "C" void kernel_launch(void* const* d_in, const int* in_sizes, int n_in,
                              void* d_out, int out_size)
{
    (void)out_size;
    const float* emb = nullptr;
    const float* q = nullptr;
    const void* mask = nullptr;
    const float* Wkvl = nullptr;
    const float* Wout = nullptr;
    for (int i = 0; i < n_in; ++i) {
        switch (in_sizes[i]) {
            case 32768000: emb = (const float*)d_in[i]; break;
            case 655360:   q = (const float*)d_in[i]; break;
            case 1280000:  mask = d_in[i]; break;
            case 786432:   Wkvl = (const float*)d_in[i]; break;
            case 262144:   Wout = (const float*)d_in[i]; break;
            default: break;
        }
    }
    float* out = (float*)d_out;

    float* glimpsep;
    __half *kvlhp, *af16, *wkt, *wot, *hf16;
    cudaGetSymbolAddress((void**)&kvlhp, g_kvlh);
    cudaGetSymbolAddress((void**)&glimpsep, g_glimpse);
    cudaGetSymbolAddress((void**)&af16, g_Af16);
    cudaGetSymbolAddress((void**)&wkt, g_Wkvl_t);
    cudaGetSymbolAddress((void**)&wot, g_Wout_t);
    cudaGetSymbolAddress((void**)&hf16, g_Hf16);

    cudaFuncSetAttribute(hmma_gemm_big, cudaFuncAttributeMaxDynamicSharedMemorySize, 147456);
    cudaFuncSetAttribute(hmma_gemm, cudaFuncAttributeMaxDynamicSharedMemorySize, 65536);
    cudaFuncSetAttribute(attn_mma_kernel, cudaFuncAttributeMaxDynamicSharedMemorySize, ATT_SMEM);

    mask_bits_kernel<<<1280, 256>>>((const unsigned int*)mask);         // 1
    prep_kernel<<<36096, 256>>>(emb, Wkvl, Wout);                       // 2

    // kvl = embeddings @ W_kvl -> g_kvlh                               // 3
    {
        dim3 grid(6, 500);
        hmma_gemm_big<<<grid, 256, 147456>>>(af16, wkt, kvlhp, 1536);
    }

    // V transpose                                                      // 4 (profiled)
    {
        dim3 grid(32, 8, 64);
        vtrans_kernel<<<grid, 256>>>();
    }

    // tensor-core attention -> g_Hf16                                  // 5
    {
        dim3 grid(8, 64);
        attn_mma_kernel<<<grid, 256, ATT_SMEM>>>(q);
    }

    // glimpse = heads @ W_out                                          // 6
    {
        dim3 grid(4, 10);
        hmma_gemm<<<grid, 256, 65536>>>(hf16, wot, glimpsep, 512);
    }

    // pointer logits                                                   // 7
    {
        dim3 grid(64, 2, 5);
        pointer_kernel<<<grid, 256>>>();
    }

    // log-softmax                                                      // 8
    {
        dim3 grid(20, 64);
        lsm_kernel<<<grid, 256>>>(out);
    }
}

// round 12
// speedup vs baseline: 2.4947x; 1.4882x over previous
#include <cuda_runtime.h>
#include <cuda_fp16.h>
#include <cstdint>

// B=64, N=1000, D=512, H=8, S=20, DK=64
#define NEG_BIG (-1e9f)
#define INV_SQRT_DK 0.125f
#define INV_SQRT_D 0.04419417382415922f

// ---------------- device scratch ----------------
__device__ __align__(16) __half g_kvlh[64032 * 1536];     // [row][gk|gv|lk]
__device__ __align__(16) __half g_vT[64 * 8 * 64 * 1024]; // V transposed [b][h][d][n(pad 1024)]
__device__ __align__(16) float g_logits[1280 * 1000];
__device__ __align__(16) __half g_Af16[64000 * 512];
__device__ __align__(16) __half g_Wkvl_t[1536 * 512];
__device__ __align__(16) __half g_Wout_t[512 * 512];
__device__ __align__(16) __half g_Hf16[1280 * 512];       // heads fp16 (attn out)
__device__ __align__(16) __half g_Gf16[1280 * 512];       // glimpse fp16
__device__ __align__(16) unsigned int g_mbits[1280 * 32];

// ---------------- helpers ----------------
__device__ __forceinline__ float warp_max(float v) {
#pragma unroll
    for (int o = 16; o; o >>= 1) v = fmaxf(v, __shfl_xor_sync(0xffffffffu, v, o));
    return v;
}
__device__ __forceinline__ float warp_sum(float v) {
#pragma unroll
    for (int o = 16; o; o >>= 1) v += __shfl_xor_sync(0xffffffffu, v, o);
    return v;
}
__device__ __forceinline__ uint32_t smem_u32(const void* p) {
    uint32_t a;
    asm("{ .reg .u64 t; cvta.to.shared.u64 t, %1; cvt.u32.u64 %0, t; }" : "=r"(a) : "l"(p));
    return a;
}
__device__ __forceinline__ void cp_async16(uint32_t saddr, const void* gaddr) {
    asm volatile("cp.async.cg.shared.global [%0], [%1], 16;" :: "r"(saddr), "l"(gaddr));
}
__device__ __forceinline__ void cp_commit() { asm volatile("cp.async.commit_group;" ::: "memory"); }
__device__ __forceinline__ void cp_wait1() { asm volatile("cp.async.wait_group 1;" ::: "memory"); }
__device__ __forceinline__ void cp_wait0() { asm volatile("cp.async.wait_group 0;" ::: "memory"); }

__device__ __forceinline__ void ldsm_x4(uint32_t& r0, uint32_t& r1, uint32_t& r2, uint32_t& r3,
                                        uint32_t addr) {
    asm volatile("ldmatrix.sync.aligned.m8n8.x4.shared.b16 {%0,%1,%2,%3}, [%4];"
                 : "=r"(r0), "=r"(r1), "=r"(r2), "=r"(r3) : "r"(addr));
}
__device__ __forceinline__ void mma16816(float& c0, float& c1, float& c2, float& c3,
                                         uint32_t a0, uint32_t a1, uint32_t a2, uint32_t a3,
                                         uint32_t b0, uint32_t b1) {
    asm volatile(
        "mma.sync.aligned.m16n8k16.row.col.f32.f16.f16.f32 "
        "{%0,%1,%2,%3}, {%4,%5,%6,%7}, {%8,%9}, {%0,%1,%2,%3};"
        : "+f"(c0), "+f"(c1), "+f"(c2), "+f"(c3)
        : "r"(a0), "r"(a1), "r"(a2), "r"(a3), "r"(b0), "r"(b1));
}

// ---------------- fused prep: emb->fp16, W transposes, mask bits ----------------
// grid 37376: [0,32000) emb; [32000,35072) Wkvl^T; [35072,36096) Wout^T; [36096,37376) mask rows
__global__ __launch_bounds__(256)
void prep_kernel(const float* __restrict__ emb, const float* __restrict__ Wkvl,
                 const float* __restrict__ Wout, const unsigned int* __restrict__ mw)
{
    int bid = blockIdx.x;
    int tid = threadIdx.x;
    if (bid < 32000) {
        int i = bid * 256 + tid;
        float4 v = ((const float4*)emb)[i];
        ((__half2*)g_Af16)[i * 2] = __floats2half2_rn(v.x, v.y);
        ((__half2*)g_Af16)[i * 2 + 1] = __floats2half2_rn(v.z, v.w);
    } else if (bid < 35072) {
        int idx = (bid - 32000) * 256 + tid;
        int n = idx >> 9, k = idx & 511;
        g_Wkvl_t[idx] = __float2half_rn(Wkvl[(size_t)k * 1536 + n]);
    } else if (bid < 36096) {
        int idx = (bid - 35072) * 256 + tid;
        int n = idx >> 9, k = idx & 511;
        g_Wout_t[idx] = __float2half_rn(Wout[(size_t)k * 512 + n]);
    } else {
        __shared__ int flags;
        if (tid == 0) flags = 0;
        __syncthreads();
        int f = 0;
        for (int i = tid; i < 1024; i += 256) {
            unsigned int v = mw[i];
            if (v != 0u && v != 1u) f |= 1;
            if (v != 0u && v != 0x3F800000u) f |= 2;
        }
        if (f) atomicOr(&flags, f);
        __syncthreads();
        const int mode = ((flags & 1) && (flags & 2)) ? 0 : 1;
        const int lane = tid & 31, wid = tid >> 5;
        const int row = bid - 36096;
#pragma unroll
        for (int j = 0; j < 4; j++) {
            int widx = wid * 4 + j;
            int n = widx * 32 + lane;
            bool feas = false;
            if (n < 1000) {
                int idx = row * 1000 + n;
                feas = mode ? (mw[idx] != 0u)
                            : (((const unsigned char*)mw)[idx] != 0);
            }
            unsigned int word = __ballot_sync(0xffffffffu, feas);
            if (lane == 0) g_mbits[row * 32 + widx] = word;
        }
    }
}

// ---------------- V transpose ----------------
__global__ __launch_bounds__(256)
void vtrans_kernel()
{
    const int nt = blockIdx.x, h = blockIdx.y, b = blockIdx.z;
    const int lane = threadIdx.x & 31, w = threadIdx.x >> 5;
    const int n = nt * 32 + lane;

    uint4 v = make_uint4(0u, 0u, 0u, 0u);
    if (n < 1000)
        v = *(const uint4*)(g_kvlh + ((size_t)b * 1000 + n) * 1536 + 512 + h * 64 + w * 8);
    const __half* hv = (const __half*)&v;

    __half* outb = g_vT + (((size_t)b * 8 + h) * 64 + w * 8) * 1024 + nt * 32 + lane;
#pragma unroll
    for (int k = 0; k < 8; ++k)
        outb[(size_t)k * 1024] = hv[k];
}

// ---------------- BIG fp16 HMMA GEMM: 128x256 tile, fp16 out ----------------
__global__ __launch_bounds__(256)
void hmma_gemm_big(const __half* __restrict__ A, const __half* __restrict__ Bt,
                   __half* __restrict__ C, int Nn)
{
    extern __shared__ char dsm[];
    const uint32_t sb = smem_u32(dsm);
    const int tid = threadIdx.x;
    const int bm = blockIdx.y * 128;
    const int bn = blockIdx.x * 256;
    const int lane = tid & 31, w = tid >> 5;
    const int wr = w >> 2;
    const int wc = w & 3;

    const char* Ag = (const char*)A + (size_t)bm * 1024;
    const char* Bg = (const char*)Bt + (size_t)bn * 1024;

#define LOAD_CHUNK(kc)                                                      \
    do {                                                                    \
        uint32_t st_ = sb + ((kc) % 3) * 49152;                             \
        size_t gk_ = (size_t)(kc) * 128;                                    \
        _Pragma("unroll")                                                   \
        for (int i_ = 0; i_ < 4; i_++) {                                    \
            int g_ = tid + i_ * 256;                                        \
            int row_ = g_ >> 3, ch_ = g_ & 7;                               \
            uint32_t off_ = row_ * 128 + ch_ * 16;                          \
            uint32_t sw_ = off_ ^ ((off_ >> 3) & 0x70);                     \
            cp_async16(st_ + sw_, Ag + (size_t)row_ * 1024 + gk_ + ch_ * 16); \
        }                                                                   \
        _Pragma("unroll")                                                   \
        for (int i_ = 0; i_ < 8; i_++) {                                    \
            int g_ = tid + i_ * 256;                                        \
            int row_ = g_ >> 3, ch_ = g_ & 7;                               \
            uint32_t off_ = row_ * 128 + ch_ * 16;                          \
            uint32_t sw_ = off_ ^ ((off_ >> 3) & 0x70);                     \
            cp_async16(st_ + 16384 + sw_, Bg + (size_t)row_ * 1024 + gk_ + ch_ * 16); \
        }                                                                   \
        cp_commit();                                                        \
    } while (0)

    float acc[4][8][4];
#pragma unroll
    for (int i = 0; i < 4; i++)
#pragma unroll
        for (int j = 0; j < 8; j++)
#pragma unroll
            for (int r = 0; r < 4; r++) acc[i][j][r] = 0.f;

    LOAD_CHUNK(0);
    LOAD_CHUNK(1);

    const int a_row = (lane & 15);
    const int a_c16 = (lane >> 4);
    const int b_nrow = (lane & 7) + ((lane >> 4) & 1) * 8;
    const int b_c16 = (lane >> 3) & 1;

    for (int kc = 0; kc < 8; ++kc) {
        if (kc == 7) cp_wait0(); else cp_wait1();
        __syncthreads();
        if (kc + 2 < 8) LOAD_CHUNK(kc + 2);

        uint32_t st = sb + (kc % 3) * 49152;
#pragma unroll
        for (int ks = 0; ks < 4; ++ks) {
            uint32_t af[4][4];
#pragma unroll
            for (int mi = 0; mi < 4; ++mi) {
                uint32_t off = (uint32_t)(wr * 64 + mi * 16 + a_row) * 128 + ks * 32 + a_c16 * 16;
                uint32_t sw = off ^ ((off >> 3) & 0x70);
                ldsm_x4(af[mi][0], af[mi][1], af[mi][2], af[mi][3], st + sw);
            }
            uint32_t bf[4][4];
#pragma unroll
            for (int pr = 0; pr < 4; ++pr) {
                uint32_t off = (uint32_t)(wc * 64 + pr * 16 + b_nrow) * 128 + ks * 32 + b_c16 * 16;
                uint32_t sw = off ^ ((off >> 3) & 0x70);
                ldsm_x4(bf[pr][0], bf[pr][1], bf[pr][2], bf[pr][3], st + 16384 + sw);
            }
#pragma unroll
            for (int mi = 0; mi < 4; ++mi) {
#pragma unroll
                for (int pr = 0; pr < 4; ++pr) {
                    mma16816(acc[mi][pr * 2][0], acc[mi][pr * 2][1],
                             acc[mi][pr * 2][2], acc[mi][pr * 2][3],
                             af[mi][0], af[mi][1], af[mi][2], af[mi][3],
                             bf[pr][0], bf[pr][1]);
                    mma16816(acc[mi][pr * 2 + 1][0], acc[mi][pr * 2 + 1][1],
                             acc[mi][pr * 2 + 1][2], acc[mi][pr * 2 + 1][3],
                             af[mi][0], af[mi][1], af[mi][2], af[mi][3],
                             bf[pr][2], bf[pr][3]);
                }
            }
        }
    }
    __syncthreads();

#pragma unroll
    for (int mi = 0; mi < 4; ++mi) {
        int row0 = bm + wr * 64 + mi * 16 + (lane >> 2);
#pragma unroll
        for (int ni = 0; ni < 8; ++ni) {
            int col = bn + wc * 64 + ni * 8 + (lane & 3) * 2;
            *(__half2*)(C + (size_t)row0 * Nn + col) =
                __floats2half2_rn(acc[mi][ni][0], acc[mi][ni][1]);
            *(__half2*)(C + (size_t)(row0 + 8) * Nn + col) =
                __floats2half2_rn(acc[mi][ni][2], acc[mi][ni][3]);
        }
    }
#undef LOAD_CHUNK
}

// ---------------- tensor-core attention, exp-inline softmax (no max pass) ----------------
#define ATT_P 0
#define ATT_KV 65536
#define ATT_Q 90112
#define ATT_MASK 94208
#define ATT_STAT 96768
#define ATT_SMEM 97024

__device__ __forceinline__ uint32_t psw(int row, int bytecol) {
    return (uint32_t)(row * 2048 + (bytecol ^ ((row & 7) << 4)));
}

__global__ __launch_bounds__(256)
void attn_mma_kernel(const float* __restrict__ qin)
{
    extern __shared__ char dsm[];
    const uint32_t sb = smem_u32(dsm);
    unsigned int* smask = (unsigned int*)(dsm + ATT_MASK);
    float* sl = (float*)(dsm + ATT_STAT);

    const int h = blockIdx.x, b = blockIdx.y;
    const int tid = threadIdx.x;
    const int lane = tid & 31, w = tid >> 5;
    const int wm = w >> 2, wn = w & 3;

    const int a_row = (lane & 15);
    const int a_c16 = (lane >> 4);
    const int b_nrow = (lane & 7) + ((lane >> 4) & 1) * 8;
    const int b_c16 = (lane >> 3) & 1;

    // ---- setup ----
    if (tid < 20) sl[tid] = 0.f;
    if (tid < 160) {
#pragma unroll
        for (int j = 0; j < 4; j++) {
            int idx = tid * 4 + j;
            smask[idx] = g_mbits[(b * 20 + (idx >> 5)) * 32 + (idx & 31)];
        }
    }
    for (int e = tid; e < 2048; e += 256) {
        int row = e >> 6, d = e & 63;
        __half v = __float2half_rn(0.f);
        if (row < 20) v = __float2half_rn(qin[((size_t)(b * 20 + row)) * 512 + h * 64 + d]);
        uint32_t off = (uint32_t)(row * 128 + d * 2);
        *(__half*)(dsm + ATT_Q + (off ^ ((off >> 3) & 0x70))) = v;
    }

#define LOADK(t)                                                              \
    do {                                                                      \
        uint32_t st_ = sb + ATT_KV + ((t) % 3) * 8192;                        \
        int n0_ = (t) * 64;                                                   \
        _Pragma("unroll")                                                     \
        for (int i_ = 0; i_ < 2; i_++) {                                      \
            int c_ = tid + i_ * 256;                                          \
            int row_ = c_ >> 3, j_ = c_ & 7;                                  \
            uint32_t off_ = row_ * 128 + j_ * 16;                             \
            uint32_t sw_ = off_ ^ ((off_ >> 3) & 0x70);                       \
            cp_async16(st_ + sw_, g_kvlh + ((size_t)b * 1000 + n0_ + row_) * 1536 + h * 64 + j_ * 8); \
        }                                                                     \
        cp_commit();                                                          \
    } while (0)

#define LOADV(t)                                                              \
    do {                                                                      \
        uint32_t st_ = sb + ATT_KV + ((t) % 3) * 8192;                        \
        int n0_ = (t) * 64;                                                   \
        _Pragma("unroll")                                                     \
        for (int i_ = 0; i_ < 2; i_++) {                                      \
            int c_ = tid + i_ * 256;                                          \
            int row_ = c_ >> 3, j_ = c_ & 7;                                  \
            uint32_t off_ = row_ * 128 + j_ * 16;                             \
            uint32_t sw_ = off_ ^ ((off_ >> 3) & 0x70);                       \
            cp_async16(st_ + sw_, g_vT + (((size_t)b * 8 + h) * 64 + row_) * 1024 + n0_ + j_ * 8); \
        }                                                                     \
        cp_commit();                                                          \
    } while (0)

    LOADK(0);
    LOADK(1);
    __syncthreads();

    uint32_t af[4][4];
#pragma unroll
    for (int ks = 0; ks < 4; ++ks) {
        uint32_t off = (uint32_t)((wm * 16 + a_row) * 128 + ks * 32 + a_c16 * 16);
        ldsm_x4(af[ks][0], af[ks][1], af[ks][2], af[ks][3],
                sb + ATT_Q + (off ^ ((off >> 3) & 0x70)));
    }

    const int r0 = wm * 16 + (lane >> 2);
    const int r1 = r0 + 8;
    float rsum0 = 0.f, rsum1 = 0.f;

    // ---- phase 1: P = exp(masked S) directly; accumulate row sums ----
    for (int t = 0; t < 16; ++t) {
        if (t >= 14) cp_wait0(); else cp_wait1();
        __syncthreads();
        if (t + 2 < 16) LOADK(t + 2);

        uint32_t st = sb + ATT_KV + (t % 3) * 8192;
        float acc[2][4] = {{0.f, 0.f, 0.f, 0.f}, {0.f, 0.f, 0.f, 0.f}};
#pragma unroll
        for (int ks = 0; ks < 4; ++ks) {
            uint32_t off = (uint32_t)((wn * 16 + b_nrow) * 128 + ks * 32 + b_c16 * 16);
            uint32_t bf0, bf1, bf2, bf3;
            ldsm_x4(bf0, bf1, bf2, bf3, st + (off ^ ((off >> 3) & 0x70)));
            mma16816(acc[0][0], acc[0][1], acc[0][2], acc[0][3],
                     af[ks][0], af[ks][1], af[ks][2], af[ks][3], bf0, bf1);
            mma16816(acc[1][0], acc[1][1], acc[1][2], acc[1][3],
                     af[ks][0], af[ks][1], af[ks][2], af[ks][3], bf2, bf3);
        }

        const int nb = t * 64 + wn * 16;
        const int widx = nb >> 5;
        unsigned int w0 = (r0 < 20) ? smask[r0 * 32 + widx] : 0u;
        unsigned int w1 = (r1 < 20) ? smask[r1 * 32 + widx] : 0u;
#pragma unroll
        for (int f = 0; f < 2; ++f) {
            int c = (lane & 3) * 2 + f * 8;
            int bit = (nb + c) & 31;
            float p00 = ((w0 >> bit) & 1u) ? fminf(__expf(acc[f][0] * INV_SQRT_DK), 60000.f) : 0.f;
            float p01 = ((w0 >> (bit + 1)) & 1u) ? fminf(__expf(acc[f][1] * INV_SQRT_DK), 60000.f) : 0.f;
            float p10 = ((w1 >> bit) & 1u) ? fminf(__expf(acc[f][2] * INV_SQRT_DK), 60000.f) : 0.f;
            float p11 = ((w1 >> (bit + 1)) & 1u) ? fminf(__expf(acc[f][3] * INV_SQRT_DK), 60000.f) : 0.f;
            rsum0 += p00 + p01;
            rsum1 += p10 + p11;
            int bytec = t * 128 + (wn * 16 + c) * 2;
            *(__half2*)(dsm + ATT_P + psw(r0, bytec)) = __floats2half2_rn(p00, p01);
            *(__half2*)(dsm + ATT_P + psw(r1, bytec)) = __floats2half2_rn(p10, p11);
        }
    }
    __syncthreads();   // all P-stores done; KV buffers free

    // prefetch V tiles (overlaps reduction)
    LOADV(0);
    LOADV(1);

    // row-sum reduction: over lane&3, then atomics across warps
    rsum0 += __shfl_xor_sync(0xffffffffu, rsum0, 1);
    rsum0 += __shfl_xor_sync(0xffffffffu, rsum0, 2);
    rsum1 += __shfl_xor_sync(0xffffffffu, rsum1, 1);
    rsum1 += __shfl_xor_sync(0xffffffffu, rsum1, 2);
    if ((lane & 3) == 0) {
        if (r0 < 20) atomicAdd(&sl[r0], rsum0);
        if (r1 < 20) atomicAdd(&sl[r1], rsum1);
    }
    __syncthreads();

    // ---- phase 4: O = P @ V ----
    float oacc[2][4] = {{0.f, 0.f, 0.f, 0.f}, {0.f, 0.f, 0.f, 0.f}};
    for (int t = 0; t < 16; ++t) {
        if (t >= 14) cp_wait0(); else cp_wait1();
        __syncthreads();
        if (t + 2 < 16) LOADV(t + 2);

        uint32_t st = sb + ATT_KV + (t % 3) * 8192;
#pragma unroll
        for (int ks = 0; ks < 4; ++ks) {
            uint32_t pa0, pa1, pa2, pa3;
            ldsm_x4(pa0, pa1, pa2, pa3,
                    sb + ATT_P + psw(wm * 16 + a_row, t * 128 + ks * 32 + a_c16 * 16));
            uint32_t off = (uint32_t)((wn * 16 + b_nrow) * 128 + ks * 32 + b_c16 * 16);
            uint32_t bf0, bf1, bf2, bf3;
            ldsm_x4(bf0, bf1, bf2, bf3, st + (off ^ ((off >> 3) & 0x70)));
            mma16816(oacc[0][0], oacc[0][1], oacc[0][2], oacc[0][3],
                     pa0, pa1, pa2, pa3, bf0, bf1);
            mma16816(oacc[1][0], oacc[1][1], oacc[1][2], oacc[1][3],
                     pa0, pa1, pa2, pa3, bf2, bf3);
        }
    }

    // ---- writeout heads fp16 ----
#pragma unroll
    for (int f = 0; f < 2; ++f) {
        int col = h * 64 + wn * 16 + f * 8 + (lane & 3) * 2;
        if (r0 < 20) {
            float inv = 1.f / sl[r0];
            *(__half2*)(g_Hf16 + ((size_t)(b * 20 + r0)) * 512 + col) =
                __floats2half2_rn(oacc[f][0] * inv, oacc[f][1] * inv);
        }
        if (r1 < 20) {
            float inv = 1.f / sl[r1];
            *(__half2*)(g_Hf16 + ((size_t)(b * 20 + r1)) * 512 + col) =
                __floats2half2_rn(oacc[f][2] * inv, oacc[f][3] * inv);
        }
    }
#undef LOADK
#undef LOADV
}

// ---------------- pointer logits via MMA ----------------
// grid (2 n-halves, 64 b), 256 threads = 8 warps (wm 2 x wn 4).
// smem: A (glimpse) 8 chunks x 4096 @0; B 2 stages x 8192 @32768; mask @49152.
#define PTR_A 0
#define PTR_B 32768
#define PTR_MASK 49152
#define PTR_SMEM 51712

__global__ __launch_bounds__(256)
void pointer_mma_kernel()
{
    extern __shared__ char dsm[];
    const uint32_t sb = smem_u32(dsm);
    unsigned int* smask = (unsigned int*)(dsm + PTR_MASK);

    const int nsl = blockIdx.x, b = blockIdx.y;
    const int tid = threadIdx.x;
    const int lane = tid & 31, w = tid >> 5;
    const int wm = w >> 2, wn = w & 3;

    const int a_row = (lane & 15);
    const int a_c16 = (lane >> 4);
    const int b_nrow = (lane & 7) + ((lane >> 4) & 1) * 8;
    const int b_c16 = (lane >> 3) & 1;

    // zero A region, load mask
    for (int i = tid; i < 32768 / 16; i += 256)
        *(uint4*)(dsm + PTR_A + i * 16) = make_uint4(0u, 0u, 0u, 0u);
    if (tid < 160) {
#pragma unroll
        for (int j = 0; j < 4; j++) {
            int idx = tid * 4 + j;
            smask[idx] = g_mbits[(b * 20 + (idx >> 5)) * 32 + (idx & 31)];
        }
    }
    __syncthreads();

    // load A: glimpse fp16 [20 x 512] -> 8 chunks of 32x128B (rows >=20 stay 0)
    for (int c = tid; c < 20 * 64; c += 256) {
        int row = c >> 6, j = c & 63;      // j = 8-half group within 512
        int kc = j >> 3, jj = j & 7;
        uint32_t off = (uint32_t)(row * 128 + jj * 16);
        uint32_t sw = off ^ ((off >> 3) & 0x70);
        *(uint4*)(dsm + PTR_A + kc * 4096 + sw) =
            *(const uint4*)(g_Gf16 + ((size_t)(b * 20 + row)) * 512 + kc * 64 + jj * 8);
    }

#define PLOADB(step)                                                          \
    do {                                                                      \
        int nt_ = (step) >> 3, kc_ = (step) & 7;                              \
        uint32_t st_ = sb + PTR_B + ((step) & 1) * 8192;                      \
        _Pragma("unroll")                                                     \
        for (int i_ = 0; i_ < 2; i_++) {                                      \
            int c_ = tid + i_ * 256;                                          \
            int row_ = c_ >> 3, j_ = c_ & 7;                                  \
            uint32_t off_ = row_ * 128 + j_ * 16;                             \
            uint32_t sw_ = off_ ^ ((off_ >> 3) & 0x70);                       \
            cp_async16(st_ + sw_,                                             \
                g_kvlh + ((size_t)b * 1000 + nsl * 512 + nt_ * 64 + row_) * 1536 + 1024 + kc_ * 64 + j_ * 8); \
        }                                                                     \
        cp_commit();                                                          \
    } while (0)

    PLOADB(0);
    __syncthreads();   // A stores visible

    const int r0 = wm * 16 + (lane >> 2);
    const int r1 = r0 + 8;

    float acc[2][4];
    for (int step = 0; step < 64; ++step) {
        if (step + 1 < 64) { PLOADB(step + 1); cp_wait1(); } else { cp_wait0(); }
        __syncthreads();

        const int kc = step & 7;
        if (kc == 0) {
#pragma unroll
            for (int f = 0; f < 2; ++f)
#pragma unroll
                for (int r = 0; r < 4; ++r) acc[f][r] = 0.f;
        }

        uint32_t stB = sb + PTR_B + (step & 1) * 8192;
#pragma unroll
        for (int ks = 0; ks < 4; ++ks) {
            uint32_t a0, a1, a2, a3;
            uint32_t offA = (uint32_t)((wm * 16 + a_row) * 128 + ks * 32 + a_c16 * 16);
            ldsm_x4(a0, a1, a2, a3, sb + PTR_A + kc * 4096 + (offA ^ ((offA >> 3) & 0x70)));
            uint32_t offB = (uint32_t)((wn * 16 + b_nrow) * 128 + ks * 32 + b_c16 * 16);
            uint32_t bf0, bf1, bf2, bf3;
            ldsm_x4(bf0, bf1, bf2, bf3, stB + (offB ^ ((offB >> 3) & 0x70)));
            mma16816(acc[0][0], acc[0][1], acc[0][2], acc[0][3], a0, a1, a2, a3, bf0, bf1);
            mma16816(acc[1][0], acc[1][1], acc[1][2], acc[1][3], a0, a1, a2, a3, bf2, bf3);
        }

        if (kc == 7) {
            const int nt = step >> 3;
            const int nb = nsl * 512 + nt * 64 + wn * 16;
            const int widx = nb >> 5;
            unsigned int w0 = (r0 < 20) ? smask[r0 * 32 + widx] : 0u;
            unsigned int w1 = (r1 < 20) ? smask[r1 * 32 + widx] : 0u;
#pragma unroll
            for (int f = 0; f < 2; ++f) {
                int c = (lane & 3) * 2 + f * 8;
                int gn = nb + c;
                int bit = gn & 31;
                if (r0 < 20) {
                    if (gn < 1000) {
                        float lg = ((w0 >> bit) & 1u)
                                 ? 10.f * tanhf(acc[f][0] * INV_SQRT_D) : NEG_BIG;
                        g_logits[(size_t)(b * 20 + r0) * 1000 + gn] = lg;
                    }
                    if (gn + 1 < 1000) {
                        float lg = ((w0 >> (bit + 1)) & 1u)
                                 ? 10.f * tanhf(acc[f][1] * INV_SQRT_D) : NEG_BIG;
                        g_logits[(size_t)(b * 20 + r0) * 1000 + gn + 1] = lg;
                    }
                }
                if (r1 < 20) {
                    if (gn < 1000) {
                        float lg = ((w1 >> bit) & 1u)
                                 ? 10.f * tanhf(acc[f][2] * INV_SQRT_D) : NEG_BIG;
                        g_logits[(size_t)(b * 20 + r1) * 1000 + gn] = lg;
                    }
                    if (gn + 1 < 1000) {
                        float lg = ((w1 >> (bit + 1)) & 1u)
                                 ? 10.f * tanhf(acc[f][3] * INV_SQRT_D) : NEG_BIG;
                        g_logits[(size_t)(b * 20 + r1) * 1000 + gn + 1] = lg;
                    }
                }
            }
        }
        __syncthreads();
    }
#undef PLOADB
}

// ---------------- log-softmax + transposed writeout ----------------
__global__ __launch_bounds__(256)
void lsm_kernel(float* __restrict__ out)
{
    const int s = blockIdx.x, b = blockIdx.y;
    const float* row = g_logits + (size_t)(b * 20 + s) * 1000;
    float* orow = out + (size_t)(s * 64 + b) * 1000;
    __shared__ float red[8];
    const int tid = threadIdx.x;
    const int lane = tid & 31, w = tid >> 5;

    float mx = -1e30f;
    for (int i = tid; i < 1000; i += 256) mx = fmaxf(mx, row[i]);
    mx = warp_max(mx);
    if (lane == 0) red[w] = mx;
    __syncthreads();
    if (w == 0) {
        float v = (lane < 8) ? red[lane] : -1e30f;
        v = warp_max(v);
        if (lane == 0) red[0] = v;
    }
    __syncthreads();
    mx = red[0];
    __syncthreads();

    float se = 0.f;
    for (int i = tid; i < 1000; i += 256) se += __expf(row[i] - mx);
    se = warp_sum(se);
    if (lane == 0) red[w] = se;
    __syncthreads();
    if (w == 0) {
        float v = (lane < 8) ? red[lane] : 0.f;
        v = warp_sum(v);
        if (lane == 0) red[0] = v;
    }
    __syncthreads();
    const float lse = mx + logf(red[0]);

    for (int i = tid; i < 1000; i += 256) orow[i] = row[i] - lse;
}

// ---------------- launch ----------------
extern "C" void kernel_launch(void* const* d_in, const int* in_sizes, int n_in,
                              void* d_out, int out_size)
{
    (void)out_size;
    const float* emb = nullptr;
    const float* q = nullptr;
    const void* mask = nullptr;
    const float* Wkvl = nullptr;
    const float* Wout = nullptr;
    for (int i = 0; i < n_in; ++i) {
        switch (in_sizes[i]) {
            case 32768000: emb = (const float*)d_in[i]; break;
            case 655360:   q = (const float*)d_in[i]; break;
            case 1280000:  mask = d_in[i]; break;
            case 786432:   Wkvl = (const float*)d_in[i]; break;
            case 262144:   Wout = (const float*)d_in[i]; break;
            default: break;
        }
    }
    float* out = (float*)d_out;

    __half *kvlhp, *af16, *wkt, *wot, *hf16, *gf16;
    cudaGetSymbolAddress((void**)&kvlhp, g_kvlh);
    cudaGetSymbolAddress((void**)&af16, g_Af16);
    cudaGetSymbolAddress((void**)&wkt, g_Wkvl_t);
    cudaGetSymbolAddress((void**)&wot, g_Wout_t);
    cudaGetSymbolAddress((void**)&hf16, g_Hf16);
    cudaGetSymbolAddress((void**)&gf16, g_Gf16);

    cudaFuncSetAttribute(hmma_gemm_big, cudaFuncAttributeMaxDynamicSharedMemorySize, 147456);
    cudaFuncSetAttribute(attn_mma_kernel, cudaFuncAttributeMaxDynamicSharedMemorySize, ATT_SMEM);
    cudaFuncSetAttribute(pointer_mma_kernel, cudaFuncAttributeMaxDynamicSharedMemorySize, PTR_SMEM);

    // 1: fused prep (emb fp16, W transposes, mask bits)
    prep_kernel<<<37376, 256>>>(emb, Wkvl, Wout, (const unsigned int*)mask);

    // 2: kvl = embeddings @ W_kvl -> g_kvlh
    {
        dim3 grid(6, 500);
        hmma_gemm_big<<<grid, 256, 147456>>>(af16, wkt, kvlhp, 1536);
    }

    // 3: V transpose
    {
        dim3 grid(32, 8, 64);
        vtrans_kernel<<<grid, 256>>>();
    }

    // 4: tensor-core attention (profiled slot)
    {
        dim3 grid(8, 64);
        attn_mma_kernel<<<grid, 256, ATT_SMEM>>>(q);
    }

    // 5: glimpse = heads @ W_out -> fp16
    {
        dim3 grid(2, 10);
        hmma_gemm_big<<<grid, 256, 147456>>>(hf16, wot, gf16, 512);
    }

    // 6: pointer logits via MMA
    {
        dim3 grid(2, 64);
        pointer_mma_kernel<<<grid, 256, PTR_SMEM>>>();
    }

    // 7: log-softmax
    {
        dim3 grid(20, 64);
        lsm_kernel<<<grid, 256>>>(out);
    }
}

// round 13
// speedup vs baseline: 2.5810x; 1.0346x over previous
#include <cuda_runtime.h>
#include <cuda_fp16.h>
#include <cstdint>

// B=64, N=1000, D=512, H=8, S=20, DK=64
#define NEG_BIG (-1e9f)
#define INV_SQRT_DK 0.125f
#define INV_SQRT_D 0.04419417382415922f

// ---------------- device scratch ----------------
__device__ __align__(16) __half g_kvlh[64032 * 1536];     // [row][gk|gv|lk]
__device__ __align__(16) __half g_vT[64 * 8 * 64 * 1024]; // V transposed [b][h][d][n(pad 1024)]
__device__ __align__(16) float g_logits[1280 * 1000];
__device__ __align__(16) __half g_Af16[64000 * 512];
__device__ __align__(16) __half g_Wkvl_t[1536 * 512];
__device__ __align__(16) __half g_Wout_t[512 * 512];
__device__ __align__(16) __half g_Hf16[1280 * 512];
__device__ __align__(16) __half g_Gf16[1280 * 512];
__device__ __align__(16) unsigned int g_mbits[1280 * 32];

// ---------------- helpers ----------------
__device__ __forceinline__ float warp_max(float v) {
#pragma unroll
    for (int o = 16; o; o >>= 1) v = fmaxf(v, __shfl_xor_sync(0xffffffffu, v, o));
    return v;
}
__device__ __forceinline__ float warp_sum(float v) {
#pragma unroll
    for (int o = 16; o; o >>= 1) v += __shfl_xor_sync(0xffffffffu, v, o);
    return v;
}
__device__ __forceinline__ uint32_t smem_u32(const void* p) {
    uint32_t a;
    asm("{ .reg .u64 t; cvta.to.shared.u64 t, %1; cvt.u32.u64 %0, t; }" : "=r"(a) : "l"(p));
    return a;
}
__device__ __forceinline__ void cp_async16(uint32_t saddr, const void* gaddr) {
    asm volatile("cp.async.cg.shared.global [%0], [%1], 16;" :: "r"(saddr), "l"(gaddr));
}
__device__ __forceinline__ void cp_commit() { asm volatile("cp.async.commit_group;" ::: "memory"); }
__device__ __forceinline__ void cp_wait1() { asm volatile("cp.async.wait_group 1;" ::: "memory"); }
__device__ __forceinline__ void cp_wait0() { asm volatile("cp.async.wait_group 0;" ::: "memory"); }

__device__ __forceinline__ void ldsm_x4(uint32_t& r0, uint32_t& r1, uint32_t& r2, uint32_t& r3,
                                        uint32_t addr) {
    asm volatile("ldmatrix.sync.aligned.m8n8.x4.shared.b16 {%0,%1,%2,%3}, [%4];"
                 : "=r"(r0), "=r"(r1), "=r"(r2), "=r"(r3) : "r"(addr));
}
__device__ __forceinline__ void mma16816(float& c0, float& c1, float& c2, float& c3,
                                         uint32_t a0, uint32_t a1, uint32_t a2, uint32_t a3,
                                         uint32_t b0, uint32_t b1) {
    asm volatile(
        "mma.sync.aligned.m16n8k16.row.col.f32.f16.f16.f32 "
        "{%0,%1,%2,%3}, {%4,%5,%6,%7}, {%8,%9}, {%0,%1,%2,%3};"
        : "+f"(c0), "+f"(c1), "+f"(c2), "+f"(c3)
        : "r"(a0), "r"(a1), "r"(a2), "r"(a3), "r"(b0), "r"(b1));
}

// ---------------- fused prep: emb->fp16, W transposes, mask bits ----------------
__global__ __launch_bounds__(256)
void prep_kernel(const float* __restrict__ emb, const float* __restrict__ Wkvl,
                 const float* __restrict__ Wout, const unsigned int* __restrict__ mw)
{
    int bid = blockIdx.x;
    int tid = threadIdx.x;
    if (bid < 32000) {
        int i = bid * 256 + tid;
        float4 v = ((const float4*)emb)[i];
        ((__half2*)g_Af16)[i * 2] = __floats2half2_rn(v.x, v.y);
        ((__half2*)g_Af16)[i * 2 + 1] = __floats2half2_rn(v.z, v.w);
    } else if (bid < 35072) {
        int idx = (bid - 32000) * 256 + tid;
        int n = idx >> 9, k = idx & 511;
        g_Wkvl_t[idx] = __float2half_rn(Wkvl[(size_t)k * 1536 + n]);
    } else if (bid < 36096) {
        int idx = (bid - 35072) * 256 + tid;
        int n = idx >> 9, k = idx & 511;
        g_Wout_t[idx] = __float2half_rn(Wout[(size_t)k * 512 + n]);
    } else {
        __shared__ int flags;
        if (tid == 0) flags = 0;
        __syncthreads();
        int f = 0;
        for (int i = tid; i < 1024; i += 256) {
            unsigned int v = mw[i];
            if (v != 0u && v != 1u) f |= 1;
            if (v != 0u && v != 0x3F800000u) f |= 2;
        }
        if (f) atomicOr(&flags, f);
        __syncthreads();
        const int mode = ((flags & 1) && (flags & 2)) ? 0 : 1;
        const int lane = tid & 31, wid = tid >> 5;
        const int row = bid - 36096;
#pragma unroll
        for (int j = 0; j < 4; j++) {
            int widx = wid * 4 + j;
            int n = widx * 32 + lane;
            bool feas = false;
            if (n < 1000) {
                int idx = row * 1000 + n;
                feas = mode ? (mw[idx] != 0u)
                            : (((const unsigned char*)mw)[idx] != 0);
            }
            unsigned int word = __ballot_sync(0xffffffffu, feas);
            if (lane == 0) g_mbits[row * 32 + widx] = word;
        }
    }
}

// ---------------- V transpose ----------------
__global__ __launch_bounds__(256)
void vtrans_kernel()
{
    const int nt = blockIdx.x, h = blockIdx.y, b = blockIdx.z;
    const int lane = threadIdx.x & 31, w = threadIdx.x >> 5;
    const int n = nt * 32 + lane;

    uint4 v = make_uint4(0u, 0u, 0u, 0u);
    if (n < 1000)
        v = *(const uint4*)(g_kvlh + ((size_t)b * 1000 + n) * 1536 + 512 + h * 64 + w * 8);
    const __half* hv = (const __half*)&v;

    __half* outb = g_vT + (((size_t)b * 8 + h) * 64 + w * 8) * 1024 + nt * 32 + lane;
#pragma unroll
    for (int k = 0; k < 8; ++k)
        outb[(size_t)k * 1024] = hv[k];
}

// ---------------- BIG fp16 HMMA GEMM: 128x256 tile, 512 threads (16 warps) ----------------
// warp grid: wm = w>>2 (0..3) -> m offset wm*32; wn = w&3 -> n offset wn*64.
// per warp: 32x64 = acc[2][8][4]. 3-stage cp.async, smem 147456, 1 CTA/SM.
__global__ __launch_bounds__(512, 1)
void hmma_gemm_big(const __half* __restrict__ A, const __half* __restrict__ Bt,
                   __half* __restrict__ C, int Nn)
{
    extern __shared__ char dsm[];
    const uint32_t sb = smem_u32(dsm);
    const int tid = threadIdx.x;
    const int bm = blockIdx.y * 128;
    const int bn = blockIdx.x * 256;
    const int lane = tid & 31, w = tid >> 5;
    const int wm = w >> 2;        // 0..3
    const int wn = w & 3;         // 0..3

    const char* Ag = (const char*)A + (size_t)bm * 1024;
    const char* Bg = (const char*)Bt + (size_t)bn * 1024;

#define LOAD_CHUNK(kc)                                                      \
    do {                                                                    \
        uint32_t st_ = sb + ((kc) % 3) * 49152;                             \
        size_t gk_ = (size_t)(kc) * 128;                                    \
        _Pragma("unroll")                                                   \
        for (int i_ = 0; i_ < 2; i_++) {                                    \
            int g_ = tid + i_ * 512;                                        \
            int row_ = g_ >> 3, ch_ = g_ & 7;                               \
            uint32_t off_ = row_ * 128 + ch_ * 16;                          \
            uint32_t sw_ = off_ ^ ((off_ >> 3) & 0x70);                     \
            cp_async16(st_ + sw_, Ag + (size_t)row_ * 1024 + gk_ + ch_ * 16); \
        }                                                                   \
        _Pragma("unroll")                                                   \
        for (int i_ = 0; i_ < 4; i_++) {                                    \
            int g_ = tid + i_ * 512;                                        \
            int row_ = g_ >> 3, ch_ = g_ & 7;                               \
            uint32_t off_ = row_ * 128 + ch_ * 16;                          \
            uint32_t sw_ = off_ ^ ((off_ >> 3) & 0x70);                     \
            cp_async16(st_ + 16384 + sw_, Bg + (size_t)row_ * 1024 + gk_ + ch_ * 16); \
        }                                                                   \
        cp_commit();                                                        \
    } while (0)

    float acc[2][8][4];
#pragma unroll
    for (int i = 0; i < 2; i++)
#pragma unroll
        for (int j = 0; j < 8; j++)
#pragma unroll
            for (int r = 0; r < 4; r++) acc[i][j][r] = 0.f;

    LOAD_CHUNK(0);
    LOAD_CHUNK(1);

    const int a_row = (lane & 15);
    const int a_c16 = (lane >> 4);
    const int b_nrow = (lane & 7) + ((lane >> 4) & 1) * 8;
    const int b_c16 = (lane >> 3) & 1;

    for (int kc = 0; kc < 8; ++kc) {
        if (kc == 7) cp_wait0(); else cp_wait1();
        __syncthreads();
        if (kc + 2 < 8) LOAD_CHUNK(kc + 2);

        uint32_t st = sb + (kc % 3) * 49152;
#pragma unroll
        for (int ks = 0; ks < 4; ++ks) {
            uint32_t af[2][4];
#pragma unroll
            for (int mi = 0; mi < 2; ++mi) {
                uint32_t off = (uint32_t)(wm * 32 + mi * 16 + a_row) * 128 + ks * 32 + a_c16 * 16;
                uint32_t sw = off ^ ((off >> 3) & 0x70);
                ldsm_x4(af[mi][0], af[mi][1], af[mi][2], af[mi][3], st + sw);
            }
            uint32_t bf[4][4];
#pragma unroll
            for (int pr = 0; pr < 4; ++pr) {
                uint32_t off = (uint32_t)(wn * 64 + pr * 16 + b_nrow) * 128 + ks * 32 + b_c16 * 16;
                uint32_t sw = off ^ ((off >> 3) & 0x70);
                ldsm_x4(bf[pr][0], bf[pr][1], bf[pr][2], bf[pr][3], st + 16384 + sw);
            }
#pragma unroll
            for (int mi = 0; mi < 2; ++mi) {
#pragma unroll
                for (int pr = 0; pr < 4; ++pr) {
                    mma16816(acc[mi][pr * 2][0], acc[mi][pr * 2][1],
                             acc[mi][pr * 2][2], acc[mi][pr * 2][3],
                             af[mi][0], af[mi][1], af[mi][2], af[mi][3],
                             bf[pr][0], bf[pr][1]);
                    mma16816(acc[mi][pr * 2 + 1][0], acc[mi][pr * 2 + 1][1],
                             acc[mi][pr * 2 + 1][2], acc[mi][pr * 2 + 1][3],
                             af[mi][0], af[mi][1], af[mi][2], af[mi][3],
                             bf[pr][2], bf[pr][3]);
                }
            }
        }
    }
    __syncthreads();

#pragma unroll
    for (int mi = 0; mi < 2; ++mi) {
        int row0 = bm + wm * 32 + mi * 16 + (lane >> 2);
#pragma unroll
        for (int ni = 0; ni < 8; ++ni) {
            int col = bn + wn * 64 + ni * 8 + (lane & 3) * 2;
            *(__half2*)(C + (size_t)row0 * Nn + col) =
                __floats2half2_rn(acc[mi][ni][0], acc[mi][ni][1]);
            *(__half2*)(C + (size_t)(row0 + 8) * Nn + col) =
                __floats2half2_rn(acc[mi][ni][2], acc[mi][ni][3]);
        }
    }
#undef LOAD_CHUNK
}

// ---------------- tensor-core attention, exp-inline softmax ----------------
#define ATT_P 0
#define ATT_KV 65536
#define ATT_Q 90112
#define ATT_MASK 94208
#define ATT_STAT 96768
#define ATT_SMEM 97024

__device__ __forceinline__ uint32_t psw(int row, int bytecol) {
    return (uint32_t)(row * 2048 + (bytecol ^ ((row & 7) << 4)));
}

__global__ __launch_bounds__(256)
void attn_mma_kernel(const float* __restrict__ qin)
{
    extern __shared__ char dsm[];
    const uint32_t sb = smem_u32(dsm);
    unsigned int* smask = (unsigned int*)(dsm + ATT_MASK);
    float* sl = (float*)(dsm + ATT_STAT);

    const int h = blockIdx.x, b = blockIdx.y;
    const int tid = threadIdx.x;
    const int lane = tid & 31, w = tid >> 5;
    const int wm = w >> 2, wn = w & 3;

    const int a_row = (lane & 15);
    const int a_c16 = (lane >> 4);
    const int b_nrow = (lane & 7) + ((lane >> 4) & 1) * 8;
    const int b_c16 = (lane >> 3) & 1;

    if (tid < 20) sl[tid] = 0.f;
    if (tid < 160) {
#pragma unroll
        for (int j = 0; j < 4; j++) {
            int idx = tid * 4 + j;
            smask[idx] = g_mbits[(b * 20 + (idx >> 5)) * 32 + (idx & 31)];
        }
    }
    for (int e = tid; e < 2048; e += 256) {
        int row = e >> 6, d = e & 63;
        __half v = __float2half_rn(0.f);
        if (row < 20) v = __float2half_rn(qin[((size_t)(b * 20 + row)) * 512 + h * 64 + d]);
        uint32_t off = (uint32_t)(row * 128 + d * 2);
        *(__half*)(dsm + ATT_Q + (off ^ ((off >> 3) & 0x70))) = v;
    }

#define LOADK(t)                                                              \
    do {                                                                      \
        uint32_t st_ = sb + ATT_KV + ((t) % 3) * 8192;                        \
        int n0_ = (t) * 64;                                                   \
        _Pragma("unroll")                                                     \
        for (int i_ = 0; i_ < 2; i_++) {                                      \
            int c_ = tid + i_ * 256;                                          \
            int row_ = c_ >> 3, j_ = c_ & 7;                                  \
            uint32_t off_ = row_ * 128 + j_ * 16;                             \
            uint32_t sw_ = off_ ^ ((off_ >> 3) & 0x70);                       \
            cp_async16(st_ + sw_, g_kvlh + ((size_t)b * 1000 + n0_ + row_) * 1536 + h * 64 + j_ * 8); \
        }                                                                     \
        cp_commit();                                                          \
    } while (0)

#define LOADV(t)                                                              \
    do {                                                                      \
        uint32_t st_ = sb + ATT_KV + ((t) % 3) * 8192;                        \
        int n0_ = (t) * 64;                                                   \
        _Pragma("unroll")                                                     \
        for (int i_ = 0; i_ < 2; i_++) {                                      \
            int c_ = tid + i_ * 256;                                          \
            int row_ = c_ >> 3, j_ = c_ & 7;                                  \
            uint32_t off_ = row_ * 128 + j_ * 16;                             \
            uint32_t sw_ = off_ ^ ((off_ >> 3) & 0x70);                       \
            cp_async16(st_ + sw_, g_vT + (((size_t)b * 8 + h) * 64 + row_) * 1024 + n0_ + j_ * 8); \
        }                                                                     \
        cp_commit();                                                          \
    } while (0)

    LOADK(0);
    LOADK(1);
    __syncthreads();

    uint32_t af[4][4];
#pragma unroll
    for (int ks = 0; ks < 4; ++ks) {
        uint32_t off = (uint32_t)((wm * 16 + a_row) * 128 + ks * 32 + a_c16 * 16);
        ldsm_x4(af[ks][0], af[ks][1], af[ks][2], af[ks][3],
                sb + ATT_Q + (off ^ ((off >> 3) & 0x70)));
    }

    const int r0 = wm * 16 + (lane >> 2);
    const int r1 = r0 + 8;
    float rsum0 = 0.f, rsum1 = 0.f;

    for (int t = 0; t < 16; ++t) {
        if (t >= 14) cp_wait0(); else cp_wait1();
        __syncthreads();
        if (t + 2 < 16) LOADK(t + 2);

        uint32_t st = sb + ATT_KV + (t % 3) * 8192;
        float acc[2][4] = {{0.f, 0.f, 0.f, 0.f}, {0.f, 0.f, 0.f, 0.f}};
#pragma unroll
        for (int ks = 0; ks < 4; ++ks) {
            uint32_t off = (uint32_t)((wn * 16 + b_nrow) * 128 + ks * 32 + b_c16 * 16);
            uint32_t bf0, bf1, bf2, bf3;
            ldsm_x4(bf0, bf1, bf2, bf3, st + (off ^ ((off >> 3) & 0x70)));
            mma16816(acc[0][0], acc[0][1], acc[0][2], acc[0][3],
                     af[ks][0], af[ks][1], af[ks][2], af[ks][3], bf0, bf1);
            mma16816(acc[1][0], acc[1][1], acc[1][2], acc[1][3],
                     af[ks][0], af[ks][1], af[ks][2], af[ks][3], bf2, bf3);
        }

        const int nb = t * 64 + wn * 16;
        const int widx = nb >> 5;
        unsigned int w0 = (r0 < 20) ? smask[r0 * 32 + widx] : 0u;
        unsigned int w1 = (r1 < 20) ? smask[r1 * 32 + widx] : 0u;
#pragma unroll
        for (int f = 0; f < 2; ++f) {
            int c = (lane & 3) * 2 + f * 8;
            int bit = (nb + c) & 31;
            float p00 = ((w0 >> bit) & 1u) ? fminf(__expf(acc[f][0] * INV_SQRT_DK), 60000.f) : 0.f;
            float p01 = ((w0 >> (bit + 1)) & 1u) ? fminf(__expf(acc[f][1] * INV_SQRT_DK), 60000.f) : 0.f;
            float p10 = ((w1 >> bit) & 1u) ? fminf(__expf(acc[f][2] * INV_SQRT_DK), 60000.f) : 0.f;
            float p11 = ((w1 >> (bit + 1)) & 1u) ? fminf(__expf(acc[f][3] * INV_SQRT_DK), 60000.f) : 0.f;
            rsum0 += p00 + p01;
            rsum1 += p10 + p11;
            int bytec = t * 128 + (wn * 16 + c) * 2;
            *(__half2*)(dsm + ATT_P + psw(r0, bytec)) = __floats2half2_rn(p00, p01);
            *(__half2*)(dsm + ATT_P + psw(r1, bytec)) = __floats2half2_rn(p10, p11);
        }
    }
    __syncthreads();

    LOADV(0);
    LOADV(1);

    rsum0 += __shfl_xor_sync(0xffffffffu, rsum0, 1);
    rsum0 += __shfl_xor_sync(0xffffffffu, rsum0, 2);
    rsum1 += __shfl_xor_sync(0xffffffffu, rsum1, 1);
    rsum1 += __shfl_xor_sync(0xffffffffu, rsum1, 2);
    if ((lane & 3) == 0) {
        if (r0 < 20) atomicAdd(&sl[r0], rsum0);
        if (r1 < 20) atomicAdd(&sl[r1], rsum1);
    }
    __syncthreads();

    float oacc[2][4] = {{0.f, 0.f, 0.f, 0.f}, {0.f, 0.f, 0.f, 0.f}};
    for (int t = 0; t < 16; ++t) {
        if (t >= 14) cp_wait0(); else cp_wait1();
        __syncthreads();
        if (t + 2 < 16) LOADV(t + 2);

        uint32_t st = sb + ATT_KV + (t % 3) * 8192;
#pragma unroll
        for (int ks = 0; ks < 4; ++ks) {
            uint32_t pa0, pa1, pa2, pa3;
            ldsm_x4(pa0, pa1, pa2, pa3,
                    sb + ATT_P + psw(wm * 16 + a_row, t * 128 + ks * 32 + a_c16 * 16));
            uint32_t off = (uint32_t)((wn * 16 + b_nrow) * 128 + ks * 32 + b_c16 * 16);
            uint32_t bf0, bf1, bf2, bf3;
            ldsm_x4(bf0, bf1, bf2, bf3, st + (off ^ ((off >> 3) & 0x70)));
            mma16816(oacc[0][0], oacc[0][1], oacc[0][2], oacc[0][3],
                     pa0, pa1, pa2, pa3, bf0, bf1);
            mma16816(oacc[1][0], oacc[1][1], oacc[1][2], oacc[1][3],
                     pa0, pa1, pa2, pa3, bf2, bf3);
        }
    }

#pragma unroll
    for (int f = 0; f < 2; ++f) {
        int col = h * 64 + wn * 16 + f * 8 + (lane & 3) * 2;
        if (r0 < 20) {
            float inv = 1.f / sl[r0];
            *(__half2*)(g_Hf16 + ((size_t)(b * 20 + r0)) * 512 + col) =
                __floats2half2_rn(oacc[f][0] * inv, oacc[f][1] * inv);
        }
        if (r1 < 20) {
            float inv = 1.f / sl[r1];
            *(__half2*)(g_Hf16 + ((size_t)(b * 20 + r1)) * 512 + col) =
                __floats2half2_rn(oacc[f][2] * inv, oacc[f][3] * inv);
        }
    }
#undef LOADK
#undef LOADV
}

// ---------------- pointer logits via MMA ----------------
#define PTR_A 0
#define PTR_B 32768
#define PTR_MASK 49152
#define PTR_SMEM 51712

__global__ __launch_bounds__(256)
void pointer_mma_kernel()
{
    extern __shared__ char dsm[];
    const uint32_t sb = smem_u32(dsm);
    unsigned int* smask = (unsigned int*)(dsm + PTR_MASK);

    const int nsl = blockIdx.x, b = blockIdx.y;
    const int tid = threadIdx.x;
    const int lane = tid & 31, w = tid >> 5;
    const int wm = w >> 2, wn = w & 3;

    const int a_row = (lane & 15);
    const int a_c16 = (lane >> 4);
    const int b_nrow = (lane & 7) + ((lane >> 4) & 1) * 8;
    const int b_c16 = (lane >> 3) & 1;

    for (int i = tid; i < 32768 / 16; i += 256)
        *(uint4*)(dsm + PTR_A + i * 16) = make_uint4(0u, 0u, 0u, 0u);
    if (tid < 160) {
#pragma unroll
        for (int j = 0; j < 4; j++) {
            int idx = tid * 4 + j;
            smask[idx] = g_mbits[(b * 20 + (idx >> 5)) * 32 + (idx & 31)];
        }
    }
    __syncthreads();

    for (int c = tid; c < 20 * 64; c += 256) {
        int row = c >> 6, j = c & 63;
        int kc = j >> 3, jj = j & 7;
        uint32_t off = (uint32_t)(row * 128 + jj * 16);
        uint32_t sw = off ^ ((off >> 3) & 0x70);
        *(uint4*)(dsm + PTR_A + kc * 4096 + sw) =
            *(const uint4*)(g_Gf16 + ((size_t)(b * 20 + row)) * 512 + kc * 64 + jj * 8);
    }

#define PLOADB(step)                                                          \
    do {                                                                      \
        int nt_ = (step) >> 3, kc_ = (step) & 7;                              \
        uint32_t st_ = sb + PTR_B + ((step) & 1) * 8192;                      \
        _Pragma("unroll")                                                     \
        for (int i_ = 0; i_ < 2; i_++) {                                      \
            int c_ = tid + i_ * 256;                                          \
            int row_ = c_ >> 3, j_ = c_ & 7;                                  \
            uint32_t off_ = row_ * 128 + j_ * 16;                             \
            uint32_t sw_ = off_ ^ ((off_ >> 3) & 0x70);                       \
            cp_async16(st_ + sw_,                                             \
                g_kvlh + ((size_t)b * 1000 + nsl * 512 + nt_ * 64 + row_) * 1536 + 1024 + kc_ * 64 + j_ * 8); \
        }                                                                     \
        cp_commit();                                                          \
    } while (0)

    PLOADB(0);
    __syncthreads();

    const int r0 = wm * 16 + (lane >> 2);
    const int r1 = r0 + 8;

    float acc[2][4];
    for (int step = 0; step < 64; ++step) {
        if (step + 1 < 64) { PLOADB(step + 1); cp_wait1(); } else { cp_wait0(); }
        __syncthreads();

        const int kc = step & 7;
        if (kc == 0) {
#pragma unroll
            for (int f = 0; f < 2; ++f)
#pragma unroll
                for (int r = 0; r < 4; ++r) acc[f][r] = 0.f;
        }

        uint32_t stB = sb + PTR_B + (step & 1) * 8192;
#pragma unroll
        for (int ks = 0; ks < 4; ++ks) {
            uint32_t a0, a1, a2, a3;
            uint32_t offA = (uint32_t)((wm * 16 + a_row) * 128 + ks * 32 + a_c16 * 16);
            ldsm_x4(a0, a1, a2, a3, sb + PTR_A + kc * 4096 + (offA ^ ((offA >> 3) & 0x70)));
            uint32_t offB = (uint32_t)((wn * 16 + b_nrow) * 128 + ks * 32 + b_c16 * 16);
            uint32_t bf0, bf1, bf2, bf3;
            ldsm_x4(bf0, bf1, bf2, bf3, stB + (offB ^ ((offB >> 3) & 0x70)));
            mma16816(acc[0][0], acc[0][1], acc[0][2], acc[0][3], a0, a1, a2, a3, bf0, bf1);
            mma16816(acc[1][0], acc[1][1], acc[1][2], acc[1][3], a0, a1, a2, a3, bf2, bf3);
        }

        if (kc == 7) {
            const int nt = step >> 3;
            const int nb = nsl * 512 + nt * 64 + wn * 16;
            const int widx = nb >> 5;
            unsigned int w0 = (r0 < 20) ? smask[r0 * 32 + widx] : 0u;
            unsigned int w1 = (r1 < 20) ? smask[r1 * 32 + widx] : 0u;
#pragma unroll
            for (int f = 0; f < 2; ++f) {
                int c = (lane & 3) * 2 + f * 8;
                int gn = nb + c;
                int bit = gn & 31;
                if (r0 < 20) {
                    if (gn < 1000) {
                        float lg = ((w0 >> bit) & 1u)
                                 ? 10.f * tanhf(acc[f][0] * INV_SQRT_D) : NEG_BIG;
                        g_logits[(size_t)(b * 20 + r0) * 1000 + gn] = lg;
                    }
                    if (gn + 1 < 1000) {
                        float lg = ((w0 >> (bit + 1)) & 1u)
                                 ? 10.f * tanhf(acc[f][1] * INV_SQRT_D) : NEG_BIG;
                        g_logits[(size_t)(b * 20 + r0) * 1000 + gn + 1] = lg;
                    }
                }
                if (r1 < 20) {
                    if (gn < 1000) {
                        float lg = ((w1 >> bit) & 1u)
                                 ? 10.f * tanhf(acc[f][2] * INV_SQRT_D) : NEG_BIG;
                        g_logits[(size_t)(b * 20 + r1) * 1000 + gn] = lg;
                    }
                    if (gn + 1 < 1000) {
                        float lg = ((w1 >> (bit + 1)) & 1u)
                                 ? 10.f * tanhf(acc[f][3] * INV_SQRT_D) : NEG_BIG;
                        g_logits[(size_t)(b * 20 + r1) * 1000 + gn + 1] = lg;
                    }
                }
            }
        }
        __syncthreads();
    }
#undef PLOADB
}

// ---------------- log-softmax + transposed writeout ----------------
__global__ __launch_bounds__(256)
void lsm_kernel(float* __restrict__ out)
{
    const int s = blockIdx.x, b = blockIdx.y;
    const float* row = g_logits + (size_t)(b * 20 + s) * 1000;
    float* orow = out + (size_t)(s * 64 + b) * 1000;
    __shared__ float red[8];
    const int tid = threadIdx.x;
    const int lane = tid & 31, w = tid >> 5;

    float mx = -1e30f;
    for (int i = tid; i < 1000; i += 256) mx = fmaxf(mx, row[i]);
    mx = warp_max(mx);
    if (lane == 0) red[w] = mx;
    __syncthreads();
    if (w == 0) {
        float v = (lane < 8) ? red[lane] : -1e30f;
        v = warp_max(v);
        if (lane == 0) red[0] = v;
    }
    __syncthreads();
    mx = red[0];
    __syncthreads();

    float se = 0.f;
    for (int i = tid; i < 1000; i += 256) se += __expf(row[i] - mx);
    se = warp_sum(se);
    if (lane == 0) red[w] = se;
    __syncthreads();
    if (w == 0) {
        float v = (lane < 8) ? red[lane] : 0.f;
        v = warp_sum(v);
        if (lane == 0) red[0] = v;
    }
    __syncthreads();
    const float lse = mx + logf(red[0]);

    for (int i = tid; i < 1000; i += 256) orow[i] = row[i] - lse;
}

// ---------------- launch ----------------
extern "C" void kernel_launch(void* const* d_in, const int* in_sizes, int n_in,
                              void* d_out, int out_size)
{
    (void)out_size;
    const float* emb = nullptr;
    const float* q = nullptr;
    const void* mask = nullptr;
    const float* Wkvl = nullptr;
    const float* Wout = nullptr;
    for (int i = 0; i < n_in; ++i) {
        switch (in_sizes[i]) {
            case 32768000: emb = (const float*)d_in[i]; break;
            case 655360:   q = (const float*)d_in[i]; break;
            case 1280000:  mask = d_in[i]; break;
            case 786432:   Wkvl = (const float*)d_in[i]; break;
            case 262144:   Wout = (const float*)d_in[i]; break;
            default: break;
        }
    }
    float* out = (float*)d_out;

    __half *kvlhp, *af16, *wkt, *wot, *hf16, *gf16;
    cudaGetSymbolAddress((void**)&kvlhp, g_kvlh);
    cudaGetSymbolAddress((void**)&af16, g_Af16);
    cudaGetSymbolAddress((void**)&wkt, g_Wkvl_t);
    cudaGetSymbolAddress((void**)&wot, g_Wout_t);
    cudaGetSymbolAddress((void**)&hf16, g_Hf16);
    cudaGetSymbolAddress((void**)&gf16, g_Gf16);

    cudaFuncSetAttribute(hmma_gemm_big, cudaFuncAttributeMaxDynamicSharedMemorySize, 147456);
    cudaFuncSetAttribute(attn_mma_kernel, cudaFuncAttributeMaxDynamicSharedMemorySize, ATT_SMEM);
    cudaFuncSetAttribute(pointer_mma_kernel, cudaFuncAttributeMaxDynamicSharedMemorySize, PTR_SMEM);

    // 1: fused prep
    prep_kernel<<<37376, 256>>>(emb, Wkvl, Wout, (const unsigned int*)mask);

    // 2: kvl = embeddings @ W_kvl -> g_kvlh (512-thread GEMM)
    {
        dim3 grid(6, 500);
        hmma_gemm_big<<<grid, 512, 147456>>>(af16, wkt, kvlhp, 1536);
    }

    // 3: V transpose
    {
        dim3 grid(32, 8, 64);
        vtrans_kernel<<<grid, 256>>>();
    }

    // 4: tensor-core attention (profiled slot)
    {
        dim3 grid(8, 64);
        attn_mma_kernel<<<grid, 256, ATT_SMEM>>>(q);
    }

    // 5: glimpse = heads @ W_out -> fp16
    {
        dim3 grid(2, 10);
        hmma_gemm_big<<<grid, 512, 147456>>>(hf16, wot, gf16, 512);
    }

    // 6: pointer logits via MMA
    {
        dim3 grid(2, 64);
        pointer_mma_kernel<<<grid, 256, PTR_SMEM>>>();
    }

    // 7: log-softmax
    {
        dim3 grid(20, 64);
        lsm_kernel<<<grid, 256>>>(out);
    }
}

// round 14
// speedup vs baseline: 2.6866x; 1.0409x over previous
#include <cuda_runtime.h>
#include <cuda_fp16.h>
#include <cstdint>

// B=64, N=1000, D=512, H=8, S=20, DK=64
#define NEG_BIG (-1e9f)
#define INV_SQRT_DK 0.125f
#define INV_SQRT_D 0.04419417382415922f

// ---------------- device scratch ----------------
__device__ __align__(16) __half g_kvlh[64032 * 1536];     // [row][gk|gv|lk]; rows>=64000 stay zero
__device__ __align__(16) float g_logits[1280 * 1000];
__device__ __align__(16) __half g_Af16[64000 * 512];
__device__ __align__(16) __half g_Wkvl_t[1536 * 512];
__device__ __align__(16) __half g_Wout_t[512 * 512];
__device__ __align__(16) __half g_Hf16[1280 * 512];
__device__ __align__(16) __half g_Gf16[1280 * 512];
__device__ __align__(16) unsigned int g_mbits[1280 * 32];

// ---------------- helpers ----------------
__device__ __forceinline__ float warp_max(float v) {
#pragma unroll
    for (int o = 16; o; o >>= 1) v = fmaxf(v, __shfl_xor_sync(0xffffffffu, v, o));
    return v;
}
__device__ __forceinline__ float warp_sum(float v) {
#pragma unroll
    for (int o = 16; o; o >>= 1) v += __shfl_xor_sync(0xffffffffu, v, o);
    return v;
}
__device__ __forceinline__ uint32_t smem_u32(const void* p) {
    uint32_t a;
    asm("{ .reg .u64 t; cvta.to.shared.u64 t, %1; cvt.u32.u64 %0, t; }" : "=r"(a) : "l"(p));
    return a;
}
__device__ __forceinline__ void cp_async16(uint32_t saddr, const void* gaddr) {
    asm volatile("cp.async.cg.shared.global [%0], [%1], 16;" :: "r"(saddr), "l"(gaddr));
}
__device__ __forceinline__ void cp_commit() { asm volatile("cp.async.commit_group;" ::: "memory"); }
__device__ __forceinline__ void cp_wait1() { asm volatile("cp.async.wait_group 1;" ::: "memory"); }
__device__ __forceinline__ void cp_wait0() { asm volatile("cp.async.wait_group 0;" ::: "memory"); }

__device__ __forceinline__ void ldsm_x4(uint32_t& r0, uint32_t& r1, uint32_t& r2, uint32_t& r3,
                                        uint32_t addr) {
    asm volatile("ldmatrix.sync.aligned.m8n8.x4.shared.b16 {%0,%1,%2,%3}, [%4];"
                 : "=r"(r0), "=r"(r1), "=r"(r2), "=r"(r3) : "r"(addr));
}
__device__ __forceinline__ void ldsm_x4_t(uint32_t& r0, uint32_t& r1, uint32_t& r2, uint32_t& r3,
                                          uint32_t addr) {
    asm volatile("ldmatrix.sync.aligned.m8n8.x4.trans.shared.b16 {%0,%1,%2,%3}, [%4];"
                 : "=r"(r0), "=r"(r1), "=r"(r2), "=r"(r3) : "r"(addr));
}
__device__ __forceinline__ void mma16816(float& c0, float& c1, float& c2, float& c3,
                                         uint32_t a0, uint32_t a1, uint32_t a2, uint32_t a3,
                                         uint32_t b0, uint32_t b1) {
    asm volatile(
        "mma.sync.aligned.m16n8k16.row.col.f32.f16.f16.f32 "
        "{%0,%1,%2,%3}, {%4,%5,%6,%7}, {%8,%9}, {%0,%1,%2,%3};"
        : "+f"(c0), "+f"(c1), "+f"(c2), "+f"(c3)
        : "r"(a0), "r"(a1), "r"(a2), "r"(a3), "r"(b0), "r"(b1));
}

// ---------------- fused prep with block offset (split across 3 launches) ----------------
// global bid: [0,32000) emb; [32000,35072) Wkvl^T; [35072,36096) Wout^T; [36096,37376) mask
__global__ __launch_bounds__(256)
void prep_kernel(const float* __restrict__ emb, const float* __restrict__ Wkvl,
                 const float* __restrict__ Wout, const unsigned int* __restrict__ mw,
                 int boff)
{
    int bid = blockIdx.x + boff;
    int tid = threadIdx.x;
    if (bid < 32000) {
        int i = bid * 256 + tid;
        float4 v = ((const float4*)emb)[i];
        ((__half2*)g_Af16)[i * 2] = __floats2half2_rn(v.x, v.y);
        ((__half2*)g_Af16)[i * 2 + 1] = __floats2half2_rn(v.z, v.w);
    } else if (bid < 35072) {
        int idx = (bid - 32000) * 256 + tid;
        int n = idx >> 9, k = idx & 511;
        g_Wkvl_t[idx] = __float2half_rn(Wkvl[(size_t)k * 1536 + n]);
    } else if (bid < 36096) {
        int idx = (bid - 35072) * 256 + tid;
        int n = idx >> 9, k = idx & 511;
        g_Wout_t[idx] = __float2half_rn(Wout[(size_t)k * 512 + n]);
    } else {
        __shared__ int flags;
        if (tid == 0) flags = 0;
        __syncthreads();
        int f = 0;
        for (int i = tid; i < 1024; i += 256) {
            unsigned int v = mw[i];
            if (v != 0u && v != 1u) f |= 1;
            if (v != 0u && v != 0x3F800000u) f |= 2;
        }
        if (f) atomicOr(&flags, f);
        __syncthreads();
        const int mode = ((flags & 1) && (flags & 2)) ? 0 : 1;
        const int lane = tid & 31, wid = tid >> 5;
        const int row = bid - 36096;
#pragma unroll
        for (int j = 0; j < 4; j++) {
            int widx = wid * 4 + j;
            int n = widx * 32 + lane;
            bool feas = false;
            if (n < 1000) {
                int idx = row * 1000 + n;
                feas = mode ? (mw[idx] != 0u)
                            : (((const unsigned char*)mw)[idx] != 0);
            }
            unsigned int word = __ballot_sync(0xffffffffu, feas);
            if (lane == 0) g_mbits[row * 32 + widx] = word;
        }
    }
}

// ---------------- BIG fp16 HMMA GEMM: 128x256 tile, 512 threads ----------------
__global__ __launch_bounds__(512, 1)
void hmma_gemm_big(const __half* __restrict__ A, const __half* __restrict__ Bt,
                   __half* __restrict__ C, int Nn)
{
    extern __shared__ char dsm[];
    const uint32_t sb = smem_u32(dsm);
    const int tid = threadIdx.x;
    const int bm = blockIdx.y * 128;
    const int bn = blockIdx.x * 256;
    const int lane = tid & 31, w = tid >> 5;
    const int wm = w >> 2;
    const int wn = w & 3;

    const char* Ag = (const char*)A + (size_t)bm * 1024;
    const char* Bg = (const char*)Bt + (size_t)bn * 1024;

#define LOAD_CHUNK(kc)                                                      \
    do {                                                                    \
        uint32_t st_ = sb + ((kc) % 3) * 49152;                             \
        size_t gk_ = (size_t)(kc) * 128;                                    \
        _Pragma("unroll")                                                   \
        for (int i_ = 0; i_ < 2; i_++) {                                    \
            int g_ = tid + i_ * 512;                                        \
            int row_ = g_ >> 3, ch_ = g_ & 7;                               \
            uint32_t off_ = row_ * 128 + ch_ * 16;                          \
            uint32_t sw_ = off_ ^ ((off_ >> 3) & 0x70);                     \
            cp_async16(st_ + sw_, Ag + (size_t)row_ * 1024 + gk_ + ch_ * 16); \
        }                                                                   \
        _Pragma("unroll")                                                   \
        for (int i_ = 0; i_ < 4; i_++) {                                    \
            int g_ = tid + i_ * 512;                                        \
            int row_ = g_ >> 3, ch_ = g_ & 7;                               \
            uint32_t off_ = row_ * 128 + ch_ * 16;                          \
            uint32_t sw_ = off_ ^ ((off_ >> 3) & 0x70);                     \
            cp_async16(st_ + 16384 + sw_, Bg + (size_t)row_ * 1024 + gk_ + ch_ * 16); \
        }                                                                   \
        cp_commit();                                                        \
    } while (0)

    float acc[2][8][4];
#pragma unroll
    for (int i = 0; i < 2; i++)
#pragma unroll
        for (int j = 0; j < 8; j++)
#pragma unroll
            for (int r = 0; r < 4; r++) acc[i][j][r] = 0.f;

    LOAD_CHUNK(0);
    LOAD_CHUNK(1);

    const int a_row = (lane & 15);
    const int a_c16 = (lane >> 4);
    const int b_nrow = (lane & 7) + ((lane >> 4) & 1) * 8;
    const int b_c16 = (lane >> 3) & 1;

    for (int kc = 0; kc < 8; ++kc) {
        if (kc == 7) cp_wait0(); else cp_wait1();
        __syncthreads();
        if (kc + 2 < 8) LOAD_CHUNK(kc + 2);

        uint32_t st = sb + (kc % 3) * 49152;
#pragma unroll
        for (int ks = 0; ks < 4; ++ks) {
            uint32_t af[2][4];
#pragma unroll
            for (int mi = 0; mi < 2; ++mi) {
                uint32_t off = (uint32_t)(wm * 32 + mi * 16 + a_row) * 128 + ks * 32 + a_c16 * 16;
                uint32_t sw = off ^ ((off >> 3) & 0x70);
                ldsm_x4(af[mi][0], af[mi][1], af[mi][2], af[mi][3], st + sw);
            }
            uint32_t bf[4][4];
#pragma unroll
            for (int pr = 0; pr < 4; ++pr) {
                uint32_t off = (uint32_t)(wn * 64 + pr * 16 + b_nrow) * 128 + ks * 32 + b_c16 * 16;
                uint32_t sw = off ^ ((off >> 3) & 0x70);
                ldsm_x4(bf[pr][0], bf[pr][1], bf[pr][2], bf[pr][3], st + 16384 + sw);
            }
#pragma unroll
            for (int mi = 0; mi < 2; ++mi) {
#pragma unroll
                for (int pr = 0; pr < 4; ++pr) {
                    mma16816(acc[mi][pr * 2][0], acc[mi][pr * 2][1],
                             acc[mi][pr * 2][2], acc[mi][pr * 2][3],
                             af[mi][0], af[mi][1], af[mi][2], af[mi][3],
                             bf[pr][0], bf[pr][1]);
                    mma16816(acc[mi][pr * 2 + 1][0], acc[mi][pr * 2 + 1][1],
                             acc[mi][pr * 2 + 1][2], acc[mi][pr * 2 + 1][3],
                             af[mi][0], af[mi][1], af[mi][2], af[mi][3],
                             bf[pr][2], bf[pr][3]);
                }
            }
        }
    }
    __syncthreads();

#pragma unroll
    for (int mi = 0; mi < 2; ++mi) {
        int row0 = bm + wm * 32 + mi * 16 + (lane >> 2);
#pragma unroll
        for (int ni = 0; ni < 8; ++ni) {
            int col = bn + wn * 64 + ni * 8 + (lane & 3) * 2;
            *(__half2*)(C + (size_t)row0 * Nn + col) =
                __floats2half2_rn(acc[mi][ni][0], acc[mi][ni][1]);
            *(__half2*)(C + (size_t)(row0 + 8) * Nn + col) =
                __floats2half2_rn(acc[mi][ni][2], acc[mi][ni][3]);
        }
    }
#undef LOAD_CHUNK
}

// ---------------- tensor-core attention, exp-inline softmax, trans-ldmatrix V ----------------
#define ATT_P 0
#define ATT_KV 65536
#define ATT_Q 90112
#define ATT_MASK 94208
#define ATT_STAT 96768
#define ATT_SMEM 97024

__device__ __forceinline__ uint32_t psw(int row, int bytecol) {
    return (uint32_t)(row * 2048 + (bytecol ^ ((row & 7) << 4)));
}

__global__ __launch_bounds__(256)
void attn_mma_kernel(const float* __restrict__ qin)
{
    extern __shared__ char dsm[];
    const uint32_t sb = smem_u32(dsm);
    unsigned int* smask = (unsigned int*)(dsm + ATT_MASK);
    float* sl = (float*)(dsm + ATT_STAT);

    const int h = blockIdx.x, b = blockIdx.y;
    const int tid = threadIdx.x;
    const int lane = tid & 31, w = tid >> 5;
    const int wm = w >> 2, wn = w & 3;

    const int a_row = (lane & 15);
    const int a_c16 = (lane >> 4);
    const int b_nrow = (lane & 7) + ((lane >> 4) & 1) * 8;
    const int b_c16 = (lane >> 3) & 1;
    // trans-ldmatrix lane mapping for V (PV B-operand)
    const int v_row = (lane & 7) + ((lane >> 3) & 1) * 8;
    const int v_c16 = lane >> 4;

    if (tid < 20) sl[tid] = 0.f;
    if (tid < 160) {
#pragma unroll
        for (int j = 0; j < 4; j++) {
            int idx = tid * 4 + j;
            smask[idx] = g_mbits[(b * 20 + (idx >> 5)) * 32 + (idx & 31)];
        }
    }
    for (int e = tid; e < 2048; e += 256) {
        int row = e >> 6, d = e & 63;
        __half v = __float2half_rn(0.f);
        if (row < 20) v = __float2half_rn(qin[((size_t)(b * 20 + row)) * 512 + h * 64 + d]);
        uint32_t off = (uint32_t)(row * 128 + d * 2);
        *(__half*)(dsm + ATT_Q + (off ^ ((off >> 3) & 0x70))) = v;
    }

    // K and V tiles share the same 64-row x 128-B shape; V = K source + 512 halves
#define LOADKV(t, voff)                                                       \
    do {                                                                      \
        uint32_t st_ = sb + ATT_KV + ((t) % 3) * 8192;                        \
        int n0_ = (t) * 64;                                                   \
        _Pragma("unroll")                                                     \
        for (int i_ = 0; i_ < 2; i_++) {                                      \
            int c_ = tid + i_ * 256;                                          \
            int row_ = c_ >> 3, j_ = c_ & 7;                                  \
            uint32_t off_ = row_ * 128 + j_ * 16;                             \
            uint32_t sw_ = off_ ^ ((off_ >> 3) & 0x70);                       \
            cp_async16(st_ + sw_,                                             \
                g_kvlh + ((size_t)b * 1000 + n0_ + row_) * 1536 + (voff) + h * 64 + j_ * 8); \
        }                                                                     \
        cp_commit();                                                          \
    } while (0)

    LOADKV(0, 0);
    LOADKV(1, 0);
    __syncthreads();

    uint32_t af[4][4];
#pragma unroll
    for (int ks = 0; ks < 4; ++ks) {
        uint32_t off = (uint32_t)((wm * 16 + a_row) * 128 + ks * 32 + a_c16 * 16);
        ldsm_x4(af[ks][0], af[ks][1], af[ks][2], af[ks][3],
                sb + ATT_Q + (off ^ ((off >> 3) & 0x70)));
    }

    const int r0 = wm * 16 + (lane >> 2);
    const int r1 = r0 + 8;
    float rsum0 = 0.f, rsum1 = 0.f;

    // ---- phase 1: P = exp(masked S); row sums in registers ----
    for (int t = 0; t < 16; ++t) {
        if (t >= 14) cp_wait0(); else cp_wait1();
        __syncthreads();
        if (t + 2 < 16) LOADKV(t + 2, 0);

        uint32_t st = sb + ATT_KV + (t % 3) * 8192;
        float acc[2][4] = {{0.f, 0.f, 0.f, 0.f}, {0.f, 0.f, 0.f, 0.f}};
#pragma unroll
        for (int ks = 0; ks < 4; ++ks) {
            uint32_t off = (uint32_t)((wn * 16 + b_nrow) * 128 + ks * 32 + b_c16 * 16);
            uint32_t bf0, bf1, bf2, bf3;
            ldsm_x4(bf0, bf1, bf2, bf3, st + (off ^ ((off >> 3) & 0x70)));
            mma16816(acc[0][0], acc[0][1], acc[0][2], acc[0][3],
                     af[ks][0], af[ks][1], af[ks][2], af[ks][3], bf0, bf1);
            mma16816(acc[1][0], acc[1][1], acc[1][2], acc[1][3],
                     af[ks][0], af[ks][1], af[ks][2], af[ks][3], bf2, bf3);
        }

        const int nb = t * 64 + wn * 16;
        const int widx = nb >> 5;
        unsigned int w0 = (r0 < 20) ? smask[r0 * 32 + widx] : 0u;
        unsigned int w1 = (r1 < 20) ? smask[r1 * 32 + widx] : 0u;
#pragma unroll
        for (int f = 0; f < 2; ++f) {
            int c = (lane & 3) * 2 + f * 8;
            int bit = (nb + c) & 31;
            float p00 = ((w0 >> bit) & 1u) ? fminf(__expf(acc[f][0] * INV_SQRT_DK), 60000.f) : 0.f;
            float p01 = ((w0 >> (bit + 1)) & 1u) ? fminf(__expf(acc[f][1] * INV_SQRT_DK), 60000.f) : 0.f;
            float p10 = ((w1 >> bit) & 1u) ? fminf(__expf(acc[f][2] * INV_SQRT_DK), 60000.f) : 0.f;
            float p11 = ((w1 >> (bit + 1)) & 1u) ? fminf(__expf(acc[f][3] * INV_SQRT_DK), 60000.f) : 0.f;
            rsum0 += p00 + p01;
            rsum1 += p10 + p11;
            int bytec = t * 128 + (wn * 16 + c) * 2;
            *(__half2*)(dsm + ATT_P + psw(r0, bytec)) = __floats2half2_rn(p00, p01);
            *(__half2*)(dsm + ATT_P + psw(r1, bytec)) = __floats2half2_rn(p10, p11);
        }
    }
    __syncthreads();

    LOADKV(0, 512);
    LOADKV(1, 512);

    rsum0 += __shfl_xor_sync(0xffffffffu, rsum0, 1);
    rsum0 += __shfl_xor_sync(0xffffffffu, rsum0, 2);
    rsum1 += __shfl_xor_sync(0xffffffffu, rsum1, 1);
    rsum1 += __shfl_xor_sync(0xffffffffu, rsum1, 2);
    if ((lane & 3) == 0) {
        if (r0 < 20) atomicAdd(&sl[r0], rsum0);
        if (r1 < 20) atomicAdd(&sl[r1], rsum1);
    }
    __syncthreads();

    // ---- phase 2: O = P @ V with trans-ldmatrix B fragments ----
    float oacc[2][4] = {{0.f, 0.f, 0.f, 0.f}, {0.f, 0.f, 0.f, 0.f}};
    for (int t = 0; t < 16; ++t) {
        if (t >= 14) cp_wait0(); else cp_wait1();
        __syncthreads();
        if (t + 2 < 16) LOADKV(t + 2, 512);

        uint32_t st = sb + ATT_KV + (t % 3) * 8192;
#pragma unroll
        for (int ks = 0; ks < 4; ++ks) {
            uint32_t pa0, pa1, pa2, pa3;
            ldsm_x4(pa0, pa1, pa2, pa3,
                    sb + ATT_P + psw(wm * 16 + a_row, t * 128 + ks * 32 + a_c16 * 16));
            // B from V tile rows n = ks*16 + v_row, byte cols wn*32 + v_c16*16
            uint32_t off = (uint32_t)((ks * 16 + v_row) * 128 + wn * 32 + v_c16 * 16);
            uint32_t bf0, bf1, bf2, bf3;
            ldsm_x4_t(bf0, bf1, bf2, bf3, st + (off ^ ((off >> 3) & 0x70)));
            mma16816(oacc[0][0], oacc[0][1], oacc[0][2], oacc[0][3],
                     pa0, pa1, pa2, pa3, bf0, bf1);
            mma16816(oacc[1][0], oacc[1][1], oacc[1][2], oacc[1][3],
                     pa0, pa1, pa2, pa3, bf2, bf3);
        }
    }

#pragma unroll
    for (int f = 0; f < 2; ++f) {
        int col = h * 64 + wn * 16 + f * 8 + (lane & 3) * 2;
        if (r0 < 20) {
            float inv = 1.f / sl[r0];
            *(__half2*)(g_Hf16 + ((size_t)(b * 20 + r0)) * 512 + col) =
                __floats2half2_rn(oacc[f][0] * inv, oacc[f][1] * inv);
        }
        if (r1 < 20) {
            float inv = 1.f / sl[r1];
            *(__half2*)(g_Hf16 + ((size_t)(b * 20 + r1)) * 512 + col) =
                __floats2half2_rn(oacc[f][2] * inv, oacc[f][3] * inv);
        }
    }
#undef LOADKV
}

// ---------------- pointer logits via MMA ----------------
#define PTR_A 0
#define PTR_B 32768
#define PTR_MASK 49152
#define PTR_SMEM 51712

__global__ __launch_bounds__(256)
void pointer_mma_kernel()
{
    extern __shared__ char dsm[];
    const uint32_t sb = smem_u32(dsm);
    unsigned int* smask = (unsigned int*)(dsm + PTR_MASK);

    const int nsl = blockIdx.x, b = blockIdx.y;
    const int tid = threadIdx.x;
    const int lane = tid & 31, w = tid >> 5;
    const int wm = w >> 2, wn = w & 3;

    const int a_row = (lane & 15);
    const int a_c16 = (lane >> 4);
    const int b_nrow = (lane & 7) + ((lane >> 4) & 1) * 8;
    const int b_c16 = (lane >> 3) & 1;

    for (int i = tid; i < 32768 / 16; i += 256)
        *(uint4*)(dsm + PTR_A + i * 16) = make_uint4(0u, 0u, 0u, 0u);
    if (tid < 160) {
#pragma unroll
        for (int j = 0; j < 4; j++) {
            int idx = tid * 4 + j;
            smask[idx] = g_mbits[(b * 20 + (idx >> 5)) * 32 + (idx & 31)];
        }
    }
    __syncthreads();

    for (int c = tid; c < 20 * 64; c += 256) {
        int row = c >> 6, j = c & 63;
        int kc = j >> 3, jj = j & 7;
        uint32_t off = (uint32_t)(row * 128 + jj * 16);
        uint32_t sw = off ^ ((off >> 3) & 0x70);
        *(uint4*)(dsm + PTR_A + kc * 4096 + sw) =
            *(const uint4*)(g_Gf16 + ((size_t)(b * 20 + row)) * 512 + kc * 64 + jj * 8);
    }

#define PLOADB(step)                                                          \
    do {                                                                      \
        int nt_ = (step) >> 3, kc_ = (step) & 7;                              \
        uint32_t st_ = sb + PTR_B + ((step) & 1) * 8192;                      \
        _Pragma("unroll")                                                     \
        for (int i_ = 0; i_ < 2; i_++) {                                      \
            int c_ = tid + i_ * 256;                                          \
            int row_ = c_ >> 3, j_ = c_ & 7;                                  \
            uint32_t off_ = row_ * 128 + j_ * 16;                             \
            uint32_t sw_ = off_ ^ ((off_ >> 3) & 0x70);                       \
            cp_async16(st_ + sw_,                                             \
                g_kvlh + ((size_t)b * 1000 + nsl * 512 + nt_ * 64 + row_) * 1536 + 1024 + kc_ * 64 + j_ * 8); \
        }                                                                     \
        cp_commit();                                                          \
    } while (0)

    PLOADB(0);
    __syncthreads();

    const int r0 = wm * 16 + (lane >> 2);
    const int r1 = r0 + 8;

    float acc[2][4];
    for (int step = 0; step < 64; ++step) {
        if (step + 1 < 64) { PLOADB(step + 1); cp_wait1(); } else { cp_wait0(); }
        __syncthreads();

        const int kc = step & 7;
        if (kc == 0) {
#pragma unroll
            for (int f = 0; f < 2; ++f)
#pragma unroll
                for (int r = 0; r < 4; ++r) acc[f][r] = 0.f;
        }

        uint32_t stB = sb + PTR_B + (step & 1) * 8192;
#pragma unroll
        for (int ks = 0; ks < 4; ++ks) {
            uint32_t a0, a1, a2, a3;
            uint32_t offA = (uint32_t)((wm * 16 + a_row) * 128 + ks * 32 + a_c16 * 16);
            ldsm_x4(a0, a1, a2, a3, sb + PTR_A + kc * 4096 + (offA ^ ((offA >> 3) & 0x70)));
            uint32_t offB = (uint32_t)((wn * 16 + b_nrow) * 128 + ks * 32 + b_c16 * 16);
            uint32_t bf0, bf1, bf2, bf3;
            ldsm_x4(bf0, bf1, bf2, bf3, stB + (offB ^ ((offB >> 3) & 0x70)));
            mma16816(acc[0][0], acc[0][1], acc[0][2], acc[0][3], a0, a1, a2, a3, bf0, bf1);
            mma16816(acc[1][0], acc[1][1], acc[1][2], acc[1][3], a0, a1, a2, a3, bf2, bf3);
        }

        if (kc == 7) {
            const int nt = step >> 3;
            const int nb = nsl * 512 + nt * 64 + wn * 16;
            const int widx = nb >> 5;
            unsigned int w0 = (r0 < 20) ? smask[r0 * 32 + widx] : 0u;
            unsigned int w1 = (r1 < 20) ? smask[r1 * 32 + widx] : 0u;
#pragma unroll
            for (int f = 0; f < 2; ++f) {
                int c = (lane & 3) * 2 + f * 8;
                int gn = nb + c;
                int bit = gn & 31;
                if (r0 < 20) {
                    if (gn < 1000) {
                        float lg = ((w0 >> bit) & 1u)
                                 ? 10.f * tanhf(acc[f][0] * INV_SQRT_D) : NEG_BIG;
                        g_logits[(size_t)(b * 20 + r0) * 1000 + gn] = lg;
                    }
                    if (gn + 1 < 1000) {
                        float lg = ((w0 >> (bit + 1)) & 1u)
                                 ? 10.f * tanhf(acc[f][1] * INV_SQRT_D) : NEG_BIG;
                        g_logits[(size_t)(b * 20 + r0) * 1000 + gn + 1] = lg;
                    }
                }
                if (r1 < 20) {
                    if (gn < 1000) {
                        float lg = ((w1 >> bit) & 1u)
                                 ? 10.f * tanhf(acc[f][2] * INV_SQRT_D) : NEG_BIG;
                        g_logits[(size_t)(b * 20 + r1) * 1000 + gn] = lg;
                    }
                    if (gn + 1 < 1000) {
                        float lg = ((w1 >> (bit + 1)) & 1u)
                                 ? 10.f * tanhf(acc[f][3] * INV_SQRT_D) : NEG_BIG;
                        g_logits[(size_t)(b * 20 + r1) * 1000 + gn + 1] = lg;
                    }
                }
            }
        }
        __syncthreads();
    }
#undef PLOADB
}

// ---------------- log-softmax + transposed writeout ----------------
__global__ __launch_bounds__(256)
void lsm_kernel(float* __restrict__ out)
{
    const int s = blockIdx.x, b = blockIdx.y;
    const float* row = g_logits + (size_t)(b * 20 + s) * 1000;
    float* orow = out + (size_t)(s * 64 + b) * 1000;
    __shared__ float red[8];
    const int tid = threadIdx.x;
    const int lane = tid & 31, w = tid >> 5;

    float mx = -1e30f;
    for (int i = tid; i < 1000; i += 256) mx = fmaxf(mx, row[i]);
    mx = warp_max(mx);
    if (lane == 0) red[w] = mx;
    __syncthreads();
    if (w == 0) {
        float v = (lane < 8) ? red[lane] : -1e30f;
        v = warp_max(v);
        if (lane == 0) red[0] = v;
    }
    __syncthreads();
    mx = red[0];
    __syncthreads();

    float se = 0.f;
    for (int i = tid; i < 1000; i += 256) se += __expf(row[i] - mx);
    se = warp_sum(se);
    if (lane == 0) red[w] = se;
    __syncthreads();
    if (w == 0) {
        float v = (lane < 8) ? red[lane] : 0.f;
        v = warp_sum(v);
        if (lane == 0) red[0] = v;
    }
    __syncthreads();
    const float lse = mx + logf(red[0]);

    for (int i = tid; i < 1000; i += 256) orow[i] = row[i] - lse;
}

// ---------------- launch ----------------
extern "C" void kernel_launch(void* const* d_in, const int* in_sizes, int n_in,
                              void* d_out, int out_size)
{
    (void)out_size;
    const float* emb = nullptr;
    const float* q = nullptr;
    const void* mask = nullptr;
    const float* Wkvl = nullptr;
    const float* Wout = nullptr;
    for (int i = 0; i < n_in; ++i) {
        switch (in_sizes[i]) {
            case 32768000: emb = (const float*)d_in[i]; break;
            case 655360:   q = (const float*)d_in[i]; break;
            case 1280000:  mask = d_in[i]; break;
            case 786432:   Wkvl = (const float*)d_in[i]; break;
            case 262144:   Wout = (const float*)d_in[i]; break;
            default: break;
        }
    }
    float* out = (float*)d_out;

    __half *kvlhp, *af16, *wkt, *wot, *hf16, *gf16;
    cudaGetSymbolAddress((void**)&kvlhp, g_kvlh);
    cudaGetSymbolAddress((void**)&af16, g_Af16);
    cudaGetSymbolAddress((void**)&wkt, g_Wkvl_t);
    cudaGetSymbolAddress((void**)&wot, g_Wout_t);
    cudaGetSymbolAddress((void**)&hf16, g_Hf16);
    cudaGetSymbolAddress((void**)&gf16, g_Gf16);

    cudaFuncSetAttribute(hmma_gemm_big, cudaFuncAttributeMaxDynamicSharedMemorySize, 147456);
    cudaFuncSetAttribute(attn_mma_kernel, cudaFuncAttributeMaxDynamicSharedMemorySize, ATT_SMEM);
    cudaFuncSetAttribute(pointer_mma_kernel, cudaFuncAttributeMaxDynamicSharedMemorySize, PTR_SMEM);

    const unsigned int* mw = (const unsigned int*)mask;
    // 1-3: prep split so the big GEMM lands in profiled slot #4
    prep_kernel<<<16000, 256>>>(emb, Wkvl, Wout, mw, 0);
    prep_kernel<<<16000, 256>>>(emb, Wkvl, Wout, mw, 16000);
    prep_kernel<<<5376, 256>>>(emb, Wkvl, Wout, mw, 32000);

    // 4: kvl = embeddings @ W_kvl -> g_kvlh (profiled)
    {
        dim3 grid(6, 500);
        hmma_gemm_big<<<grid, 512, 147456>>>(af16, wkt, kvlhp, 1536);
    }

    // 5: tensor-core attention (V via trans-ldmatrix, no vtrans pass)
    {
        dim3 grid(8, 64);
        attn_mma_kernel<<<grid, 256, ATT_SMEM>>>(q);
    }

    // 6: glimpse = heads @ W_out -> fp16
    {
        dim3 grid(2, 10);
        hmma_gemm_big<<<grid, 512, 147456>>>(hf16, wot, gf16, 512);
    }

    // 7: pointer logits via MMA
    {
        dim3 grid(2, 64);
        pointer_mma_kernel<<<grid, 256, PTR_SMEM>>>();
    }

    // 8: log-softmax
    {
        dim3 grid(20, 64);
        lsm_kernel<<<grid, 256>>>(out);
    }
}

// round 15
// speedup vs baseline: 2.7260x; 1.0147x over previous
#include <cuda_runtime.h>
#include <cuda_fp16.h>
#include <cstdint>

// B=64, N=1000, D=512, H=8, S=20, DK=64
#define NEG_BIG (-1e9f)
#define INV_SQRT_DK 0.125f
#define INV_SQRT_D 0.04419417382415922f

// ---------------- device scratch ----------------
__device__ __align__(16) __half g_kvlh[64032 * 1536];     // [row][gk|gv|lk]; rows>=64000 stay zero
__device__ __align__(16) float g_logits[1280 * 1000];
__device__ __align__(16) __half g_Af16[64000 * 512];
__device__ __align__(16) __half g_Wkvl_t[1536 * 512];
__device__ __align__(16) __half g_Wout_t[512 * 512];
__device__ __align__(16) __half g_Hf16[1280 * 512];
__device__ __align__(16) __half g_Gf16[1280 * 512];
__device__ __align__(16) unsigned int g_mbits[1280 * 32];

// ---------------- helpers ----------------
__device__ __forceinline__ float warp_max(float v) {
#pragma unroll
    for (int o = 16; o; o >>= 1) v = fmaxf(v, __shfl_xor_sync(0xffffffffu, v, o));
    return v;
}
__device__ __forceinline__ float warp_sum(float v) {
#pragma unroll
    for (int o = 16; o; o >>= 1) v += __shfl_xor_sync(0xffffffffu, v, o);
    return v;
}
__device__ __forceinline__ uint32_t smem_u32(const void* p) {
    uint32_t a;
    asm("{ .reg .u64 t; cvta.to.shared.u64 t, %1; cvt.u32.u64 %0, t; }" : "=r"(a) : "l"(p));
    return a;
}
__device__ __forceinline__ void cp_async16(uint32_t saddr, const void* gaddr) {
    asm volatile("cp.async.cg.shared.global [%0], [%1], 16;" :: "r"(saddr), "l"(gaddr));
}
__device__ __forceinline__ void cp_commit() { asm volatile("cp.async.commit_group;" ::: "memory"); }
__device__ __forceinline__ void cp_wait1() { asm volatile("cp.async.wait_group 1;" ::: "memory"); }
__device__ __forceinline__ void cp_wait0() { asm volatile("cp.async.wait_group 0;" ::: "memory"); }

__device__ __forceinline__ void ldsm_x4(uint32_t& r0, uint32_t& r1, uint32_t& r2, uint32_t& r3,
                                        uint32_t addr) {
    asm volatile("ldmatrix.sync.aligned.m8n8.x4.shared.b16 {%0,%1,%2,%3}, [%4];"
                 : "=r"(r0), "=r"(r1), "=r"(r2), "=r"(r3) : "r"(addr));
}
__device__ __forceinline__ void ldsm_x4_t(uint32_t& r0, uint32_t& r1, uint32_t& r2, uint32_t& r3,
                                          uint32_t addr) {
    asm volatile("ldmatrix.sync.aligned.m8n8.x4.trans.shared.b16 {%0,%1,%2,%3}, [%4];"
                 : "=r"(r0), "=r"(r1), "=r"(r2), "=r"(r3) : "r"(addr));
}
__device__ __forceinline__ void mma16816(float& c0, float& c1, float& c2, float& c3,
                                         uint32_t a0, uint32_t a1, uint32_t a2, uint32_t a3,
                                         uint32_t b0, uint32_t b1) {
    asm volatile(
        "mma.sync.aligned.m16n8k16.row.col.f32.f16.f16.f32 "
        "{%0,%1,%2,%3}, {%4,%5,%6,%7}, {%8,%9}, {%0,%1,%2,%3};"
        : "+f"(c0), "+f"(c1), "+f"(c2), "+f"(c3)
        : "r"(a0), "r"(a1), "r"(a2), "r"(a3), "r"(b0), "r"(b1));
}

// ---------------- fused prep with block offset ----------------
__global__ __launch_bounds__(256)
void prep_kernel(const float* __restrict__ emb, const float* __restrict__ Wkvl,
                 const float* __restrict__ Wout, const unsigned int* __restrict__ mw,
                 int boff)
{
    int bid = blockIdx.x + boff;
    int tid = threadIdx.x;
    if (bid < 32000) {
        int i = bid * 256 + tid;
        float4 v = ((const float4*)emb)[i];
        ((__half2*)g_Af16)[i * 2] = __floats2half2_rn(v.x, v.y);
        ((__half2*)g_Af16)[i * 2 + 1] = __floats2half2_rn(v.z, v.w);
    } else if (bid < 35072) {
        int idx = (bid - 32000) * 256 + tid;
        int n = idx >> 9, k = idx & 511;
        g_Wkvl_t[idx] = __float2half_rn(Wkvl[(size_t)k * 1536 + n]);
    } else if (bid < 36096) {
        int idx = (bid - 35072) * 256 + tid;
        int n = idx >> 9, k = idx & 511;
        g_Wout_t[idx] = __float2half_rn(Wout[(size_t)k * 512 + n]);
    } else {
        __shared__ int flags;
        if (tid == 0) flags = 0;
        __syncthreads();
        int f = 0;
        for (int i = tid; i < 1024; i += 256) {
            unsigned int v = mw[i];
            if (v != 0u && v != 1u) f |= 1;
            if (v != 0u && v != 0x3F800000u) f |= 2;
        }
        if (f) atomicOr(&flags, f);
        __syncthreads();
        const int mode = ((flags & 1) && (flags & 2)) ? 0 : 1;
        const int lane = tid & 31, wid = tid >> 5;
        const int row = bid - 36096;
#pragma unroll
        for (int j = 0; j < 4; j++) {
            int widx = wid * 4 + j;
            int n = widx * 32 + lane;
            bool feas = false;
            if (n < 1000) {
                int idx = row * 1000 + n;
                feas = mode ? (mw[idx] != 0u)
                            : (((const unsigned char*)mw)[idx] != 0);
            }
            unsigned int word = __ballot_sync(0xffffffffu, feas);
            if (lane == 0) g_mbits[row * 32 + widx] = word;
        }
    }
}

// ---------------- fp16 HMMA GEMM: 128x128 tile, 256 threads, 3-stage, 2 CTAs/SM ----------------
// warps: wr = w>>2 (0..1) -> 64 m-rows; wc = w&3 -> 32 n-cols. fp16 output.
__global__ __launch_bounds__(256, 2)
void hmma_gemm128(const __half* __restrict__ A, const __half* __restrict__ Bt,
                  __half* __restrict__ C, int Nn)
{
    extern __shared__ char dsm[];
    const uint32_t sb = smem_u32(dsm);
    const int tid = threadIdx.x;
    const int bm = blockIdx.y * 128;
    const int bn = blockIdx.x * 128;
    const int lane = tid & 31, w = tid >> 5;
    const int wr = w >> 2;
    const int wc = w & 3;

    const char* Ag = (const char*)A + (size_t)bm * 1024;
    const char* Bg = (const char*)Bt + (size_t)bn * 1024;

#define LOAD_CHUNK(kc)                                                      \
    do {                                                                    \
        uint32_t st_ = sb + ((kc) % 3) * 32768;                             \
        size_t gk_ = (size_t)(kc) * 128;                                    \
        _Pragma("unroll")                                                   \
        for (int i_ = 0; i_ < 4; i_++) {                                    \
            int g_ = tid + i_ * 256;                                        \
            int row_ = g_ >> 3, ch_ = g_ & 7;                               \
            uint32_t off_ = row_ * 128 + ch_ * 16;                          \
            uint32_t sw_ = off_ ^ ((off_ >> 3) & 0x70);                     \
            size_t go_ = (size_t)row_ * 1024 + gk_ + ch_ * 16;              \
            cp_async16(st_ + sw_, Ag + go_);                                \
            cp_async16(st_ + 16384 + sw_, Bg + go_);                        \
        }                                                                   \
        cp_commit();                                                        \
    } while (0)

    float acc[4][4][4];
#pragma unroll
    for (int i = 0; i < 4; i++)
#pragma unroll
        for (int j = 0; j < 4; j++)
#pragma unroll
            for (int r = 0; r < 4; r++) acc[i][j][r] = 0.f;

    LOAD_CHUNK(0);
    LOAD_CHUNK(1);

    const int a_row = (lane & 15);
    const int a_c16 = (lane >> 4);
    const int b_nrow = (lane & 7) + ((lane >> 4) & 1) * 8;
    const int b_c16 = (lane >> 3) & 1;

    for (int kc = 0; kc < 8; ++kc) {
        if (kc == 7) cp_wait0(); else cp_wait1();
        __syncthreads();
        if (kc + 2 < 8) LOAD_CHUNK(kc + 2);

        uint32_t st = sb + (kc % 3) * 32768;
#pragma unroll
        for (int ks = 0; ks < 4; ++ks) {
            uint32_t af[4][4];
#pragma unroll
            for (int mi = 0; mi < 4; ++mi) {
                uint32_t off = (uint32_t)(wr * 64 + mi * 16 + a_row) * 128 + ks * 32 + a_c16 * 16;
                uint32_t sw = off ^ ((off >> 3) & 0x70);
                ldsm_x4(af[mi][0], af[mi][1], af[mi][2], af[mi][3], st + sw);
            }
            uint32_t bf[2][4];
#pragma unroll
            for (int pr = 0; pr < 2; ++pr) {
                uint32_t off = (uint32_t)(wc * 32 + pr * 16 + b_nrow) * 128 + ks * 32 + b_c16 * 16;
                uint32_t sw = off ^ ((off >> 3) & 0x70);
                ldsm_x4(bf[pr][0], bf[pr][1], bf[pr][2], bf[pr][3], st + 16384 + sw);
            }
#pragma unroll
            for (int mi = 0; mi < 4; ++mi) {
#pragma unroll
                for (int pr = 0; pr < 2; ++pr) {
                    mma16816(acc[mi][pr * 2][0], acc[mi][pr * 2][1],
                             acc[mi][pr * 2][2], acc[mi][pr * 2][3],
                             af[mi][0], af[mi][1], af[mi][2], af[mi][3],
                             bf[pr][0], bf[pr][1]);
                    mma16816(acc[mi][pr * 2 + 1][0], acc[mi][pr * 2 + 1][1],
                             acc[mi][pr * 2 + 1][2], acc[mi][pr * 2 + 1][3],
                             af[mi][0], af[mi][1], af[mi][2], af[mi][3],
                             bf[pr][2], bf[pr][3]);
                }
            }
        }
    }
    __syncthreads();

#pragma unroll
    for (int mi = 0; mi < 4; ++mi) {
        int row0 = bm + wr * 64 + mi * 16 + (lane >> 2);
#pragma unroll
        for (int ni = 0; ni < 4; ++ni) {
            int col = bn + wc * 32 + ni * 8 + (lane & 3) * 2;
            *(__half2*)(C + (size_t)row0 * Nn + col) =
                __floats2half2_rn(acc[mi][ni][0], acc[mi][ni][1]);
            *(__half2*)(C + (size_t)(row0 + 8) * Nn + col) =
                __floats2half2_rn(acc[mi][ni][2], acc[mi][ni][3]);
        }
    }
#undef LOAD_CHUNK
}

// ---------------- tensor-core attention, exp-inline softmax, trans-ldmatrix V ----------------
#define ATT_P 0
#define ATT_KV 65536
#define ATT_Q 90112
#define ATT_MASK 94208
#define ATT_STAT 96768
#define ATT_SMEM 97024

__device__ __forceinline__ uint32_t psw(int row, int bytecol) {
    return (uint32_t)(row * 2048 + (bytecol ^ ((row & 7) << 4)));
}

__global__ __launch_bounds__(256)
void attn_mma_kernel(const float* __restrict__ qin)
{
    extern __shared__ char dsm[];
    const uint32_t sb = smem_u32(dsm);
    unsigned int* smask = (unsigned int*)(dsm + ATT_MASK);
    float* sl = (float*)(dsm + ATT_STAT);

    const int h = blockIdx.x, b = blockIdx.y;
    const int tid = threadIdx.x;
    const int lane = tid & 31, w = tid >> 5;
    const int wm = w >> 2, wn = w & 3;

    const int a_row = (lane & 15);
    const int a_c16 = (lane >> 4);
    const int b_nrow = (lane & 7) + ((lane >> 4) & 1) * 8;
    const int b_c16 = (lane >> 3) & 1;
    const int v_row = (lane & 7) + ((lane >> 3) & 1) * 8;
    const int v_c16 = lane >> 4;

    if (tid < 20) sl[tid] = 0.f;
    if (tid < 160) {
#pragma unroll
        for (int j = 0; j < 4; j++) {
            int idx = tid * 4 + j;
            smask[idx] = g_mbits[(b * 20 + (idx >> 5)) * 32 + (idx & 31)];
        }
    }
    for (int e = tid; e < 2048; e += 256) {
        int row = e >> 6, d = e & 63;
        __half v = __float2half_rn(0.f);
        if (row < 20) v = __float2half_rn(qin[((size_t)(b * 20 + row)) * 512 + h * 64 + d]);
        uint32_t off = (uint32_t)(row * 128 + d * 2);
        *(__half*)(dsm + ATT_Q + (off ^ ((off >> 3) & 0x70))) = v;
    }

#define LOADKV(t, voff)                                                       \
    do {                                                                      \
        uint32_t st_ = sb + ATT_KV + ((t) % 3) * 8192;                        \
        int n0_ = (t) * 64;                                                   \
        _Pragma("unroll")                                                     \
        for (int i_ = 0; i_ < 2; i_++) {                                      \
            int c_ = tid + i_ * 256;                                          \
            int row_ = c_ >> 3, j_ = c_ & 7;                                  \
            uint32_t off_ = row_ * 128 + j_ * 16;                             \
            uint32_t sw_ = off_ ^ ((off_ >> 3) & 0x70);                       \
            cp_async16(st_ + sw_,                                             \
                g_kvlh + ((size_t)b * 1000 + n0_ + row_) * 1536 + (voff) + h * 64 + j_ * 8); \
        }                                                                     \
        cp_commit();                                                          \
    } while (0)

    LOADKV(0, 0);
    LOADKV(1, 0);
    __syncthreads();

    uint32_t af[4][4];
#pragma unroll
    for (int ks = 0; ks < 4; ++ks) {
        uint32_t off = (uint32_t)((wm * 16 + a_row) * 128 + ks * 32 + a_c16 * 16);
        ldsm_x4(af[ks][0], af[ks][1], af[ks][2], af[ks][3],
                sb + ATT_Q + (off ^ ((off >> 3) & 0x70)));
    }

    const int r0 = wm * 16 + (lane >> 2);
    const int r1 = r0 + 8;
    float rsum0 = 0.f, rsum1 = 0.f;

    for (int t = 0; t < 16; ++t) {
        if (t >= 14) cp_wait0(); else cp_wait1();
        __syncthreads();
        if (t + 2 < 16) LOADKV(t + 2, 0);

        uint32_t st = sb + ATT_KV + (t % 3) * 8192;
        float acc[2][4] = {{0.f, 0.f, 0.f, 0.f}, {0.f, 0.f, 0.f, 0.f}};
#pragma unroll
        for (int ks = 0; ks < 4; ++ks) {
            uint32_t off = (uint32_t)((wn * 16 + b_nrow) * 128 + ks * 32 + b_c16 * 16);
            uint32_t bf0, bf1, bf2, bf3;
            ldsm_x4(bf0, bf1, bf2, bf3, st + (off ^ ((off >> 3) & 0x70)));
            mma16816(acc[0][0], acc[0][1], acc[0][2], acc[0][3],
                     af[ks][0], af[ks][1], af[ks][2], af[ks][3], bf0, bf1);
            mma16816(acc[1][0], acc[1][1], acc[1][2], acc[1][3],
                     af[ks][0], af[ks][1], af[ks][2], af[ks][3], bf2, bf3);
        }

        const int nb = t * 64 + wn * 16;
        const int widx = nb >> 5;
        unsigned int w0 = (r0 < 20) ? smask[r0 * 32 + widx] : 0u;
        unsigned int w1 = (r1 < 20) ? smask[r1 * 32 + widx] : 0u;
#pragma unroll
        for (int f = 0; f < 2; ++f) {
            int c = (lane & 3) * 2 + f * 8;
            int bit = (nb + c) & 31;
            float p00 = ((w0 >> bit) & 1u) ? fminf(__expf(acc[f][0] * INV_SQRT_DK), 60000.f) : 0.f;
            float p01 = ((w0 >> (bit + 1)) & 1u) ? fminf(__expf(acc[f][1] * INV_SQRT_DK), 60000.f) : 0.f;
            float p10 = ((w1 >> bit) & 1u) ? fminf(__expf(acc[f][2] * INV_SQRT_DK), 60000.f) : 0.f;
            float p11 = ((w1 >> (bit + 1)) & 1u) ? fminf(__expf(acc[f][3] * INV_SQRT_DK), 60000.f) : 0.f;
            rsum0 += p00 + p01;
            rsum1 += p10 + p11;
            int bytec = t * 128 + (wn * 16 + c) * 2;
            *(__half2*)(dsm + ATT_P + psw(r0, bytec)) = __floats2half2_rn(p00, p01);
            *(__half2*)(dsm + ATT_P + psw(r1, bytec)) = __floats2half2_rn(p10, p11);
        }
    }
    __syncthreads();

    LOADKV(0, 512);
    LOADKV(1, 512);

    rsum0 += __shfl_xor_sync(0xffffffffu, rsum0, 1);
    rsum0 += __shfl_xor_sync(0xffffffffu, rsum0, 2);
    rsum1 += __shfl_xor_sync(0xffffffffu, rsum1, 1);
    rsum1 += __shfl_xor_sync(0xffffffffu, rsum1, 2);
    if ((lane & 3) == 0) {
        if (r0 < 20) atomicAdd(&sl[r0], rsum0);
        if (r1 < 20) atomicAdd(&sl[r1], rsum1);
    }
    __syncthreads();

    float oacc[2][4] = {{0.f, 0.f, 0.f, 0.f}, {0.f, 0.f, 0.f, 0.f}};
    for (int t = 0; t < 16; ++t) {
        if (t >= 14) cp_wait0(); else cp_wait1();
        __syncthreads();
        if (t + 2 < 16) LOADKV(t + 2, 512);

        uint32_t st = sb + ATT_KV + (t % 3) * 8192;
#pragma unroll
        for (int ks = 0; ks < 4; ++ks) {
            uint32_t pa0, pa1, pa2, pa3;
            ldsm_x4(pa0, pa1, pa2, pa3,
                    sb + ATT_P + psw(wm * 16 + a_row, t * 128 + ks * 32 + a_c16 * 16));
            uint32_t off = (uint32_t)((ks * 16 + v_row) * 128 + wn * 32 + v_c16 * 16);
            uint32_t bf0, bf1, bf2, bf3;
            ldsm_x4_t(bf0, bf1, bf2, bf3, st + (off ^ ((off >> 3) & 0x70)));
            mma16816(oacc[0][0], oacc[0][1], oacc[0][2], oacc[0][3],
                     pa0, pa1, pa2, pa3, bf0, bf1);
            mma16816(oacc[1][0], oacc[1][1], oacc[1][2], oacc[1][3],
                     pa0, pa1, pa2, pa3, bf2, bf3);
        }
    }

#pragma unroll
    for (int f = 0; f < 2; ++f) {
        int col = h * 64 + wn * 16 + f * 8 + (lane & 3) * 2;
        if (r0 < 20) {
            float inv = 1.f / sl[r0];
            *(__half2*)(g_Hf16 + ((size_t)(b * 20 + r0)) * 512 + col) =
                __floats2half2_rn(oacc[f][0] * inv, oacc[f][1] * inv);
        }
        if (r1 < 20) {
            float inv = 1.f / sl[r1];
            *(__half2*)(g_Hf16 + ((size_t)(b * 20 + r1)) * 512 + col) =
                __floats2half2_rn(oacc[f][2] * inv, oacc[f][3] * inv);
        }
    }
#undef LOADKV
}

// ---------------- pointer logits via MMA ----------------
#define PTR_A 0
#define PTR_B 32768
#define PTR_MASK 49152
#define PTR_SMEM 51712

__global__ __launch_bounds__(256)
void pointer_mma_kernel()
{
    extern __shared__ char dsm[];
    const uint32_t sb = smem_u32(dsm);
    unsigned int* smask = (unsigned int*)(dsm + PTR_MASK);

    const int nsl = blockIdx.x, b = blockIdx.y;
    const int tid = threadIdx.x;
    const int lane = tid & 31, w = tid >> 5;
    const int wm = w >> 2, wn = w & 3;

    const int a_row = (lane & 15);
    const int a_c16 = (lane >> 4);
    const int b_nrow = (lane & 7) + ((lane >> 4) & 1) * 8;
    const int b_c16 = (lane >> 3) & 1;

    for (int i = tid; i < 32768 / 16; i += 256)
        *(uint4*)(dsm + PTR_A + i * 16) = make_uint4(0u, 0u, 0u, 0u);
    if (tid < 160) {
#pragma unroll
        for (int j = 0; j < 4; j++) {
            int idx = tid * 4 + j;
            smask[idx] = g_mbits[(b * 20 + (idx >> 5)) * 32 + (idx & 31)];
        }
    }
    __syncthreads();

    for (int c = tid; c < 20 * 64; c += 256) {
        int row = c >> 6, j = c & 63;
        int kc = j >> 3, jj = j & 7;
        uint32_t off = (uint32_t)(row * 128 + jj * 16);
        uint32_t sw = off ^ ((off >> 3) & 0x70);
        *(uint4*)(dsm + PTR_A + kc * 4096 + sw) =
            *(const uint4*)(g_Gf16 + ((size_t)(b * 20 + row)) * 512 + kc * 64 + jj * 8);
    }

#define PLOADB(step)                                                          \
    do {                                                                      \
        int nt_ = (step) >> 3, kc_ = (step) & 7;                              \
        uint32_t st_ = sb + PTR_B + ((step) & 1) * 8192;                      \
        _Pragma("unroll")                                                     \
        for (int i_ = 0; i_ < 2; i_++) {                                      \
            int c_ = tid + i_ * 256;                                          \
            int row_ = c_ >> 3, j_ = c_ & 7;                                  \
            uint32_t off_ = row_ * 128 + j_ * 16;                             \
            uint32_t sw_ = off_ ^ ((off_ >> 3) & 0x70);                       \
            cp_async16(st_ + sw_,                                             \
                g_kvlh + ((size_t)b * 1000 + nsl * 512 + nt_ * 64 + row_) * 1536 + 1024 + kc_ * 64 + j_ * 8); \
        }                                                                     \
        cp_commit();                                                          \
    } while (0)

    PLOADB(0);
    __syncthreads();

    const int r0 = wm * 16 + (lane >> 2);
    const int r1 = r0 + 8;

    float acc[2][4];
    for (int step = 0; step < 64; ++step) {
        if (step + 1 < 64) { PLOADB(step + 1); cp_wait1(); } else { cp_wait0(); }
        __syncthreads();

        const int kc = step & 7;
        if (kc == 0) {
#pragma unroll
            for (int f = 0; f < 2; ++f)
#pragma unroll
                for (int r = 0; r < 4; ++r) acc[f][r] = 0.f;
        }

        uint32_t stB = sb + PTR_B + (step & 1) * 8192;
#pragma unroll
        for (int ks = 0; ks < 4; ++ks) {
            uint32_t a0, a1, a2, a3;
            uint32_t offA = (uint32_t)((wm * 16 + a_row) * 128 + ks * 32 + a_c16 * 16);
            ldsm_x4(a0, a1, a2, a3, sb + PTR_A + kc * 4096 + (offA ^ ((offA >> 3) & 0x70)));
            uint32_t offB = (uint32_t)((wn * 16 + b_nrow) * 128 + ks * 32 + b_c16 * 16);
            uint32_t bf0, bf1, bf2, bf3;
            ldsm_x4(bf0, bf1, bf2, bf3, stB + (offB ^ ((offB >> 3) & 0x70)));
            mma16816(acc[0][0], acc[0][1], acc[0][2], acc[0][3], a0, a1, a2, a3, bf0, bf1);
            mma16816(acc[1][0], acc[1][1], acc[1][2], acc[1][3], a0, a1, a2, a3, bf2, bf3);
        }

        if (kc == 7) {
            const int nt = step >> 3;
            const int nb = nsl * 512 + nt * 64 + wn * 16;
            const int widx = nb >> 5;
            unsigned int w0 = (r0 < 20) ? smask[r0 * 32 + widx] : 0u;
            unsigned int w1 = (r1 < 20) ? smask[r1 * 32 + widx] : 0u;
#pragma unroll
            for (int f = 0; f < 2; ++f) {
                int c = (lane & 3) * 2 + f * 8;
                int gn = nb + c;
                int bit = gn & 31;
                if (r0 < 20) {
                    if (gn < 1000) {
                        float lg = ((w0 >> bit) & 1u)
                                 ? 10.f * tanhf(acc[f][0] * INV_SQRT_D) : NEG_BIG;
                        g_logits[(size_t)(b * 20 + r0) * 1000 + gn] = lg;
                    }
                    if (gn + 1 < 1000) {
                        float lg = ((w0 >> (bit + 1)) & 1u)
                                 ? 10.f * tanhf(acc[f][1] * INV_SQRT_D) : NEG_BIG;
                        g_logits[(size_t)(b * 20 + r0) * 1000 + gn + 1] = lg;
                    }
                }
                if (r1 < 20) {
                    if (gn < 1000) {
                        float lg = ((w1 >> bit) & 1u)
                                 ? 10.f * tanhf(acc[f][2] * INV_SQRT_D) : NEG_BIG;
                        g_logits[(size_t)(b * 20 + r1) * 1000 + gn] = lg;
                    }
                    if (gn + 1 < 1000) {
                        float lg = ((w1 >> (bit + 1)) & 1u)
                                 ? 10.f * tanhf(acc[f][3] * INV_SQRT_D) : NEG_BIG;
                        g_logits[(size_t)(b * 20 + r1) * 1000 + gn + 1] = lg;
                    }
                }
            }
        }
        __syncthreads();
    }
#undef PLOADB
}

// ---------------- log-softmax + transposed writeout ----------------
__global__ __launch_bounds__(256)
void lsm_kernel(float* __restrict__ out)
{
    const int s = blockIdx.x, b = blockIdx.y;
    const float* row = g_logits + (size_t)(b * 20 + s) * 1000;
    float* orow = out + (size_t)(s * 64 + b) * 1000;
    __shared__ float red[8];
    const int tid = threadIdx.x;
    const int lane = tid & 31, w = tid >> 5;

    float mx = -1e30f;
    for (int i = tid; i < 1000; i += 256) mx = fmaxf(mx, row[i]);
    mx = warp_max(mx);
    if (lane == 0) red[w] = mx;
    __syncthreads();
    if (w == 0) {
        float v = (lane < 8) ? red[lane] : -1e30f;
        v = warp_max(v);
        if (lane == 0) red[0] = v;
    }
    __syncthreads();
    mx = red[0];
    __syncthreads();

    float se = 0.f;
    for (int i = tid; i < 1000; i += 256) se += __expf(row[i] - mx);
    se = warp_sum(se);
    if (lane == 0) red[w] = se;
    __syncthreads();
    if (w == 0) {
        float v = (lane < 8) ? red[lane] : 0.f;
        v = warp_sum(v);
        if (lane == 0) red[0] = v;
    }
    __syncthreads();
    const float lse = mx + logf(red[0]);

    for (int i = tid; i < 1000; i += 256) orow[i] = row[i] - lse;
}

// ---------------- launch ----------------
extern "C" void kernel_launch(void* const* d_in, const int* in_sizes, int n_in,
                              void* d_out, int out_size)
{
    (void)out_size;
    const float* emb = nullptr;
    const float* q = nullptr;
    const void* mask = nullptr;
    const float* Wkvl = nullptr;
    const float* Wout = nullptr;
    for (int i = 0; i < n_in; ++i) {
        switch (in_sizes[i]) {
            case 32768000: emb = (const float*)d_in[i]; break;
            case 655360:   q = (const float*)d_in[i]; break;
            case 1280000:  mask = d_in[i]; break;
            case 786432:   Wkvl = (const float*)d_in[i]; break;
            case 262144:   Wout = (const float*)d_in[i]; break;
            default: break;
        }
    }
    float* out = (float*)d_out;

    __half *kvlhp, *af16, *wkt, *wot, *hf16, *gf16;
    cudaGetSymbolAddress((void**)&kvlhp, g_kvlh);
    cudaGetSymbolAddress((void**)&af16, g_Af16);
    cudaGetSymbolAddress((void**)&wkt, g_Wkvl_t);
    cudaGetSymbolAddress((void**)&wot, g_Wout_t);
    cudaGetSymbolAddress((void**)&hf16, g_Hf16);
    cudaGetSymbolAddress((void**)&gf16, g_Gf16);

    cudaFuncSetAttribute(hmma_gemm128, cudaFuncAttributeMaxDynamicSharedMemorySize, 98304);
    cudaFuncSetAttribute(attn_mma_kernel, cudaFuncAttributeMaxDynamicSharedMemorySize, ATT_SMEM);
    cudaFuncSetAttribute(pointer_mma_kernel, cudaFuncAttributeMaxDynamicSharedMemorySize, PTR_SMEM);

    const unsigned int* mw = (const unsigned int*)mask;
    // 1-3: prep split so the big GEMM lands in profiled slot #4
    prep_kernel<<<16000, 256>>>(emb, Wkvl, Wout, mw, 0);
    prep_kernel<<<16000, 256>>>(emb, Wkvl, Wout, mw, 16000);
    prep_kernel<<<5376, 256>>>(emb, Wkvl, Wout, mw, 32000);

    // 4: kvl = embeddings @ W_kvl -> g_kvlh (profiled; 2 CTAs/SM)
    {
        dim3 grid(12, 500);
        hmma_gemm128<<<grid, 256, 98304>>>(af16, wkt, kvlhp, 1536);
    }

    // 5: tensor-core attention
    {
        dim3 grid(8, 64);
        attn_mma_kernel<<<grid, 256, ATT_SMEM>>>(q);
    }

    // 6: glimpse = heads @ W_out -> fp16
    {
        dim3 grid(4, 10);
        hmma_gemm128<<<grid, 256, 98304>>>(hf16, wot, gf16, 512);
    }

    // 7: pointer logits via MMA
    {
        dim3 grid(2, 64);
        pointer_mma_kernel<<<grid, 256, PTR_SMEM>>>();
    }

    // 8: log-softmax
    {
        dim3 grid(20, 64);
        lsm_kernel<<<grid, 256>>>(out);
    }
}